// round 4
// baseline (speedup 1.0000x reference)
#include <cuda_runtime.h>
#include <math.h>

#define TT 512
#define BBATCH 4
#define NT 2048   // BBATCH*TT tokens
#define DD 768
#define HH 12
#define HDIM 64
#define MM 3072
#define VV 32128
#define LL 6
#define NEGINF -1e10f
#define BK 32

// ---------------- scratch (device globals; no cudaMalloc allowed) ----------------
__device__ float g_xe[NT * DD];
__device__ float g_xd[NT * DD];
__device__ float g_enc[NT * DD];
__device__ float g_h[NT * DD];
__device__ float g_q[NT * DD];
__device__ float g_k[NT * DD];
__device__ float g_v[NT * DD];
__device__ float g_ao[NT * DD];
__device__ float g_hid[NT * MM];
__device__ float g_sc[BBATCH * HH * TT * TT];
__device__ float g_bias_e[HH * TT * TT];
__device__ float g_bias_d[HH * TT * TT];
__device__ int   g_val_e[NT];
__device__ int   g_val_t[NT];

// ---------------- low-level helpers ----------------

__device__ __forceinline__ void cp16(unsigned dst, const void* src)
{
    asm volatile("cp.async.cg.shared.global [%0], [%1], 16;\n" :: "r"(dst), "l"(src));
}
__device__ __forceinline__ void cp_commit() { asm volatile("cp.async.commit_group;\n"); }
__device__ __forceinline__ void cp_wait1()  { asm volatile("cp.async.wait_group 1;\n"); }

__device__ __forceinline__ unsigned tf32cvt(float x)
{
    unsigned y;
    asm("cvt.rna.tf32.f32 %0, %1;" : "=r"(y) : "f"(x));
    return y;
}

__device__ __forceinline__ void ldsm4(unsigned addr, unsigned* a)
{
    asm volatile("ldmatrix.sync.aligned.m8n8.x4.shared.b16 {%0,%1,%2,%3}, [%4];"
                 : "=r"(a[0]), "=r"(a[1]), "=r"(a[2]), "=r"(a[3]) : "r"(addr));
}
__device__ __forceinline__ void ldsm2(unsigned addr, unsigned* b)
{
    asm volatile("ldmatrix.sync.aligned.m8n8.x2.shared.b16 {%0,%1}, [%2];"
                 : "=r"(b[0]), "=r"(b[1]) : "r"(addr));
}

__device__ __forceinline__ void mma8(float* c, const unsigned* a, const unsigned* b)
{
    asm volatile(
        "mma.sync.aligned.m16n8k8.row.col.f32.tf32.tf32.f32 "
        "{%0,%1,%2,%3}, {%4,%5,%6,%7}, {%8,%9}, {%0,%1,%2,%3};"
        : "+f"(c[0]), "+f"(c[1]), "+f"(c[2]), "+f"(c[3])
        : "r"(a[0]), "r"(a[1]), "r"(a[2]), "r"(a[3]), "r"(b[0]), "r"(b[1]));
}

// A-tile (or NT B-tile) loader: 128 rows x 32 cols fp32, XOR-swizzled 16B chunks
__device__ __forceinline__ void load_tileA(unsigned sb, int st, const float* A,
                                           int row0, int k0, int lda, int tid)
{
#pragma unroll
    for (int j = 0; j < 4; j++) {
        int c = tid + 256 * j;
        int m = c >> 3, kc = c & 7;
        cp16(sb + st * (128 * BK * 4) + (((m << 5) | ((kc ^ (m & 7)) << 2)) << 2),
             A + (long)(row0 + m) * lda + k0 + kc * 4);
    }
}

// B-tile loader (NN): BK rows x BN cols fp32, swizzled
template<int BN>
__device__ __forceinline__ void load_tileB(unsigned sb, int st, const float* B,
                                           int n0, int k0, int ldb, int tid)
{
    constexpr int BCH = BN / 4;
    constexpr int BPT = (BK * BCH) / 256;
#pragma unroll
    for (int j = 0; j < BPT; j++) {
        int c = tid + 256 * j;
        int k = c / BCH, nc = c % BCH;
        cp16(sb + st * (BK * BN * 4) + (((k * BN) + ((nc ^ (k & 7)) << 2)) << 2),
             B + (long)(k0 + k) * ldb + n0 + nc * 4);
    }
}

// ---------------- tf32 tensor-core GEMM (NN): C[M,N] (+)= A[M,K]*B[K,N] ----------------
// BN in {128,64}. MS = M-subtiles per warp (4 for BN=128, 2 for BN=64).
template<int BN, int MS, bool ACC, bool RELU>
__global__ __launch_bounds__(256) void gemm_nn(
    const float* __restrict__ A, const float* __restrict__ B, float* __restrict__ C,
    int K, int lda, int ldb, int ldc,
    int zdiv, long az1, long az2, long bz1, long bz2, long cz1, long cz2)
{
    extern __shared__ float sm[];
    float* As = sm;                    // [2][128*BK]
    float* Bs = sm + 2 * 128 * BK;     // [2][BK*BN]
    const unsigned asb = (unsigned)__cvta_generic_to_shared(As);
    const unsigned bsb = (unsigned)__cvta_generic_to_shared(Bs);

    const int tid = threadIdx.x;
    const int lane = tid & 31, warp = tid >> 5;
    constexpr int WARPS_M = (BN == 128) ? 2 : 4;
    const int mw = (warp % WARPS_M) * (MS * 16);
    const int nw = (warp / WARPS_M) * 32;
    const int m0 = blockIdx.y * 128, n0 = blockIdx.x * BN;

    const int z = blockIdx.z;
    A += (long)(z / zdiv) * az1 + (long)(z % zdiv) * az2;
    B += (long)(z / zdiv) * bz1 + (long)(z % zdiv) * bz2;
    C += (long)(z / zdiv) * cz1 + (long)(z % zdiv) * cz2;

    float acc[MS][4][4];
#pragma unroll
    for (int i = 0; i < MS; i++)
#pragma unroll
        for (int j = 0; j < 4; j++)
#pragma unroll
            for (int q = 0; q < 4; q++) acc[i][j][q] = 0.f;

    const int nk = K / BK;
    load_tileA(asb, 0, A, m0, 0, lda, tid);
    load_tileB<BN>(bsb, 0, B, n0, 0, ldb, tid);
    cp_commit();

    for (int kt = 0; kt < nk; kt++) {
        int st = kt & 1;
        if (kt + 1 < nk) {
            load_tileA(asb, st ^ 1, A, m0, (kt + 1) * BK, lda, tid);
            load_tileB<BN>(bsb, st ^ 1, B, n0, (kt + 1) * BK, ldb, tid);
        }
        cp_commit();
        cp_wait1();
        __syncthreads();

        const unsigned ab = asb + st * (128 * BK * 4);
        const float* Bp = Bs + st * (BK * BN);

#pragma unroll
        for (int kk = 0; kk < BK; kk += 8) {
            unsigned a[MS][4];
#pragma unroll
            for (int i = 0; i < MS; i++) {
                int r = mw + 16 * i + (lane & 7) + ((lane >> 3) & 1) * 8;
                int ch = (kk >> 2) + (lane >> 4);
                ldsm4(ab + (((r << 5) | ((ch ^ (r & 7)) << 2)) << 2), a[i]);
            }
#pragma unroll
            for (int i = 0; i < MS; i++)
#pragma unroll
                for (int q = 0; q < 4; q++) a[i][q] = tf32cvt(__uint_as_float(a[i][q]));

            unsigned bf[4][2];
#pragma unroll
            for (int j = 0; j < 4; j++) {
                int n = nw + 8 * j + (lane >> 2);
                int ncc = n >> 2, nr = n & 3;
                int k1 = kk + (lane & 3);
                int k2 = k1 + 4;
                bf[j][0] = tf32cvt(Bp[k1 * BN + (((ncc ^ (k1 & 7)) << 2) | nr)]);
                bf[j][1] = tf32cvt(Bp[k2 * BN + (((ncc ^ (k2 & 7)) << 2) | nr)]);
            }
#pragma unroll
            for (int i = 0; i < MS; i++)
#pragma unroll
                for (int j = 0; j < 4; j++) mma8(acc[i][j], a[i], bf[j]);
        }
        __syncthreads();
    }

#pragma unroll
    for (int i = 0; i < MS; i++) {
        int r = m0 + mw + 16 * i + (lane >> 2);
#pragma unroll
        for (int j = 0; j < 4; j++) {
            int cn = n0 + nw + 8 * j + ((lane & 3) << 1);
            float2* p0 = (float2*)(C + (long)r * ldc + cn);
            float2* p1 = (float2*)(C + (long)(r + 8) * ldc + cn);
            float2 v0 = make_float2(acc[i][j][0], acc[i][j][1]);
            float2 v1 = make_float2(acc[i][j][2], acc[i][j][3]);
            if (RELU) {
                v0.x = fmaxf(v0.x, 0.f); v0.y = fmaxf(v0.y, 0.f);
                v1.x = fmaxf(v1.x, 0.f); v1.y = fmaxf(v1.y, 0.f);
            }
            if (ACC) {
                float2 o0 = *p0, o1 = *p1;
                v0.x += o0.x; v0.y += o0.y; v1.x += o1.x; v1.y += o1.y;
            }
            *p0 = v0; *p1 = v1;
        }
    }
}

// ---------------- tf32 attention scores (NT): S = Q*K^T + bias, masked ----------------
__global__ __launch_bounds__(256) void attn_scores_tc(
    const float* __restrict__ Q, const float* __restrict__ Km, float* __restrict__ S,
    const float* __restrict__ bias, const int* __restrict__ validQ,
    const int* __restrict__ validK, int causal)
{
    extern __shared__ float sm[];
    float* As = sm;                     // [2][128*32]
    float* Bs = sm + 2 * 128 * BK;      // [2][128*32]
    const unsigned asb = (unsigned)__cvta_generic_to_shared(As);
    const unsigned bsb = (unsigned)__cvta_generic_to_shared(Bs);

    const int tid = threadIdx.x;
    const int lane = tid & 31, warp = tid >> 5;
    const int mw = (warp & 1) * 64;
    const int nw = (warp >> 1) * 32;
    const int m0 = blockIdx.y * 128, n0 = blockIdx.x * 128;

    const int z = blockIdx.z;
    const int b = z / HH, h = z % HH;
    const float* Ap = Q + (long)b * TT * DD + h * HDIM;
    const float* Bp = Km + (long)b * TT * DD + h * HDIM;

    float acc[4][4][4];
#pragma unroll
    for (int i = 0; i < 4; i++)
#pragma unroll
        for (int j = 0; j < 4; j++)
#pragma unroll
            for (int q = 0; q < 4; q++) acc[i][j][q] = 0.f;

    const int nk = HDIM / BK;   // 2
    load_tileA(asb, 0, Ap, m0, 0, DD, tid);
    load_tileA(bsb, 0, Bp, n0, 0, DD, tid);
    cp_commit();

    for (int kt = 0; kt < nk; kt++) {
        int st = kt & 1;
        if (kt + 1 < nk) {
            load_tileA(asb, st ^ 1, Ap, m0, (kt + 1) * BK, DD, tid);
            load_tileA(bsb, st ^ 1, Bp, n0, (kt + 1) * BK, DD, tid);
        }
        cp_commit();
        cp_wait1();
        __syncthreads();

        const unsigned ab = asb + st * (128 * BK * 4);
        const unsigned bb = bsb + st * (128 * BK * 4);

#pragma unroll
        for (int kk = 0; kk < BK; kk += 8) {
            unsigned a[4][4];
#pragma unroll
            for (int i = 0; i < 4; i++) {
                int r = mw + 16 * i + (lane & 7) + ((lane >> 3) & 1) * 8;
                int ch = (kk >> 2) + (lane >> 4);
                ldsm4(ab + (((r << 5) | ((ch ^ (r & 7)) << 2)) << 2), a[i]);
            }
#pragma unroll
            for (int i = 0; i < 4; i++)
#pragma unroll
                for (int q = 0; q < 4; q++) a[i][q] = tf32cvt(__uint_as_float(a[i][q]));

            unsigned bf[4][2];
#pragma unroll
            for (int j = 0; j < 4; j++) {
                int r = nw + 8 * j + (lane & 7);
                int ch = (kk >> 2) + ((lane >> 3) & 1);
                ldsm2(bb + (((r << 5) | ((ch ^ (r & 7)) << 2)) << 2), bf[j]);
                bf[j][0] = tf32cvt(__uint_as_float(bf[j][0]));
                bf[j][1] = tf32cvt(__uint_as_float(bf[j][1]));
            }
#pragma unroll
            for (int i = 0; i < 4; i++)
#pragma unroll
                for (int j = 0; j < 4; j++) mma8(acc[i][j], a[i], bf[j]);
        }
        __syncthreads();
    }

    const long sbase = (long)z * TT * TT;
#pragma unroll
    for (int i = 0; i < 4; i++) {
        int q0 = m0 + mw + 16 * i + (lane >> 2);
#pragma unroll
        for (int j = 0; j < 4; j++) {
            int s0 = n0 + nw + 8 * j + ((lane & 3) << 1);
#pragma unroll
            for (int rr = 0; rr < 2; rr++) {
                int q = q0 + rr * 8;
                int vq = validQ[b * TT + q];
#pragma unroll
                for (int cc = 0; cc < 2; cc++) {
                    int s = s0 + cc;
                    float v = acc[i][j][rr * 2 + cc];
                    if (bias) v += bias[(long)h * TT * TT + (long)q * TT + s];
                    bool m = vq && validK[b * TT + s] && (!causal || s <= q);
                    S[sbase + (long)q * TT + s] = m ? v : NEGINF;
                }
            }
        }
    }
}

// ---------------- elementwise / reduction kernels ----------------

__global__ void softmax_rows(float* __restrict__ S)
{
    size_t base = (size_t)blockIdx.x * TT;
    int tid = threadIdx.x;
    float v0 = S[base + tid], v1 = S[base + tid + 256];
    __shared__ float red[256];
    red[tid] = fmaxf(v0, v1);
    __syncthreads();
    for (int o = 128; o > 0; o >>= 1) {
        if (tid < o) red[tid] = fmaxf(red[tid], red[tid + o]);
        __syncthreads();
    }
    float mx = red[0];
    __syncthreads();
    float e0 = expf(v0 - mx), e1 = expf(v1 - mx);
    red[tid] = e0 + e1;
    __syncthreads();
    for (int o = 128; o > 0; o >>= 1) {
        if (tid < o) red[tid] += red[tid + o];
        __syncthreads();
    }
    float inv = 1.0f / red[0];
    S[base + tid] = e0 * inv;
    S[base + tid + 256] = e1 * inv;
}

__global__ void rmsnorm_k(const float* __restrict__ X, const float* __restrict__ scale,
                          float* __restrict__ O)
{
    int row = blockIdx.x;
    int tid = threadIdx.x;
    const float* x = X + (size_t)row * DD;
    float s = 0.f;
    for (int d = tid; d < DD; d += 256) { float v = x[d]; s += v * v; }
    __shared__ float red[256];
    red[tid] = s;
    __syncthreads();
    for (int o = 128; o > 0; o >>= 1) {
        if (tid < o) red[tid] += red[tid + o];
        __syncthreads();
    }
    float r = 1.0f / sqrtf(red[0] / (float)DD + 1e-6f);
    for (int d = tid; d < DD; d += 256) O[(size_t)row * DD + d] = x[d] * r * scale[d];
}

__global__ void embed_k(const int* __restrict__ tok, const float* __restrict__ emb,
                        float* __restrict__ O)
{
    int t = blockIdx.x;
    int token = tok[t];
    const float* e = emb + (size_t)token * DD;
    for (int d = threadIdx.x; d < DD; d += 256) O[(size_t)t * DD + d] = e[d];
}

__global__ void valid_k(const int* __restrict__ tok, int* __restrict__ v, int n)
{
    int i = blockIdx.x * blockDim.x + threadIdx.x;
    if (i < n) v[i] = tok[i] > 0 ? 1 : 0;
}

__global__ void build_bias(const float* __restrict__ rel, float* __restrict__ bias, int bidir)
{
    int idx = blockIdx.x * blockDim.x + threadIdx.x;
    if (idx >= TT * TT) return;
    int q = idx / TT, s = idx % TT;
    int n = q - s;
    int bucket;
    if (bidir) {
        int ret = (n < 0) ? 16 : 0;
        int na = n < 0 ? -n : n;
        if (na < 8) {
            bucket = ret + na;
        } else {
            int v = 8 + (int)(log((double)na / 8.0) / log(16.0) * 8.0);
            bucket = ret + (v < 15 ? v : 15);
        }
    } else {
        int na = n > 0 ? n : 0;
        if (na < 16) {
            bucket = na;
        } else {
            int v = 16 + (int)(log((double)na / 16.0) / log(8.0) * 16.0);
            bucket = (v < 31 ? v : 31);
        }
    }
#pragma unroll
    for (int h = 0; h < HH; h++)
        bias[(size_t)h * TT * TT + idx] = rel[h * 32 + bucket];
}

// ---------------- host orchestration ----------------

#define SMEM_NN128 ((2 * 128 * BK + 2 * BK * 128) * 4)   // 65536
#define SMEM_NN64  ((2 * 128 * BK + 2 * BK * 64) * 4)    // 49152
#define SMEM_NT    ((2 * 128 * BK + 2 * 128 * BK) * 4)   // 65536

static void set_attrs()
{
    cudaFuncSetAttribute(gemm_nn<128, 4, false, false>, cudaFuncAttributeMaxDynamicSharedMemorySize, SMEM_NN128);
    cudaFuncSetAttribute(gemm_nn<128, 4, true,  false>, cudaFuncAttributeMaxDynamicSharedMemorySize, SMEM_NN128);
    cudaFuncSetAttribute(gemm_nn<128, 4, false, true >, cudaFuncAttributeMaxDynamicSharedMemorySize, SMEM_NN128);
    cudaFuncSetAttribute(gemm_nn<64,  2, false, false>, cudaFuncAttributeMaxDynamicSharedMemorySize, SMEM_NN64);
    cudaFuncSetAttribute(attn_scores_tc, cudaFuncAttributeMaxDynamicSharedMemorySize, SMEM_NT);
}

static void run_attention(const float* q_in, const float* kv_in,
                          const float* wq, const float* wk, const float* wv, const float* wo,
                          float* x, const float* bias,
                          const int* validQ, const int* validK, int causal,
                          float* q, float* k, float* v, float* sc, float* ao)
{
    dim3 g(DD / 128, NT / 128, 1);
    gemm_nn<128, 4, false, false><<<g, 256, SMEM_NN128>>>(q_in, wq, q, DD, DD, DD, DD, 1, 0, 0, 0, 0, 0, 0);
    gemm_nn<128, 4, false, false><<<g, 256, SMEM_NN128>>>(kv_in, wk, k, DD, DD, DD, DD, 1, 0, 0, 0, 0, 0, 0);
    gemm_nn<128, 4, false, false><<<g, 256, SMEM_NN128>>>(kv_in, wv, v, DD, DD, DD, DD, 1, 0, 0, 0, 0, 0, 0);

    attn_scores_tc<<<dim3(TT / 128, TT / 128, BBATCH * HH), 256, SMEM_NT>>>(
        q, k, sc, bias, validQ, validK, causal);
    softmax_rows<<<BBATCH * HH * TT, 256>>>(sc);

    // PV: O[b,q,h,:] = P[bh] * V[b,:,h,:]
    gemm_nn<64, 2, false, false><<<dim3(1, TT / 128, BBATCH * HH), 256, SMEM_NN64>>>(
        sc, v, ao, TT, TT, DD, DD, HH,
        (long)HH * TT * TT, (long)TT * TT,
        (long)TT * DD, 64,
        (long)TT * DD, 64);

    gemm_nn<128, 4, true, false><<<g, 256, SMEM_NN128>>>(ao, wo, x, DD, DD, DD, DD, 1, 0, 0, 0, 0, 0, 0);
}

extern "C" void kernel_launch(void* const* d_in, const int* in_sizes, int n_in,
                              void* d_out, int out_size)
{
    const float* emb      = (const float*)d_in[0];
    const float* rel_enc  = (const float*)d_in[1];
    const float* rel_dec  = (const float*)d_in[2];
    const float* enc_ln1  = (const float*)d_in[3];
    const float* enc_wq   = (const float*)d_in[4];
    const float* enc_wk   = (const float*)d_in[5];
    const float* enc_wv   = (const float*)d_in[6];
    const float* enc_wo   = (const float*)d_in[7];
    const float* enc_ln2  = (const float*)d_in[8];
    const float* enc_wi   = (const float*)d_in[9];
    const float* enc_wmo  = (const float*)d_in[10];
    const float* enc_norm = (const float*)d_in[11];
    const float* dec_ln1  = (const float*)d_in[12];
    const float* dec_sq   = (const float*)d_in[13];
    const float* dec_sk   = (const float*)d_in[14];
    const float* dec_sv   = (const float*)d_in[15];
    const float* dec_so   = (const float*)d_in[16];
    const float* dec_ln2  = (const float*)d_in[17];
    const float* dec_cq   = (const float*)d_in[18];
    const float* dec_ck   = (const float*)d_in[19];
    const float* dec_cv   = (const float*)d_in[20];
    const float* dec_co   = (const float*)d_in[21];
    const float* dec_ln3  = (const float*)d_in[22];
    const float* dec_wi   = (const float*)d_in[23];
    const float* dec_wmo  = (const float*)d_in[24];
    const float* dec_norm = (const float*)d_in[25];
    const float* logits_w = (const float*)d_in[26];
    const int* enc_tok    = (const int*)d_in[27];
    const int* dec_in_tok = (const int*)d_in[28];
    const int* dec_tgt    = (const int*)d_in[29];

    float *xe, *xd, *enc, *h, *q, *k, *v, *ao, *hid, *sc, *be, *bd;
    int *ve, *vt;
    cudaGetSymbolAddress((void**)&xe,  g_xe);
    cudaGetSymbolAddress((void**)&xd,  g_xd);
    cudaGetSymbolAddress((void**)&enc, g_enc);
    cudaGetSymbolAddress((void**)&h,   g_h);
    cudaGetSymbolAddress((void**)&q,   g_q);
    cudaGetSymbolAddress((void**)&k,   g_k);
    cudaGetSymbolAddress((void**)&v,   g_v);
    cudaGetSymbolAddress((void**)&ao,  g_ao);
    cudaGetSymbolAddress((void**)&hid, g_hid);
    cudaGetSymbolAddress((void**)&sc,  g_sc);
    cudaGetSymbolAddress((void**)&be,  g_bias_e);
    cudaGetSymbolAddress((void**)&bd,  g_bias_d);
    cudaGetSymbolAddress((void**)&ve,  g_val_e);
    cudaGetSymbolAddress((void**)&vt,  g_val_t);

    set_attrs();

    valid_k<<<(NT + 255) / 256, 256>>>(enc_tok, ve, NT);
    valid_k<<<(NT + 255) / 256, 256>>>(dec_tgt, vt, NT);
    build_bias<<<(TT * TT) / 256, 256>>>(rel_enc, be, 1);
    build_bias<<<(TT * TT) / 256, 256>>>(rel_dec, bd, 0);

    const size_t WS = (size_t)DD * DD;
    const size_t MS_ = (size_t)DD * MM;
    dim3 gMLP1(MM / 128, NT / 128, 1);
    dim3 gMLP2(DD / 128, NT / 128, 1);

    // -------- encoder --------
    embed_k<<<NT, 256>>>(enc_tok, emb, xe);
    for (int l = 0; l < LL; l++) {
        rmsnorm_k<<<NT, 256>>>(xe, enc_ln1 + (size_t)l * DD, h);
        run_attention(h, h, enc_wq + l * WS, enc_wk + l * WS, enc_wv + l * WS, enc_wo + l * WS,
                      xe, be, ve, ve, 0, q, k, v, sc, ao);
        rmsnorm_k<<<NT, 256>>>(xe, enc_ln2 + (size_t)l * DD, h);
        gemm_nn<128, 4, false, true><<<gMLP1, 256, SMEM_NN128>>>(h, enc_wi + l * MS_, hid, DD, DD, MM, MM, 1, 0, 0, 0, 0, 0, 0);
        gemm_nn<128, 4, true, false><<<gMLP2, 256, SMEM_NN128>>>(hid, enc_wmo + l * MS_, xe, MM, MM, DD, DD, 1, 0, 0, 0, 0, 0, 0);
    }
    rmsnorm_k<<<NT, 256>>>(xe, enc_norm, enc);

    // -------- decoder --------
    embed_k<<<NT, 256>>>(dec_in_tok, emb, xd);
    for (int l = 0; l < LL; l++) {
        rmsnorm_k<<<NT, 256>>>(xd, dec_ln1 + (size_t)l * DD, h);
        run_attention(h, h, dec_sq + l * WS, dec_sk + l * WS, dec_sv + l * WS, dec_so + l * WS,
                      xd, bd, vt, vt, 1, q, k, v, sc, ao);
        rmsnorm_k<<<NT, 256>>>(xd, dec_ln2 + (size_t)l * DD, h);
        run_attention(h, enc, dec_cq + l * WS, dec_ck + l * WS, dec_cv + l * WS, dec_co + l * WS,
                      xd, nullptr, vt, ve, 0, q, k, v, sc, ao);
        rmsnorm_k<<<NT, 256>>>(xd, dec_ln3 + (size_t)l * DD, h);
        gemm_nn<128, 4, false, true><<<gMLP1, 256, SMEM_NN128>>>(h, dec_wi + l * MS_, hid, DD, DD, MM, MM, 1, 0, 0, 0, 0, 0, 0);
        gemm_nn<128, 4, true, false><<<gMLP2, 256, SMEM_NN128>>>(hid, dec_wmo + l * MS_, xd, MM, MM, DD, DD, 1, 0, 0, 0, 0, 0, 0);
    }
    rmsnorm_k<<<NT, 256>>>(xd, dec_norm, h);

    // -------- logits --------
    gemm_nn<128, 4, false, false><<<dim3(VV / 128, NT / 128, 1), 256, SMEM_NN128>>>(
        h, logits_w, (float*)d_out, DD, DD, VV, VV, 1, 0, 0, 0, 0, 0, 0);
}

// round 7
// speedup vs baseline: 1.3699x; 1.3699x over previous
#include <cuda_runtime.h>
#include <math.h>
#include <stdint.h>

#define TT 512
#define BBATCH 4
#define NT 2048
#define DD 768
#define HH 12
#define HDIM 64
#define MM 3072
#define VV 32128
#define LL 6
#define NEGINF -1e10f
#define BK 32
#define WSZ ((long)DD * DD)
#define DMM ((long)DD * MM)

// ---------------- scratch ----------------
__device__ float g_xe[NT * DD];
__device__ float g_xd[NT * DD];
__device__ float g_enc[NT * DD];
__device__ float g_h[NT * DD];
__device__ float g_qkv[NT * 3 * DD];
__device__ float g_q[NT * DD];
__device__ float g_kv[NT * 2 * DD];
__device__ float g_ao[NT * DD];
__device__ float g_hid[NT * MM];
__device__ float g_sc[BBATCH * HH * TT * TT];
__device__ float g_bias_e[HH * TT * TT];
__device__ float g_bias_d[HH * TT * TT];
__device__ int   g_val_e[NT];
__device__ int   g_val_t[NT];
// transposed tf32-rounded weights [N,K]
__device__ float g_wA_e[LL * 3 * DD * DD];
__device__ float g_wo_e[LL * DD * DD];
__device__ float g_wA_s[LL * 3 * DD * DD];
__device__ float g_wo_s[LL * DD * DD];
__device__ float g_cqT [LL * DD * DD];
__device__ float g_ckvT[LL * 2 * DD * DD];
__device__ float g_coT [LL * DD * DD];
__device__ float g_wiT_e [LL * DD * MM];
__device__ float g_wmoT_e[LL * DD * MM];
__device__ float g_wiT_d [LL * DD * MM];
__device__ float g_wmoT_d[LL * DD * MM];
__device__ float g_logT[(long)VV * DD];

// ---------------- helpers ----------------
__device__ __forceinline__ void cp16(unsigned dst, const void* src)
{ asm volatile("cp.async.cg.shared.global [%0], [%1], 16;\n" :: "r"(dst), "l"(src)); }
__device__ __forceinline__ void cp_commit() { asm volatile("cp.async.commit_group;\n"); }
__device__ __forceinline__ void cp_wait1()  { asm volatile("cp.async.wait_group 1;\n"); }

__device__ __forceinline__ unsigned tf32cvt(float x)
{ unsigned y; asm("cvt.rna.tf32.f32 %0, %1;" : "=r"(y) : "f"(x)); return y; }
__device__ __forceinline__ float tf32r(float x) { return __uint_as_float(tf32cvt(x)); }

__device__ __forceinline__ unsigned su32(const void* p)
{ return (unsigned)__cvta_generic_to_shared(p); }

__device__ __forceinline__ void ldsm4(unsigned a_, unsigned* a)
{
    asm volatile("ldmatrix.sync.aligned.m8n8.x4.shared.b16 {%0,%1,%2,%3}, [%4];"
                 : "=r"(a[0]), "=r"(a[1]), "=r"(a[2]), "=r"(a[3]) : "r"(a_));
}
__device__ __forceinline__ void ldsm2(unsigned a_, unsigned* b)
{
    asm volatile("ldmatrix.sync.aligned.m8n8.x2.shared.b16 {%0,%1}, [%2];"
                 : "=r"(b[0]), "=r"(b[1]) : "r"(a_));
}
__device__ __forceinline__ void mma8(float* c, const unsigned* a, const unsigned* b)
{
    asm volatile("mma.sync.aligned.m16n8k8.row.col.f32.tf32.tf32.f32 "
                 "{%0,%1,%2,%3}, {%4,%5,%6,%7}, {%8,%9}, {%0,%1,%2,%3};"
                 : "+f"(c[0]), "+f"(c[1]), "+f"(c[2]), "+f"(c[3])
                 : "r"(a[0]), "r"(a[1]), "r"(a[2]), "r"(a[3]), "r"(b[0]), "r"(b[1]));
}

// ---------------- transpose (+tf32 round): dst[N,K] = src[K,N] ----------------
__global__ void transpose_b(const float* __restrict__ src, float* __restrict__ dst,
                            int K, int N, long ss, long ds)
{
    __shared__ float t[32][33];
    const float* S = src + (long)blockIdx.z * ss;
    float* D = dst + (long)blockIdx.z * ds;
    int k0 = blockIdx.y * 32, n0 = blockIdx.x * 32;
    int tx = threadIdx.x, ty = threadIdx.y;
#pragma unroll
    for (int i = 0; i < 32; i += 8)
        t[ty + i][tx] = S[(long)(k0 + ty + i) * N + n0 + tx];
    __syncthreads();
#pragma unroll
    for (int i = 0; i < 32; i += 8)
        D[(long)(n0 + ty + i) * K + k0 + tx] = tf32r(t[tx][ty + i]);
}

// K-major tile loader: ROWS rows x 32 K-cols fp32, XOR-swizzled 16B chunks
template<int ROWS>
__device__ __forceinline__ void load_tileT(unsigned sbase, const float* P,
                                           int row0, int k0, int ld, int tid)
{
#pragma unroll
    for (int j = 0; j < ROWS / 32; j++) {
        int c = tid + 256 * j, m = c >> 3, kc = c & 7;
        cp16(sbase + (((m << 5) | ((kc ^ (m & 7)) << 2)) << 2),
             P + (long)(row0 + m) * ld + k0 + kc * 4);
    }
}

// ---------------- NT GEMM (legacy tf32 mma, both operands via ldmatrix) ----------------
// C[M,N] (+)= A[M,K] * Bt[N,K]^T.  All inputs pre-rounded tf32 (no in-loop cvt).
template<bool ACC, bool RELU, bool RNA>
__global__ __launch_bounds__(256) void gemm_nt(
    const float* __restrict__ A, const float* __restrict__ Bt, float* __restrict__ C,
    int K, int lda, int ldb, int ldc)
{
    extern __shared__ float sm[];
    const unsigned asb = su32(sm);
    const unsigned bsb = su32(sm + 2 * 128 * BK);
    constexpr int STG = 128 * BK * 4;

    const int tid = threadIdx.x, lane = tid & 31, warp = tid >> 5;
    const int mw = (warp & 1) * 64, nw = (warp >> 1) * 32;
    const int m0 = blockIdx.y * 128, n0 = blockIdx.x * 128;

    float acc[4][4][4];
#pragma unroll
    for (int i = 0; i < 4; i++)
#pragma unroll
        for (int j = 0; j < 4; j++)
#pragma unroll
            for (int q = 0; q < 4; q++) acc[i][j][q] = 0.f;

    const int nk = K / BK;
    load_tileT<128>(asb, A, m0, 0, lda, tid);
    load_tileT<128>(bsb, Bt, n0, 0, ldb, tid);
    cp_commit();

    for (int kt = 0; kt < nk; kt++) {
        const int st = kt & 1;
        if (kt + 1 < nk) {
            load_tileT<128>(asb + (st ^ 1) * STG, A, m0, (kt + 1) * BK, lda, tid);
            load_tileT<128>(bsb + (st ^ 1) * STG, Bt, n0, (kt + 1) * BK, ldb, tid);
        }
        cp_commit();
        cp_wait1();
        __syncthreads();

        const unsigned ab = asb + st * STG;
        const unsigned bb = bsb + st * STG;
#pragma unroll
        for (int kk = 0; kk < BK; kk += 8) {
            unsigned a[4][4];
#pragma unroll
            for (int i = 0; i < 4; i++) {
                int r = mw + 16 * i + (lane & 7) + ((lane >> 3) & 1) * 8;
                int ch = (kk >> 2) + (lane >> 4);
                ldsm4(ab + (((r << 5) | ((ch ^ (r & 7)) << 2)) << 2), a[i]);
            }
            unsigned bf[4][2];
#pragma unroll
            for (int j = 0; j < 4; j++) {
                int r = nw + 8 * j + (lane & 7);
                int ch = (kk >> 2) + ((lane >> 3) & 1);
                ldsm2(bb + (((r << 5) | ((ch ^ (r & 7)) << 2)) << 2), bf[j]);
            }
#pragma unroll
            for (int i = 0; i < 4; i++)
#pragma unroll
                for (int j = 0; j < 4; j++) mma8(acc[i][j], a[i], bf[j]);
        }
        __syncthreads();
    }

#pragma unroll
    for (int i = 0; i < 4; i++) {
        int r = m0 + mw + 16 * i + (lane >> 2);
#pragma unroll
        for (int j = 0; j < 4; j++) {
            int cn = n0 + nw + 8 * j + ((lane & 3) << 1);
            float2* p0 = (float2*)(C + (long)r * ldc + cn);
            float2* p1 = (float2*)(C + (long)(r + 8) * ldc + cn);
            float2 v0 = make_float2(acc[i][j][0], acc[i][j][1]);
            float2 v1 = make_float2(acc[i][j][2], acc[i][j][3]);
            if (RELU) {
                v0.x = fmaxf(v0.x, 0.f); v0.y = fmaxf(v0.y, 0.f);
                v1.x = fmaxf(v1.x, 0.f); v1.y = fmaxf(v1.y, 0.f);
            }
            if (RNA) {
                v0.x = tf32r(v0.x); v0.y = tf32r(v0.y);
                v1.x = tf32r(v1.x); v1.y = tf32r(v1.y);
            }
            if (ACC) {
                float2 o0 = *p0, o1 = *p1;
                v0.x += o0.x; v0.y += o0.y; v1.x += o1.x; v1.y += o1.y;
            }
            *p0 = v0; *p1 = v1;
        }
    }
}

// ---------------- attention scores: S = Q*K^T + bias, masked ----------------
__global__ __launch_bounds__(256) void attn_scores_tc(
    const float* __restrict__ Q, int ldq, const float* __restrict__ Km, int ldk,
    float* __restrict__ S, const float* __restrict__ bias,
    const int* __restrict__ validQ, const int* __restrict__ validK, int causal)
{
    extern __shared__ float sm[];
    const unsigned asb = su32(sm);
    const unsigned bsb = su32(sm + 2 * 128 * BK);
    constexpr int STG = 128 * BK * 4;
    const int tid = threadIdx.x, lane = tid & 31, warp = tid >> 5;
    const int mw = (warp & 1) * 64, nw = (warp >> 1) * 32;
    const int m0 = blockIdx.y * 128, n0 = blockIdx.x * 128;
    const int z = blockIdx.z, b = z / HH, h = z % HH;
    const float* Ap = Q + (long)b * TT * ldq + h * HDIM;
    const float* Bp = Km + (long)b * TT * ldk + h * HDIM;

    float acc[4][4][4];
#pragma unroll
    for (int i = 0; i < 4; i++)
#pragma unroll
        for (int j = 0; j < 4; j++)
#pragma unroll
            for (int q = 0; q < 4; q++) acc[i][j][q] = 0.f;

    load_tileT<128>(asb, Ap, m0, 0, ldq, tid);
    load_tileT<128>(bsb, Bp, n0, 0, ldk, tid);
    cp_commit();
    for (int kt = 0; kt < 2; kt++) {
        const int st = kt & 1;
        if (kt + 1 < 2) {
            load_tileT<128>(asb + (st ^ 1) * STG, Ap, m0, BK, ldq, tid);
            load_tileT<128>(bsb + (st ^ 1) * STG, Bp, n0, BK, ldk, tid);
        }
        cp_commit();
        cp_wait1();
        __syncthreads();
        const unsigned ab = asb + st * STG;
        const unsigned bb = bsb + st * STG;
#pragma unroll
        for (int kk = 0; kk < BK; kk += 8) {
            unsigned a[4][4];
#pragma unroll
            for (int i = 0; i < 4; i++) {
                int r = mw + 16 * i + (lane & 7) + ((lane >> 3) & 1) * 8;
                int ch = (kk >> 2) + (lane >> 4);
                ldsm4(ab + (((r << 5) | ((ch ^ (r & 7)) << 2)) << 2), a[i]);
            }
            unsigned bf[4][2];
#pragma unroll
            for (int j = 0; j < 4; j++) {
                int r = nw + 8 * j + (lane & 7);
                int ch = (kk >> 2) + ((lane >> 3) & 1);
                ldsm2(bb + (((r << 5) | ((ch ^ (r & 7)) << 2)) << 2), bf[j]);
            }
#pragma unroll
            for (int i = 0; i < 4; i++)
#pragma unroll
                for (int j = 0; j < 4; j++) mma8(acc[i][j], a[i], bf[j]);
        }
        __syncthreads();
    }
    const long sbase = (long)z * TT * TT;
#pragma unroll
    for (int i = 0; i < 4; i++) {
        int q0 = m0 + mw + 16 * i + (lane >> 2);
#pragma unroll
        for (int j = 0; j < 4; j++) {
            int s0 = n0 + nw + 8 * j + ((lane & 3) << 1);
#pragma unroll
            for (int rr = 0; rr < 2; rr++) {
                int q = q0 + rr * 8;
                int vq = validQ[b * TT + q];
#pragma unroll
                for (int cc = 0; cc < 2; cc++) {
                    int s = s0 + cc;
                    float v = acc[i][j][rr * 2 + cc];
                    if (bias) v += bias[(long)h * TT * TT + (long)q * TT + s];
                    bool m = vq && validK[b * TT + s] && (!causal || s <= q);
                    S[sbase + (long)q * TT + s] = m ? v : NEGINF;
                }
            }
        }
    }
}

// ---------------- PV: O[b,q,h,:] = P[bh]*V (NN, scalar B, no cvt) ----------------
__global__ __launch_bounds__(256) void gemm_pv(
    const float* __restrict__ P, const float* __restrict__ V, float* __restrict__ O,
    int ldb)
{
    extern __shared__ float sm[];
    float* Bs = sm + 2 * 128 * BK;
    const unsigned asb = su32(sm), bsb = su32(Bs);
    constexpr int ASTG = 128 * BK * 4, BSTG = BK * 64 * 4;
    const int tid = threadIdx.x, lane = tid & 31, warp = tid >> 5;
    const int mw = (warp & 3) * 32, nw = (warp >> 2) * 32;
    const int m0 = blockIdx.y * 128;
    const int z = blockIdx.z, b = z / HH, h = z % HH;
    const float* A = P + (long)z * TT * TT;
    const float* B = V + (long)b * TT * ldb + h * HDIM;
    float* C = O + (long)b * TT * DD + h * HDIM;

    float acc[2][4][4];
#pragma unroll
    for (int i = 0; i < 2; i++)
#pragma unroll
        for (int j = 0; j < 4; j++)
#pragma unroll
            for (int q = 0; q < 4; q++) acc[i][j][q] = 0.f;

    auto loadB = [&](int st, int k0) {
#pragma unroll
        for (int j = 0; j < 2; j++) {
            int c = tid + 256 * j, k = c >> 4, nc = c & 15;
            cp16(bsb + st * BSTG + (((k * 64) + ((nc ^ (k & 7)) << 2)) << 2),
                 B + (long)(k0 + k) * ldb + nc * 4);
        }
    };
    load_tileT<128>(asb, A, m0, 0, TT, tid);
    loadB(0, 0);
    cp_commit();
    const int nk = TT / BK;
    for (int kt = 0; kt < nk; kt++) {
        const int st = kt & 1;
        if (kt + 1 < nk) {
            load_tileT<128>(asb + (st ^ 1) * ASTG, A, m0, (kt + 1) * BK, TT, tid);
            loadB(st ^ 1, (kt + 1) * BK);
        }
        cp_commit();
        cp_wait1();
        __syncthreads();
        const unsigned ab = asb + st * ASTG;
        const float* Bp = Bs + st * (BK * 64);
#pragma unroll
        for (int kk = 0; kk < BK; kk += 8) {
            unsigned a[2][4];
#pragma unroll
            for (int i = 0; i < 2; i++) {
                int r = mw + 16 * i + (lane & 7) + ((lane >> 3) & 1) * 8;
                int ch = (kk >> 2) + (lane >> 4);
                ldsm4(ab + (((r << 5) | ((ch ^ (r & 7)) << 2)) << 2), a[i]);
            }
            unsigned bf[4][2];
#pragma unroll
            for (int j = 0; j < 4; j++) {
                int n = nw + 8 * j + (lane >> 2);
                int ncc = n >> 2, nr = n & 3;
                int k1 = kk + (lane & 3), k2 = k1 + 4;
                bf[j][0] = __float_as_uint(Bp[k1 * 64 + (((ncc ^ (k1 & 7)) << 2) | nr)]);
                bf[j][1] = __float_as_uint(Bp[k2 * 64 + (((ncc ^ (k2 & 7)) << 2) | nr)]);
            }
#pragma unroll
            for (int i = 0; i < 2; i++)
#pragma unroll
                for (int j = 0; j < 4; j++) mma8(acc[i][j], a[i], bf[j]);
        }
        __syncthreads();
    }
#pragma unroll
    for (int i = 0; i < 2; i++) {
        int r = m0 + mw + 16 * i + (lane >> 2);
#pragma unroll
        for (int j = 0; j < 4; j++) {
            int cn = nw + 8 * j + ((lane & 3) << 1);
            float2 v0 = make_float2(tf32r(acc[i][j][0]), tf32r(acc[i][j][1]));
            float2 v1 = make_float2(tf32r(acc[i][j][2]), tf32r(acc[i][j][3]));
            *(float2*)(C + (long)r * DD + cn) = v0;
            *(float2*)(C + (long)(r + 8) * DD + cn) = v1;
        }
    }
}

// ---------------- elementwise ----------------
// warp-per-row softmax over 512 cols; output tf32-rounded
__global__ void softmax_rows(float* __restrict__ S)
{
    const int row = blockIdx.x * 8 + (threadIdx.x >> 5);
    const int lane = threadIdx.x & 31;
    float4* p = (float4*)(S + (long)row * TT);
    float4 v[4];
    float mx = -3.4e38f;
#pragma unroll
    for (int i = 0; i < 4; i++) {
        v[i] = p[i * 32 + lane];
        mx = fmaxf(mx, fmaxf(fmaxf(v[i].x, v[i].y), fmaxf(v[i].z, v[i].w)));
    }
#pragma unroll
    for (int o = 16; o > 0; o >>= 1) mx = fmaxf(mx, __shfl_xor_sync(0xffffffffu, mx, o));
    float s = 0.f;
#pragma unroll
    for (int i = 0; i < 4; i++) {
        v[i].x = __expf(v[i].x - mx); v[i].y = __expf(v[i].y - mx);
        v[i].z = __expf(v[i].z - mx); v[i].w = __expf(v[i].w - mx);
        s += v[i].x + v[i].y + v[i].z + v[i].w;
    }
#pragma unroll
    for (int o = 16; o > 0; o >>= 1) s += __shfl_xor_sync(0xffffffffu, s, o);
    const float inv = 1.0f / s;
#pragma unroll
    for (int i = 0; i < 4; i++) {
        v[i].x = tf32r(v[i].x * inv); v[i].y = tf32r(v[i].y * inv);
        v[i].z = tf32r(v[i].z * inv); v[i].w = tf32r(v[i].w * inv);
        p[i * 32 + lane] = v[i];
    }
}

__global__ void rmsnorm_k(const float* __restrict__ X, const float* __restrict__ scale,
                          float* __restrict__ O)
{
    int row = blockIdx.x, tid = threadIdx.x;
    const float* x = X + (size_t)row * DD;
    float s = 0.f;
    for (int d = tid; d < DD; d += 256) { float v = x[d]; s += v * v; }
    __shared__ float red[256];
    red[tid] = s;
    __syncthreads();
    for (int o = 128; o > 0; o >>= 1) { if (tid < o) red[tid] += red[tid + o]; __syncthreads(); }
    float r = 1.0f / sqrtf(red[0] / (float)DD + 1e-6f);
    for (int d = tid; d < DD; d += 256) O[(size_t)row * DD + d] = tf32r(x[d] * r * scale[d]);
}

__global__ void embed_k(const int* __restrict__ tok, const float* __restrict__ emb,
                        float* __restrict__ O)
{
    int t = blockIdx.x, token = tok[t];
    const float* e = emb + (size_t)token * DD;
    for (int d = threadIdx.x; d < DD; d += 256) O[(size_t)t * DD + d] = e[d];
}

__global__ void valid_k(const int* __restrict__ tok, int* __restrict__ v, int n)
{
    int i = blockIdx.x * blockDim.x + threadIdx.x;
    if (i < n) v[i] = tok[i] > 0 ? 1 : 0;
}

__global__ void build_bias(const float* __restrict__ rel, float* __restrict__ bias, int bidir)
{
    int idx = blockIdx.x * blockDim.x + threadIdx.x;
    if (idx >= TT * TT) return;
    int q = idx / TT, s = idx % TT;
    int n = q - s, bucket;
    if (bidir) {
        int ret = (n < 0) ? 16 : 0;
        int na = n < 0 ? -n : n;
        if (na < 8) bucket = ret + na;
        else { int v = 8 + (int)(log((double)na / 8.0) / log(16.0) * 8.0); bucket = ret + (v < 15 ? v : 15); }
    } else {
        int na = n > 0 ? n : 0;
        if (na < 16) bucket = na;
        else { int v = 16 + (int)(log((double)na / 16.0) / log(8.0) * 16.0); bucket = (v < 31 ? v : 31); }
    }
#pragma unroll
    for (int h = 0; h < HH; h++)
        bias[(size_t)h * TT * TT + idx] = rel[h * 32 + bucket];
}

// ---------------- host ----------------
#define SMEM_NT ((2 * 128 * BK + 2 * 128 * BK) * 4)   // 65536
#define SMEM_PV ((2 * 128 * BK + 2 * BK * 64) * 4)    // 49152

static void set_attrs()
{
    cudaFuncSetAttribute(gemm_nt<false, false, true >, cudaFuncAttributeMaxDynamicSharedMemorySize, SMEM_NT);
    cudaFuncSetAttribute(gemm_nt<false, true,  true >, cudaFuncAttributeMaxDynamicSharedMemorySize, SMEM_NT);
    cudaFuncSetAttribute(gemm_nt<true,  false, false>, cudaFuncAttributeMaxDynamicSharedMemorySize, SMEM_NT);
    cudaFuncSetAttribute(gemm_nt<false, false, false>, cudaFuncAttributeMaxDynamicSharedMemorySize, SMEM_NT);
    cudaFuncSetAttribute(attn_scores_tc, cudaFuncAttributeMaxDynamicSharedMemorySize, SMEM_NT);
    cudaFuncSetAttribute(gemm_pv, cudaFuncAttributeMaxDynamicSharedMemorySize, SMEM_PV);
}

extern "C" void kernel_launch(void* const* d_in, const int* in_sizes, int n_in,
                              void* d_out, int out_size)
{
    const float* emb      = (const float*)d_in[0];
    const float* rel_enc  = (const float*)d_in[1];
    const float* rel_dec  = (const float*)d_in[2];
    const float* enc_ln1  = (const float*)d_in[3];
    const float* enc_wq   = (const float*)d_in[4];
    const float* enc_wk   = (const float*)d_in[5];
    const float* enc_wv   = (const float*)d_in[6];
    const float* enc_wo   = (const float*)d_in[7];
    const float* enc_ln2  = (const float*)d_in[8];
    const float* enc_wi   = (const float*)d_in[9];
    const float* enc_wmo  = (const float*)d_in[10];
    const float* enc_norm = (const float*)d_in[11];
    const float* dec_ln1  = (const float*)d_in[12];
    const float* dec_sq   = (const float*)d_in[13];
    const float* dec_sk   = (const float*)d_in[14];
    const float* dec_sv   = (const float*)d_in[15];
    const float* dec_so   = (const float*)d_in[16];
    const float* dec_ln2  = (const float*)d_in[17];
    const float* dec_cq   = (const float*)d_in[18];
    const float* dec_ck   = (const float*)d_in[19];
    const float* dec_cv   = (const float*)d_in[20];
    const float* dec_co   = (const float*)d_in[21];
    const float* dec_ln3  = (const float*)d_in[22];
    const float* dec_wi   = (const float*)d_in[23];
    const float* dec_wmo  = (const float*)d_in[24];
    const float* dec_norm = (const float*)d_in[25];
    const float* logits_w = (const float*)d_in[26];
    const int* enc_tok    = (const int*)d_in[27];
    const int* dec_in_tok = (const int*)d_in[28];
    const int* dec_tgt    = (const int*)d_in[29];

    float *xe, *xd, *enc, *h, *qkv, *q, *kv, *ao, *hid, *sc, *be, *bd;
    float *wAe, *woe, *wAs, *wos, *cqT, *ckvT, *coT, *wie, *wmoe, *wid_, *wmod, *logT;
    int *ve, *vt;
    cudaGetSymbolAddress((void**)&xe, g_xe);     cudaGetSymbolAddress((void**)&xd, g_xd);
    cudaGetSymbolAddress((void**)&enc, g_enc);   cudaGetSymbolAddress((void**)&h, g_h);
    cudaGetSymbolAddress((void**)&qkv, g_qkv);   cudaGetSymbolAddress((void**)&q, g_q);
    cudaGetSymbolAddress((void**)&kv, g_kv);     cudaGetSymbolAddress((void**)&ao, g_ao);
    cudaGetSymbolAddress((void**)&hid, g_hid);   cudaGetSymbolAddress((void**)&sc, g_sc);
    cudaGetSymbolAddress((void**)&be, g_bias_e); cudaGetSymbolAddress((void**)&bd, g_bias_d);
    cudaGetSymbolAddress((void**)&ve, g_val_e);  cudaGetSymbolAddress((void**)&vt, g_val_t);
    cudaGetSymbolAddress((void**)&wAe, g_wA_e);  cudaGetSymbolAddress((void**)&woe, g_wo_e);
    cudaGetSymbolAddress((void**)&wAs, g_wA_s);  cudaGetSymbolAddress((void**)&wos, g_wo_s);
    cudaGetSymbolAddress((void**)&cqT, g_cqT);   cudaGetSymbolAddress((void**)&ckvT, g_ckvT);
    cudaGetSymbolAddress((void**)&coT, g_coT);   cudaGetSymbolAddress((void**)&wie, g_wiT_e);
    cudaGetSymbolAddress((void**)&wmoe, g_wmoT_e); cudaGetSymbolAddress((void**)&wid_, g_wiT_d);
    cudaGetSymbolAddress((void**)&wmod, g_wmoT_d); cudaGetSymbolAddress((void**)&logT, g_logT);

    set_attrs();

    valid_k<<<(NT + 255) / 256, 256>>>(enc_tok, ve, NT);
    valid_k<<<(NT + 255) / 256, 256>>>(dec_tgt, vt, NT);
    build_bias<<<(TT * TT) / 256, 256>>>(rel_enc, be, 1);
    build_bias<<<(TT * TT) / 256, 256>>>(rel_dec, bd, 0);

    auto T = [](const float* s, float* d, int K, int N, long ss, long ds, int cnt) {
        transpose_b<<<dim3(N / 32, K / 32, cnt), dim3(32, 8)>>>(s, d, K, N, ss, ds);
    };
    const long QS = 3 * WSZ, KS = 2 * WSZ;
    T(enc_wq, wAe + 0,       768, 768, WSZ, QS, 6);
    T(enc_wk, wAe + WSZ,     768, 768, WSZ, QS, 6);
    T(enc_wv, wAe + 2 * WSZ, 768, 768, WSZ, QS, 6);
    T(enc_wo, woe, 768, 768, WSZ, WSZ, 6);
    T(dec_sq, wAs + 0,       768, 768, WSZ, QS, 6);
    T(dec_sk, wAs + WSZ,     768, 768, WSZ, QS, 6);
    T(dec_sv, wAs + 2 * WSZ, 768, 768, WSZ, QS, 6);
    T(dec_so, wos, 768, 768, WSZ, WSZ, 6);
    T(dec_cq, cqT, 768, 768, WSZ, WSZ, 6);
    T(dec_ck, ckvT + 0,   768, 768, WSZ, KS, 6);
    T(dec_cv, ckvT + WSZ, 768, 768, WSZ, KS, 6);
    T(dec_co, coT, 768, 768, WSZ, WSZ, 6);
    T(enc_wi,  wie,  768, 3072, DMM, DMM, 6);
    T(enc_wmo, wmoe, 3072, 768, DMM, DMM, 6);
    T(dec_wi,  wid_, 768, 3072, DMM, DMM, 6);
    T(dec_wmo, wmod, 3072, 768, DMM, DMM, 6);
    T(logits_w, logT, 768, VV, 0, 0, 1);

    auto self_attn = [&](const float* hin, const float* wqkvT, const float* woT, float* x,
                         const float* bias, const int* vQ, const int* vK, int causal) {
        gemm_nt<false, false, true><<<dim3(18, 16), 256, SMEM_NT>>>(hin, wqkvT, qkv, DD, DD, DD, 2304);
        attn_scores_tc<<<dim3(4, 4, 48), 256, SMEM_NT>>>(qkv, 2304, qkv + 768, 2304, sc, bias, vQ, vK, causal);
        softmax_rows<<<BBATCH * HH * TT / 8, 256>>>(sc);
        gemm_pv<<<dim3(1, 4, 48), 256, SMEM_PV>>>(sc, qkv + 1536, ao, 2304);
        gemm_nt<true, false, false><<<dim3(6, 16), 256, SMEM_NT>>>(ao, woT, x, DD, DD, DD, DD);
    };
    auto mlp = [&](const float* hin, const float* wiT, const float* wmoT, float* x) {
        gemm_nt<false, true, true><<<dim3(24, 16), 256, SMEM_NT>>>(hin, wiT, hid, DD, DD, DD, MM);
        gemm_nt<true, false, false><<<dim3(6, 16), 256, SMEM_NT>>>(hid, wmoT, x, MM, MM, MM, DD);
    };

    // -------- encoder --------
    embed_k<<<NT, 256>>>(enc_tok, emb, xe);
    for (int l = 0; l < LL; l++) {
        rmsnorm_k<<<NT, 256>>>(xe, enc_ln1 + (size_t)l * DD, h);
        self_attn(h, wAe + l * QS, woe + l * WSZ, xe, be, ve, ve, 0);
        rmsnorm_k<<<NT, 256>>>(xe, enc_ln2 + (size_t)l * DD, h);
        mlp(h, wie + l * DMM, wmoe + l * DMM, xe);
    }
    rmsnorm_k<<<NT, 256>>>(xe, enc_norm, enc);

    // -------- decoder --------
    embed_k<<<NT, 256>>>(dec_in_tok, emb, xd);
    for (int l = 0; l < LL; l++) {
        rmsnorm_k<<<NT, 256>>>(xd, dec_ln1 + (size_t)l * DD, h);
        self_attn(h, wAs + l * QS, wos + l * WSZ, xd, bd, vt, vt, 1);
        rmsnorm_k<<<NT, 256>>>(xd, dec_ln2 + (size_t)l * DD, h);
        // cross attention
        gemm_nt<false, false, true><<<dim3(6, 16), 256, SMEM_NT>>>(h, cqT + l * WSZ, q, DD, DD, DD, DD);
        gemm_nt<false, false, true><<<dim3(12, 16), 256, SMEM_NT>>>(enc, ckvT + l * KS, kv, DD, DD, DD, 1536);
        attn_scores_tc<<<dim3(4, 4, 48), 256, SMEM_NT>>>(q, DD, kv, 1536, sc, nullptr, vt, ve, 0);
        softmax_rows<<<BBATCH * HH * TT / 8, 256>>>(sc);
        gemm_pv<<<dim3(1, 4, 48), 256, SMEM_PV>>>(sc, kv + 768, ao, 1536);
        gemm_nt<true, false, false><<<dim3(6, 16), 256, SMEM_NT>>>(ao, coT + l * WSZ, xd, DD, DD, DD, DD);
        rmsnorm_k<<<NT, 256>>>(xd, dec_ln3 + (size_t)l * DD, h);
        mlp(h, wid_ + l * DMM, wmod + l * DMM, xd);
    }
    rmsnorm_k<<<NT, 256>>>(xd, dec_norm, h);

    // -------- logits --------
    gemm_nt<false, false, false><<<dim3(251, 16), 256, SMEM_NT>>>(h, logT, (float*)d_out, DD, DD, DD, VV);
}

// round 8
// speedup vs baseline: 1.4805x; 1.0807x over previous
#include <cuda_runtime.h>
#include <math.h>
#include <stdint.h>

#define TT 512
#define BBATCH 4
#define NT 2048
#define DD 768
#define HH 12
#define HDIM 64
#define MM 3072
#define VV 32128
#define LL 6
#define NEGINF -1e10f
#define BK 32
#define WSZ ((long)DD * DD)
#define DMM ((long)DD * MM)

// ---------------- scratch ----------------
__device__ float g_xe[NT * DD];
__device__ float g_xd[NT * DD];
__device__ float g_enc[NT * DD];
__device__ float g_h[NT * DD];
__device__ float g_qkv[NT * 3 * DD];
__device__ float g_q[NT * DD];
__device__ float g_kv[NT * 2 * DD];
__device__ float g_ao[NT * DD];
__device__ float g_hid[NT * MM];
__device__ float g_bias_e[HH * TT * TT];
__device__ float g_bias_d[HH * TT * TT];
__device__ int   g_val_e[NT];
__device__ int   g_val_t[NT];
// transposed tf32-rounded weights [N,K]
__device__ float g_wA_e[LL * 3 * DD * DD];
__device__ float g_wo_e[LL * DD * DD];
__device__ float g_wA_s[LL * 3 * DD * DD];
__device__ float g_wo_s[LL * DD * DD];
__device__ float g_cqT [LL * DD * DD];
__device__ float g_ckvT[LL * 2 * DD * DD];
__device__ float g_coT [LL * DD * DD];
__device__ float g_wiT_e [LL * DD * MM];
__device__ float g_wmoT_e[LL * DD * MM];
__device__ float g_wiT_d [LL * DD * MM];
__device__ float g_wmoT_d[LL * DD * MM];
__device__ float g_logT[(long)VV * DD];

// ---------------- helpers ----------------
__device__ __forceinline__ void cp16(unsigned dst, const void* src)
{ asm volatile("cp.async.cg.shared.global [%0], [%1], 16;\n" :: "r"(dst), "l"(src)); }
__device__ __forceinline__ void cp_commit() { asm volatile("cp.async.commit_group;\n"); }
__device__ __forceinline__ void cp_wait1()  { asm volatile("cp.async.wait_group 1;\n"); }
__device__ __forceinline__ void cp_wait0()  { asm volatile("cp.async.wait_group 0;\n"); }

__device__ __forceinline__ unsigned tf32cvt(float x)
{ unsigned y; asm("cvt.rna.tf32.f32 %0, %1;" : "=r"(y) : "f"(x)); return y; }
__device__ __forceinline__ float tf32r(float x) { return __uint_as_float(tf32cvt(x)); }

__device__ __forceinline__ unsigned su32(const void* p)
{ return (unsigned)__cvta_generic_to_shared(p); }

__device__ __forceinline__ void ldsm4(unsigned a_, unsigned* a)
{
    asm volatile("ldmatrix.sync.aligned.m8n8.x4.shared.b16 {%0,%1,%2,%3}, [%4];"
                 : "=r"(a[0]), "=r"(a[1]), "=r"(a[2]), "=r"(a[3]) : "r"(a_));
}
__device__ __forceinline__ void ldsm2(unsigned a_, unsigned* b)
{
    asm volatile("ldmatrix.sync.aligned.m8n8.x2.shared.b16 {%0,%1}, [%2];"
                 : "=r"(b[0]), "=r"(b[1]) : "r"(a_));
}
__device__ __forceinline__ void mma8(float* c, const unsigned* a, const unsigned* b)
{
    asm volatile("mma.sync.aligned.m16n8k8.row.col.f32.tf32.tf32.f32 "
                 "{%0,%1,%2,%3}, {%4,%5,%6,%7}, {%8,%9}, {%0,%1,%2,%3};"
                 : "+f"(c[0]), "+f"(c[1]), "+f"(c[2]), "+f"(c[3])
                 : "r"(a[0]), "r"(a[1]), "r"(a[2]), "r"(a[3]), "r"(b[0]), "r"(b[1]));
}

// ---------------- transpose (+tf32 round): dst[N,K] = src[K,N] ----------------
__global__ void transpose_b(const float* __restrict__ src, float* __restrict__ dst,
                            int K, int N, long ss, long ds)
{
    __shared__ float t[32][33];
    const float* S = src + (long)blockIdx.z * ss;
    float* D = dst + (long)blockIdx.z * ds;
    int k0 = blockIdx.y * 32, n0 = blockIdx.x * 32;
    int tx = threadIdx.x, ty = threadIdx.y;
#pragma unroll
    for (int i = 0; i < 32; i += 8)
        t[ty + i][tx] = S[(long)(k0 + ty + i) * N + n0 + tx];
    __syncthreads();
#pragma unroll
    for (int i = 0; i < 32; i += 8)
        D[(long)(n0 + ty + i) * K + k0 + tx] = tf32r(t[tx][ty + i]);
}

// K-major tile loader: ROWS rows x 32 K-cols fp32, XOR-swizzled 16B chunks
template<int ROWS>
__device__ __forceinline__ void load_tileT(unsigned sbase, const float* P,
                                           int row0, int k0, int ld, int tid)
{
#pragma unroll
    for (int j = 0; j < ROWS / 32; j++) {
        int c = tid + 256 * j, m = c >> 3, kc = c & 7;
        cp16(sbase + (((m << 5) | ((kc ^ (m & 7)) << 2)) << 2),
             P + (long)(row0 + m) * ld + k0 + kc * 4);
    }
}

// ---------------- NT GEMM (legacy tf32 mma, both operands via ldmatrix) ----------------
template<bool ACC, bool RELU, bool RNA>
__global__ __launch_bounds__(256) void gemm_nt(
    const float* __restrict__ A, const float* __restrict__ Bt, float* __restrict__ C,
    int K, int lda, int ldb, int ldc)
{
    extern __shared__ float sm[];
    const unsigned asb = su32(sm);
    const unsigned bsb = su32(sm + 2 * 128 * BK);
    constexpr int STG = 128 * BK * 4;

    const int tid = threadIdx.x, lane = tid & 31, warp = tid >> 5;
    const int mw = (warp & 1) * 64, nw = (warp >> 1) * 32;
    const int m0 = blockIdx.y * 128, n0 = blockIdx.x * 128;

    float acc[4][4][4];
#pragma unroll
    for (int i = 0; i < 4; i++)
#pragma unroll
        for (int j = 0; j < 4; j++)
#pragma unroll
            for (int q = 0; q < 4; q++) acc[i][j][q] = 0.f;

    const int nk = K / BK;
    load_tileT<128>(asb, A, m0, 0, lda, tid);
    load_tileT<128>(bsb, Bt, n0, 0, ldb, tid);
    cp_commit();

    for (int kt = 0; kt < nk; kt++) {
        const int st = kt & 1;
        if (kt + 1 < nk) {
            load_tileT<128>(asb + (st ^ 1) * STG, A, m0, (kt + 1) * BK, lda, tid);
            load_tileT<128>(bsb + (st ^ 1) * STG, Bt, n0, (kt + 1) * BK, ldb, tid);
        }
        cp_commit();
        cp_wait1();
        __syncthreads();

        const unsigned ab = asb + st * STG;
        const unsigned bb = bsb + st * STG;
#pragma unroll
        for (int kk = 0; kk < BK; kk += 8) {
            unsigned a[4][4];
#pragma unroll
            for (int i = 0; i < 4; i++) {
                int r = mw + 16 * i + (lane & 7) + ((lane >> 3) & 1) * 8;
                int ch = (kk >> 2) + (lane >> 4);
                ldsm4(ab + (((r << 5) | ((ch ^ (r & 7)) << 2)) << 2), a[i]);
            }
            unsigned bf[4][2];
#pragma unroll
            for (int j = 0; j < 4; j++) {
                int r = nw + 8 * j + (lane & 7);
                int ch = (kk >> 2) + ((lane >> 3) & 1);
                ldsm2(bb + (((r << 5) | ((ch ^ (r & 7)) << 2)) << 2), bf[j]);
            }
#pragma unroll
            for (int i = 0; i < 4; i++)
#pragma unroll
                for (int j = 0; j < 4; j++) mma8(acc[i][j], a[i], bf[j]);
        }
        __syncthreads();
    }

#pragma unroll
    for (int i = 0; i < 4; i++) {
        int r = m0 + mw + 16 * i + (lane >> 2);
#pragma unroll
        for (int j = 0; j < 4; j++) {
            int cn = n0 + nw + 8 * j + ((lane & 3) << 1);
            float2* p0 = (float2*)(C + (long)r * ldc + cn);
            float2* p1 = (float2*)(C + (long)(r + 8) * ldc + cn);
            float2 v0 = make_float2(acc[i][j][0], acc[i][j][1]);
            float2 v1 = make_float2(acc[i][j][2], acc[i][j][3]);
            if (RELU) {
                v0.x = fmaxf(v0.x, 0.f); v0.y = fmaxf(v0.y, 0.f);
                v1.x = fmaxf(v1.x, 0.f); v1.y = fmaxf(v1.y, 0.f);
            }
            if (RNA) {
                v0.x = tf32r(v0.x); v0.y = tf32r(v0.y);
                v1.x = tf32r(v1.x); v1.y = tf32r(v1.y);
            }
            if (ACC) {
                float2 o0 = *p0, o1 = *p1;
                v0.x += o0.x; v0.y += o0.y; v1.x += o1.x; v1.y += o1.y;
            }
            *p0 = v0; *p1 = v1;
        }
    }
}

// ================= fused flash attention =================
// smem float offsets:
#define FQ   0        // Q: 2 chunks x 128x32         (8192)
#define FK   8192     // K: 2 bufs x 2 chunks x 128x32 (16384)
#define FV   24576    // V: 128 x 64 k-major            (8192)
#define FP   32768    // P: 128 x 128 swizzled          (16384)
#define FRED 49152    // red: [2][128][2]               (512)
#define FVK  49664    // validK (512 int)
#define FVQ  50176    // validQ (512 int)
#define FLOATS_TOTAL 50688
#define FASMEM (FLOATS_TOTAL * 4)

__global__ __launch_bounds__(256) void flash_attn(
    const float* __restrict__ Q, int ldq,
    const float* __restrict__ K, int ldk,
    const float* __restrict__ V, int ldv,
    const float* __restrict__ bias,
    const int* __restrict__ validQ, const int* __restrict__ validK,
    int causal, float* __restrict__ O)
{
    extern __shared__ float smf[];
    int* smi = (int*)smf;
    const unsigned sb = su32(smf);
    const int tid = threadIdx.x, lane = tid & 31, warp = tid >> 5;
    const int mw = (warp & 3) * 32;       // rows of warp tile
    const int nwid = warp >> 2;           // 0/1
    const int nw = nwid * 64;             // S cols
    const int nhd = nwid * 32;            // PV cols
    const int q0 = blockIdx.x * 128;
    const int z = blockIdx.y, b = z / HH, h = z % HH;
    const float* Qp = Q + (long)b * TT * ldq + h * HDIM;
    const float* Kp = K + (long)b * TT * ldk + h * HDIM;
    const float* Vp = V + (long)b * TT * ldv + h * HDIM;
    const float* biasH = bias ? bias + (long)h * TT * TT : nullptr;
    const int nt = TT / 128;   // always process all tiles (exact ref semantics)

    auto loadQ = [&]() {
#pragma unroll
        for (int cc = 0; cc < 2; cc++)
#pragma unroll
            for (int j = 0; j < 4; j++) {
                int c = tid + 256 * j, m = c >> 3, kc = c & 7;
                cp16(sb + ((FQ + cc * 4096) << 2) + ((m * 8 + (kc ^ (m & 7))) << 4),
                     Qp + (long)(q0 + m) * ldq + cc * 32 + kc * 4);
            }
    };
    auto loadK = [&](int buf, int st) {
        int s0 = st * 128;
#pragma unroll
        for (int cc = 0; cc < 2; cc++)
#pragma unroll
            for (int j = 0; j < 4; j++) {
                int c = tid + 256 * j, m = c >> 3, kc = c & 7;
                cp16(sb + ((FK + buf * 8192 + cc * 4096) << 2) + ((m * 8 + (kc ^ (m & 7))) << 4),
                     Kp + (long)(s0 + m) * ldk + cc * 32 + kc * 4);
            }
    };
    auto loadV = [&](int st) {
        int s0 = st * 128;
#pragma unroll
        for (int j = 0; j < 8; j++) {
            int c = tid + 256 * j, k = c >> 4, nc = c & 15;
            cp16(sb + (FV << 2) + ((k * 16 + (nc ^ (k & 7))) << 4),
                 Vp + (long)(s0 + k) * ldv + nc * 4);
        }
    };

    loadQ(); loadK(0, 0); cp_commit();
    loadV(0); cp_commit();
    loadK(1, 1); cp_commit();

    smi[FVK + tid] = validK[b * TT + tid];
    smi[FVK + 256 + tid] = validK[b * TT + 256 + tid];
    smi[FVQ + tid] = validQ[b * TT + tid];
    smi[FVQ + 256 + tid] = validQ[b * TT + 256 + tid];

    cp_wait1();
    __syncthreads();

    float m_run[2][2], s_run[2][2], oacc[2][4][4];
#pragma unroll
    for (int i = 0; i < 2; i++)
#pragma unroll
        for (int rr = 0; rr < 2; rr++) { m_run[i][rr] = -3.0e38f; s_run[i][rr] = 0.f; }
#pragma unroll
    for (int i = 0; i < 2; i++)
#pragma unroll
        for (int j = 0; j < 4; j++)
#pragma unroll
            for (int q = 0; q < 4; q++) oacc[i][j][q] = 0.f;

    for (int t = 0; t < nt; t++) {
        if (t >= 1) {
            loadV(t); cp_commit();
            if (t + 1 < nt) { loadK((t + 1) & 1, t + 1); cp_commit(); }
        }
        const int s0 = t * 128;

        // ---- S = Q K^T ----
        float acc[2][8][4];
#pragma unroll
        for (int i = 0; i < 2; i++)
#pragma unroll
            for (int j = 0; j < 8; j++)
#pragma unroll
                for (int q = 0; q < 4; q++) acc[i][j][q] = 0.f;

#pragma unroll
        for (int cc = 0; cc < 2; cc++) {
            const unsigned qb = sb + ((FQ + cc * 4096) << 2);
            const unsigned kb = sb + ((FK + (t & 1) * 8192 + cc * 4096) << 2);
#pragma unroll
            for (int kk = 0; kk < 32; kk += 8) {
                unsigned a[2][4];
#pragma unroll
                for (int i = 0; i < 2; i++) {
                    int r = mw + 16 * i + (lane & 7) + ((lane >> 3) & 1) * 8;
                    int ch = (kk >> 2) + (lane >> 4);
                    ldsm4(qb + ((r * 8 + (ch ^ (r & 7))) << 4), a[i]);
                }
                unsigned bf[8][2];
#pragma unroll
                for (int j = 0; j < 8; j++) {
                    int r = nw + 8 * j + (lane & 7);
                    int ch = (kk >> 2) + ((lane >> 3) & 1);
                    ldsm2(kb + ((r * 8 + (ch ^ (r & 7))) << 4), bf[j]);
                }
#pragma unroll
                for (int i = 0; i < 2; i++)
#pragma unroll
                    for (int j = 0; j < 8; j++) mma8(acc[i][j], a[i], bf[j]);
            }
        }

        // ---- bias + mask ----
#pragma unroll
        for (int i = 0; i < 2; i++)
#pragma unroll
            for (int rr = 0; rr < 2; rr++) {
                int Rl = mw + 16 * i + 8 * rr + (lane >> 2);
                int q = q0 + Rl;
                int vq = smi[FVQ + q];
#pragma unroll
                for (int j = 0; j < 8; j++) {
                    int Cl = nw + 8 * j + 2 * (lane & 3);
                    int s = s0 + Cl;
                    float b0 = 0.f, b1 = 0.f;
                    if (biasH) {
                        float2 bb = *(const float2*)(biasH + (long)q * TT + s);
                        b0 = bb.x; b1 = bb.y;
                    }
                    int2 vk = *(const int2*)(smi + FVK + s);
                    float v0 = acc[i][j][2 * rr + 0] + b0;
                    float v1 = acc[i][j][2 * rr + 1] + b1;
                    bool m0 = vq && vk.x && (!causal || s <= q);
                    bool m1 = vq && vk.y && (!causal || s + 1 <= q);
                    acc[i][j][2 * rr + 0] = m0 ? v0 : NEGINF;
                    acc[i][j][2 * rr + 1] = m1 ? v1 : NEGINF;
                }
            }

        // ---- online softmax: row max ----
        float mp[2][2];
#pragma unroll
        for (int i = 0; i < 2; i++)
#pragma unroll
            for (int rr = 0; rr < 2; rr++) {
                float m = -3.4e38f;
#pragma unroll
                for (int j = 0; j < 8; j++)
                    m = fmaxf(m, fmaxf(acc[i][j][2 * rr], acc[i][j][2 * rr + 1]));
                mp[i][rr] = m;
            }
#pragma unroll
        for (int o = 1; o <= 2; o <<= 1)
#pragma unroll
            for (int i = 0; i < 2; i++)
#pragma unroll
                for (int rr = 0; rr < 2; rr++)
                    mp[i][rr] = fmaxf(mp[i][rr], __shfl_xor_sync(0xffffffffu, mp[i][rr], o));
        if ((lane & 3) == 0) {
#pragma unroll
            for (int i = 0; i < 2; i++)
#pragma unroll
                for (int rr = 0; rr < 2; rr++) {
                    int Rl = mw + 16 * i + 8 * rr + (lane >> 2);
                    smf[FRED + Rl * 2 + nwid] = mp[i][rr];
                }
        }
        __syncthreads();

        float mnew[2][2], scl[2][2];
#pragma unroll
        for (int i = 0; i < 2; i++)
#pragma unroll
            for (int rr = 0; rr < 2; rr++) {
                int Rl = mw + 16 * i + 8 * rr + (lane >> 2);
                float mt = fmaxf(smf[FRED + Rl * 2], smf[FRED + Rl * 2 + 1]);
                float mn = fmaxf(m_run[i][rr], mt);
                scl[i][rr] = __expf(m_run[i][rr] - mn);
                m_run[i][rr] = mn;
                mnew[i][rr] = mn;
            }

        // ---- p = exp(s-m), stage P, partial sums ----
        float sp[2][2] = {{0.f, 0.f}, {0.f, 0.f}};
#pragma unroll
        for (int i = 0; i < 2; i++)
#pragma unroll
            for (int rr = 0; rr < 2; rr++) {
                int Rl = mw + 16 * i + 8 * rr + (lane >> 2);
#pragma unroll
                for (int j = 0; j < 8; j++) {
                    float p0 = __expf(acc[i][j][2 * rr + 0] - mnew[i][rr]);
                    float p1 = __expf(acc[i][j][2 * rr + 1] - mnew[i][rr]);
                    sp[i][rr] += p0 + p1;
                    int Cl = nw + 8 * j + 2 * (lane & 3);
                    int nc = Cl >> 2;
                    float2 pv = make_float2(tf32r(p0), tf32r(p1));
                    *(float2*)(smf + FP + Rl * 128 + ((nc ^ (Rl & 7)) << 2) + (Cl & 3)) = pv;
                }
            }
#pragma unroll
        for (int o = 1; o <= 2; o <<= 1)
#pragma unroll
            for (int i = 0; i < 2; i++)
#pragma unroll
                for (int rr = 0; rr < 2; rr++)
                    sp[i][rr] += __shfl_xor_sync(0xffffffffu, sp[i][rr], o);
        if ((lane & 3) == 0) {
#pragma unroll
            for (int i = 0; i < 2; i++)
#pragma unroll
                for (int rr = 0; rr < 2; rr++) {
                    int Rl = mw + 16 * i + 8 * rr + (lane >> 2);
                    smf[FRED + 256 + Rl * 2 + nwid] = sp[i][rr];
                }
        }
        if (t + 1 < nt) cp_wait1(); else cp_wait0();   // V(t) ready; K(t+1) may pend
        __syncthreads();

#pragma unroll
        for (int i = 0; i < 2; i++)
#pragma unroll
            for (int rr = 0; rr < 2; rr++) {
                int Rl = mw + 16 * i + 8 * rr + (lane >> 2);
                float st = smf[FRED + 256 + Rl * 2] + smf[FRED + 256 + Rl * 2 + 1];
                s_run[i][rr] = s_run[i][rr] * scl[i][rr] + st;
            }
        // rescale O accumulator
#pragma unroll
        for (int i = 0; i < 2; i++)
#pragma unroll
            for (int j = 0; j < 4; j++) {
                oacc[i][j][0] *= scl[i][0]; oacc[i][j][1] *= scl[i][0];
                oacc[i][j][2] *= scl[i][1]; oacc[i][j][3] *= scl[i][1];
            }

        // ---- PV: O += P * V ----
#pragma unroll
        for (int kk = 0; kk < 128; kk += 8) {
            unsigned a[2][4];
#pragma unroll
            for (int i = 0; i < 2; i++) {
                int r = mw + 16 * i + (lane & 7) + ((lane >> 3) & 1) * 8;
                int ch = (kk >> 2) + (lane >> 4);
                ldsm4(sb + (FP << 2) + ((r * 32 + (ch ^ (r & 7))) << 4), a[i]);
            }
            unsigned bf[4][2];
#pragma unroll
            for (int j = 0; j < 4; j++) {
                int n = nhd + 8 * j + (lane >> 2);
                int ncc = n >> 2, nr = n & 3;
                int k1 = kk + (lane & 3), k2 = k1 + 4;
                bf[j][0] = __float_as_uint(smf[FV + k1 * 64 + ((ncc ^ (k1 & 7)) << 2) + nr]);
                bf[j][1] = __float_as_uint(smf[FV + k2 * 64 + ((ncc ^ (k2 & 7)) << 2) + nr]);
            }
#pragma unroll
            for (int i = 0; i < 2; i++)
#pragma unroll
                for (int j = 0; j < 4; j++) mma8(oacc[i][j], a[i], bf[j]);
        }

        if (t + 1 < nt) { cp_wait0(); __syncthreads(); }   // K(t+1) ready; P safe to overwrite
    }

    // ---- epilogue: O / sum, tf32-round, store ----
    float* Op = O + (long)b * TT * DD + h * HDIM;
#pragma unroll
    for (int i = 0; i < 2; i++)
#pragma unroll
        for (int rr = 0; rr < 2; rr++) {
            int Rl = mw + 16 * i + 8 * rr + (lane >> 2);
            float inv = 1.0f / s_run[i][rr];
#pragma unroll
            for (int j = 0; j < 4; j++) {
                int cn = nhd + 8 * j + 2 * (lane & 3);
                float2 v = make_float2(tf32r(oacc[i][j][2 * rr + 0] * inv),
                                       tf32r(oacc[i][j][2 * rr + 1] * inv));
                *(float2*)(Op + (long)(q0 + Rl) * DD + cn) = v;
            }
        }
}

// ---------------- elementwise ----------------
__global__ void rmsnorm_k(const float* __restrict__ X, const float* __restrict__ scale,
                          float* __restrict__ O)
{
    int row = blockIdx.x, tid = threadIdx.x;
    const float* x = X + (size_t)row * DD;
    float s = 0.f;
    for (int d = tid; d < DD; d += 256) { float v = x[d]; s += v * v; }
    __shared__ float red[256];
    red[tid] = s;
    __syncthreads();
    for (int o = 128; o > 0; o >>= 1) { if (tid < o) red[tid] += red[tid + o]; __syncthreads(); }
    float r = 1.0f / sqrtf(red[0] / (float)DD + 1e-6f);
    for (int d = tid; d < DD; d += 256) O[(size_t)row * DD + d] = tf32r(x[d] * r * scale[d]);
}

__global__ void embed_k(const int* __restrict__ tok, const float* __restrict__ emb,
                        float* __restrict__ O)
{
    int t = blockIdx.x, token = tok[t];
    const float* e = emb + (size_t)token * DD;
    for (int d = threadIdx.x; d < DD; d += 256) O[(size_t)t * DD + d] = e[d];
}

__global__ void valid_k(const int* __restrict__ tok, int* __restrict__ v, int n)
{
    int i = blockIdx.x * blockDim.x + threadIdx.x;
    if (i < n) v[i] = tok[i] > 0 ? 1 : 0;
}

__global__ void build_bias(const float* __restrict__ rel, float* __restrict__ bias, int bidir)
{
    int idx = blockIdx.x * blockDim.x + threadIdx.x;
    if (idx >= TT * TT) return;
    int q = idx / TT, s = idx % TT;
    int n = q - s, bucket;
    if (bidir) {
        int ret = (n < 0) ? 16 : 0;
        int na = n < 0 ? -n : n;
        if (na < 8) bucket = ret + na;
        else { int v = 8 + (int)(log((double)na / 8.0) / log(16.0) * 8.0); bucket = ret + (v < 15 ? v : 15); }
    } else {
        int na = n > 0 ? n : 0;
        if (na < 16) bucket = na;
        else { int v = 16 + (int)(log((double)na / 16.0) / log(8.0) * 16.0); bucket = (v < 31 ? v : 31); }
    }
#pragma unroll
    for (int h = 0; h < HH; h++)
        bias[(size_t)h * TT * TT + idx] = rel[h * 32 + bucket];
}

// ---------------- host ----------------
#define SMEM_NT ((2 * 128 * BK + 2 * 128 * BK) * 4)   // 65536

static void set_attrs()
{
    cudaFuncSetAttribute(gemm_nt<false, false, true >, cudaFuncAttributeMaxDynamicSharedMemorySize, SMEM_NT);
    cudaFuncSetAttribute(gemm_nt<false, true,  true >, cudaFuncAttributeMaxDynamicSharedMemorySize, SMEM_NT);
    cudaFuncSetAttribute(gemm_nt<true,  false, false>, cudaFuncAttributeMaxDynamicSharedMemorySize, SMEM_NT);
    cudaFuncSetAttribute(gemm_nt<false, false, false>, cudaFuncAttributeMaxDynamicSharedMemorySize, SMEM_NT);
    cudaFuncSetAttribute(flash_attn, cudaFuncAttributeMaxDynamicSharedMemorySize, FASMEM);
}

extern "C" void kernel_launch(void* const* d_in, const int* in_sizes, int n_in,
                              void* d_out, int out_size)
{
    const float* emb      = (const float*)d_in[0];
    const float* rel_enc  = (const float*)d_in[1];
    const float* rel_dec  = (const float*)d_in[2];
    const float* enc_ln1  = (const float*)d_in[3];
    const float* enc_wq   = (const float*)d_in[4];
    const float* enc_wk   = (const float*)d_in[5];
    const float* enc_wv   = (const float*)d_in[6];
    const float* enc_wo   = (const float*)d_in[7];
    const float* enc_ln2  = (const float*)d_in[8];
    const float* enc_wi   = (const float*)d_in[9];
    const float* enc_wmo  = (const float*)d_in[10];
    const float* enc_norm = (const float*)d_in[11];
    const float* dec_ln1  = (const float*)d_in[12];
    const float* dec_sq   = (const float*)d_in[13];
    const float* dec_sk   = (const float*)d_in[14];
    const float* dec_sv   = (const float*)d_in[15];
    const float* dec_so   = (const float*)d_in[16];
    const float* dec_ln2  = (const float*)d_in[17];
    const float* dec_cq   = (const float*)d_in[18];
    const float* dec_ck   = (const float*)d_in[19];
    const float* dec_cv   = (const float*)d_in[20];
    const float* dec_co   = (const float*)d_in[21];
    const float* dec_ln3  = (const float*)d_in[22];
    const float* dec_wi   = (const float*)d_in[23];
    const float* dec_wmo  = (const float*)d_in[24];
    const float* dec_norm = (const float*)d_in[25];
    const float* logits_w = (const float*)d_in[26];
    const int* enc_tok    = (const int*)d_in[27];
    const int* dec_in_tok = (const int*)d_in[28];
    const int* dec_tgt    = (const int*)d_in[29];

    float *xe, *xd, *enc, *h, *qkv, *q, *kv, *ao, *hid, *be, *bd;
    float *wAe, *woe, *wAs, *wos, *cqT, *ckvT, *coT, *wie, *wmoe, *wid_, *wmod, *logT;
    int *ve, *vt;
    cudaGetSymbolAddress((void**)&xe, g_xe);     cudaGetSymbolAddress((void**)&xd, g_xd);
    cudaGetSymbolAddress((void**)&enc, g_enc);   cudaGetSymbolAddress((void**)&h, g_h);
    cudaGetSymbolAddress((void**)&qkv, g_qkv);   cudaGetSymbolAddress((void**)&q, g_q);
    cudaGetSymbolAddress((void**)&kv, g_kv);     cudaGetSymbolAddress((void**)&ao, g_ao);
    cudaGetSymbolAddress((void**)&hid, g_hid);
    cudaGetSymbolAddress((void**)&be, g_bias_e); cudaGetSymbolAddress((void**)&bd, g_bias_d);
    cudaGetSymbolAddress((void**)&ve, g_val_e);  cudaGetSymbolAddress((void**)&vt, g_val_t);
    cudaGetSymbolAddress((void**)&wAe, g_wA_e);  cudaGetSymbolAddress((void**)&woe, g_wo_e);
    cudaGetSymbolAddress((void**)&wAs, g_wA_s);  cudaGetSymbolAddress((void**)&wos, g_wo_s);
    cudaGetSymbolAddress((void**)&cqT, g_cqT);   cudaGetSymbolAddress((void**)&ckvT, g_ckvT);
    cudaGetSymbolAddress((void**)&coT, g_coT);   cudaGetSymbolAddress((void**)&wie, g_wiT_e);
    cudaGetSymbolAddress((void**)&wmoe, g_wmoT_e); cudaGetSymbolAddress((void**)&wid_, g_wiT_d);
    cudaGetSymbolAddress((void**)&wmod, g_wmoT_d); cudaGetSymbolAddress((void**)&logT, g_logT);

    set_attrs();

    valid_k<<<(NT + 255) / 256, 256>>>(enc_tok, ve, NT);
    valid_k<<<(NT + 255) / 256, 256>>>(dec_tgt, vt, NT);
    build_bias<<<(TT * TT) / 256, 256>>>(rel_enc, be, 1);
    build_bias<<<(TT * TT) / 256, 256>>>(rel_dec, bd, 0);

    auto T = [](const float* s, float* d, int K, int N, long ss, long ds, int cnt) {
        transpose_b<<<dim3(N / 32, K / 32, cnt), dim3(32, 8)>>>(s, d, K, N, ss, ds);
    };
    const long QS = 3 * WSZ, KS = 2 * WSZ;
    T(enc_wq, wAe + 0,       768, 768, WSZ, QS, 6);
    T(enc_wk, wAe + WSZ,     768, 768, WSZ, QS, 6);
    T(enc_wv, wAe + 2 * WSZ, 768, 768, WSZ, QS, 6);
    T(enc_wo, woe, 768, 768, WSZ, WSZ, 6);
    T(dec_sq, wAs + 0,       768, 768, WSZ, QS, 6);
    T(dec_sk, wAs + WSZ,     768, 768, WSZ, QS, 6);
    T(dec_sv, wAs + 2 * WSZ, 768, 768, WSZ, QS, 6);
    T(dec_so, wos, 768, 768, WSZ, WSZ, 6);
    T(dec_cq, cqT, 768, 768, WSZ, WSZ, 6);
    T(dec_ck, ckvT + 0,   768, 768, WSZ, KS, 6);
    T(dec_cv, ckvT + WSZ, 768, 768, WSZ, KS, 6);
    T(dec_co, coT, 768, 768, WSZ, WSZ, 6);
    T(enc_wi,  wie,  768, 3072, DMM, DMM, 6);
    T(enc_wmo, wmoe, 3072, 768, DMM, DMM, 6);
    T(dec_wi,  wid_, 768, 3072, DMM, DMM, 6);
    T(dec_wmo, wmod, 3072, 768, DMM, DMM, 6);
    T(logits_w, logT, 768, VV, 0, 0, 1);

    auto self_attn = [&](const float* hin, const float* wqkvT, const float* woT, float* x,
                         const float* bias, const int* vQ, const int* vK, int causal) {
        gemm_nt<false, false, true><<<dim3(18, 16), 256, SMEM_NT>>>(hin, wqkvT, qkv, DD, DD, DD, 2304);
        flash_attn<<<dim3(4, 48), 256, FASMEM>>>(qkv, 2304, qkv + 768, 2304, qkv + 1536, 2304,
                                                 bias, vQ, vK, causal, ao);
        gemm_nt<true, false, false><<<dim3(6, 16), 256, SMEM_NT>>>(ao, woT, x, DD, DD, DD, DD);
    };
    auto mlp = [&](const float* hin, const float* wiT, const float* wmoT, float* x) {
        gemm_nt<false, true, true><<<dim3(24, 16), 256, SMEM_NT>>>(hin, wiT, hid, DD, DD, DD, MM);
        gemm_nt<true, false, false><<<dim3(6, 16), 256, SMEM_NT>>>(hid, wmoT, x, MM, MM, MM, DD);
    };

    // -------- encoder --------
    embed_k<<<NT, 256>>>(enc_tok, emb, xe);
    for (int l = 0; l < LL; l++) {
        rmsnorm_k<<<NT, 256>>>(xe, enc_ln1 + (size_t)l * DD, h);
        self_attn(h, wAe + l * QS, woe + l * WSZ, xe, be, ve, ve, 0);
        rmsnorm_k<<<NT, 256>>>(xe, enc_ln2 + (size_t)l * DD, h);
        mlp(h, wie + l * DMM, wmoe + l * DMM, xe);
    }
    rmsnorm_k<<<NT, 256>>>(xe, enc_norm, enc);

    // -------- decoder --------
    embed_k<<<NT, 256>>>(dec_in_tok, emb, xd);
    for (int l = 0; l < LL; l++) {
        rmsnorm_k<<<NT, 256>>>(xd, dec_ln1 + (size_t)l * DD, h);
        self_attn(h, wAs + l * QS, wos + l * WSZ, xd, bd, vt, vt, 1);
        rmsnorm_k<<<NT, 256>>>(xd, dec_ln2 + (size_t)l * DD, h);
        // cross attention
        gemm_nt<false, false, true><<<dim3(6, 16), 256, SMEM_NT>>>(h, cqT + l * WSZ, q, DD, DD, DD, DD);
        gemm_nt<false, false, true><<<dim3(12, 16), 256, SMEM_NT>>>(enc, ckvT + l * KS, kv, DD, DD, DD, 1536);
        flash_attn<<<dim3(4, 48), 256, FASMEM>>>(q, DD, kv, 1536, kv + 768, 1536,
                                                 nullptr, vt, ve, 0, ao);
        gemm_nt<true, false, false><<<dim3(6, 16), 256, SMEM_NT>>>(ao, coT + l * WSZ, xd, DD, DD, DD, DD);
        rmsnorm_k<<<NT, 256>>>(xd, dec_ln3 + (size_t)l * DD, h);
        mlp(h, wid_ + l * DMM, wmod + l * DMM, xd);
    }
    rmsnorm_k<<<NT, 256>>>(xd, dec_norm, h);

    // -------- logits --------
    gemm_nt<false, false, false><<<dim3(251, 16), 256, SMEM_NT>>>(h, logT, (float*)d_out, DD, DD, DD, VV);
}

// round 9
// speedup vs baseline: 2.4559x; 1.6589x over previous
#include <cuda_runtime.h>
#include <cuda_fp16.h>
#include <math.h>
#include <stdint.h>

#define TT 512
#define BBATCH 4
#define NT 2048
#define DD 768
#define HH 12
#define HDIM 64
#define MM 3072
#define VV 32128
#define LL 6
#define NEGINF -1e10f
#define WSZ ((long)DD * DD)
#define DMM ((long)DD * MM)

// ---------------- scratch ----------------
__device__ float  g_xe[NT * DD];
__device__ float  g_xd[NT * DD];
__device__ __half g_enc[NT * DD];
__device__ __half g_h[NT * DD];
__device__ __half g_qkv[NT * 3 * DD];
__device__ __half g_q[NT * DD];
__device__ __half g_kv[NT * 2 * DD];
__device__ __half g_ao[NT * DD];
__device__ __half g_hid[NT * MM];
__device__ float  g_bias_e[HH * TT * TT];
__device__ float  g_bias_d[HH * TT * TT];
__device__ int    g_val_e[NT];
__device__ int    g_val_t[NT];
// transposed fp16 weights [N,K]
__device__ __half g_wA_e[LL * 3 * DD * DD];
__device__ __half g_wo_e[LL * DD * DD];
__device__ __half g_wA_s[LL * 3 * DD * DD];
__device__ __half g_wo_s[LL * DD * DD];
__device__ __half g_cqT [LL * DD * DD];
__device__ __half g_ckvT[LL * 2 * DD * DD];
__device__ __half g_coT [LL * DD * DD];
__device__ __half g_wiT_e [LL * DD * MM];
__device__ __half g_wmoT_e[LL * DD * MM];
__device__ __half g_wiT_d [LL * DD * MM];
__device__ __half g_wmoT_d[LL * DD * MM];
__device__ __half g_logT[(long)VV * DD];

// ---------------- helpers ----------------
__device__ __forceinline__ void cp16(unsigned dst, const void* src)
{ asm volatile("cp.async.cg.shared.global [%0], [%1], 16;\n" :: "r"(dst), "l"(src)); }
__device__ __forceinline__ void cp_commit() { asm volatile("cp.async.commit_group;\n"); }
__device__ __forceinline__ void cp_wait1()  { asm volatile("cp.async.wait_group 1;\n"); }
__device__ __forceinline__ void cp_wait0()  { asm volatile("cp.async.wait_group 0;\n"); }

__device__ __forceinline__ unsigned su32(const void* p)
{ return (unsigned)__cvta_generic_to_shared(p); }

__device__ __forceinline__ void ldsm4(unsigned a_, unsigned* a)
{
    asm volatile("ldmatrix.sync.aligned.m8n8.x4.shared.b16 {%0,%1,%2,%3}, [%4];"
                 : "=r"(a[0]), "=r"(a[1]), "=r"(a[2]), "=r"(a[3]) : "r"(a_));
}
__device__ __forceinline__ void ldsm2(unsigned a_, unsigned* b)
{
    asm volatile("ldmatrix.sync.aligned.m8n8.x2.shared.b16 {%0,%1}, [%2];"
                 : "=r"(b[0]), "=r"(b[1]) : "r"(a_));
}
__device__ __forceinline__ void ldsm2t(unsigned a_, unsigned* b)
{
    asm volatile("ldmatrix.sync.aligned.m8n8.x2.trans.shared.b16 {%0,%1}, [%2];"
                 : "=r"(b[0]), "=r"(b[1]) : "r"(a_));
}
__device__ __forceinline__ void mma16(float* c, const unsigned* a, const unsigned* b)
{
    asm volatile("mma.sync.aligned.m16n8k16.row.col.f32.f16.f16.f32 "
                 "{%0,%1,%2,%3}, {%4,%5,%6,%7}, {%8,%9}, {%0,%1,%2,%3};"
                 : "+f"(c[0]), "+f"(c[1]), "+f"(c[2]), "+f"(c[3])
                 : "r"(a[0]), "r"(a[1]), "r"(a[2]), "r"(a[3]), "r"(b[0]), "r"(b[1]));
}

// ---------------- transpose (+fp16 cvt): dst[N,K] = src[K,N] ----------------
__global__ void transpose_b(const float* __restrict__ src, __half* __restrict__ dst,
                            int K, int N, long ss, long ds)
{
    __shared__ float t[32][33];
    const float* S = src + (long)blockIdx.z * ss;
    __half* D = dst + (long)blockIdx.z * ds;
    int k0 = blockIdx.y * 32, n0 = blockIdx.x * 32;
    int tx = threadIdx.x, ty = threadIdx.y;
#pragma unroll
    for (int i = 0; i < 32; i += 8)
        t[ty + i][tx] = S[(long)(k0 + ty + i) * N + n0 + tx];
    __syncthreads();
#pragma unroll
    for (int i = 0; i < 32; i += 8)
        D[(long)(n0 + ty + i) * K + k0 + tx] = __float2half_rn(t[tx][ty + i]);
}

// tile loader: 128 rows x 64 halves, swizzled 16B (8-half) chunks
__device__ __forceinline__ void load_tileH(unsigned sbase, const __half* P,
                                           int row0, int k0, int ld, int tid)
{
#pragma unroll
    for (int j = 0; j < 4; j++) {
        int c = tid + 256 * j, m = c >> 3, kc = c & 7;
        cp16(sbase + ((m * 8 + (kc ^ (m & 7))) << 4),
             P + (long)(row0 + m) * ld + k0 + kc * 8);
    }
}

// ---------------- fp16 NT GEMM: C[M,N](+)= A[M,K]*Bt[N,K]^T ----------------
// OUTH: write C as half; else fp32. ACC: fp32 residual accumulate.
template<bool ACC, bool RELU, bool OUTH>
__global__ __launch_bounds__(256) void gemm_h(
    const __half* __restrict__ A, const __half* __restrict__ Bt, void* __restrict__ Cv,
    int K, int lda, int ldb, int ldc)
{
    extern __shared__ char smc[];
    const unsigned asb = su32(smc);
    const unsigned bsb = asb + 32768;
    constexpr int STG = 16384;

    const int tid = threadIdx.x, lane = tid & 31, warp = tid >> 5;
    const int mw = (warp & 1) * 64, nw = (warp >> 1) * 32;
    const int m0 = blockIdx.y * 128, n0 = blockIdx.x * 128;

    float acc[4][4][4];
#pragma unroll
    for (int i = 0; i < 4; i++)
#pragma unroll
        for (int j = 0; j < 4; j++)
#pragma unroll
            for (int q = 0; q < 4; q++) acc[i][j][q] = 0.f;

    const int nk = K >> 6;
    load_tileH(asb, A, m0, 0, lda, tid);
    load_tileH(bsb, Bt, n0, 0, ldb, tid);
    cp_commit();

    for (int kt = 0; kt < nk; kt++) {
        const int st = kt & 1;
        if (kt + 1 < nk) {
            load_tileH(asb + (st ^ 1) * STG, A, m0, (kt + 1) << 6, lda, tid);
            load_tileH(bsb + (st ^ 1) * STG, Bt, n0, (kt + 1) << 6, ldb, tid);
        }
        cp_commit();
        cp_wait1();
        __syncthreads();

        const unsigned ab = asb + st * STG;
        const unsigned bb = bsb + st * STG;
#pragma unroll
        for (int kk = 0; kk < 64; kk += 16) {
            unsigned a[4][4];
#pragma unroll
            for (int i = 0; i < 4; i++) {
                int r = mw + 16 * i + (lane & 15);
                int ch = (kk >> 3) + (lane >> 4);
                ldsm4(ab + ((r * 8 + (ch ^ (r & 7))) << 4), a[i]);
            }
            unsigned bf[4][2];
#pragma unroll
            for (int j = 0; j < 4; j++) {
                int r = nw + 8 * j + (lane & 7);
                int ch = (kk >> 3) + ((lane >> 3) & 1);
                ldsm2(bb + ((r * 8 + (ch ^ (r & 7))) << 4), bf[j]);
            }
#pragma unroll
            for (int i = 0; i < 4; i++)
#pragma unroll
                for (int j = 0; j < 4; j++) mma16(acc[i][j], a[i], bf[j]);
        }
        __syncthreads();
    }

#pragma unroll
    for (int i = 0; i < 4; i++) {
        int r = m0 + mw + 16 * i + (lane >> 2);
#pragma unroll
        for (int j = 0; j < 4; j++) {
            int cn = n0 + nw + 8 * j + ((lane & 3) << 1);
            float2 v0 = make_float2(acc[i][j][0], acc[i][j][1]);
            float2 v1 = make_float2(acc[i][j][2], acc[i][j][3]);
            if (RELU) {
                v0.x = fmaxf(v0.x, 0.f); v0.y = fmaxf(v0.y, 0.f);
                v1.x = fmaxf(v1.x, 0.f); v1.y = fmaxf(v1.y, 0.f);
            }
            if (OUTH) {
                __half* C = (__half*)Cv;
                *(__half2*)(C + (long)r * ldc + cn)       = __floats2half2_rn(v0.x, v0.y);
                *(__half2*)(C + (long)(r + 8) * ldc + cn) = __floats2half2_rn(v1.x, v1.y);
            } else {
                float* C = (float*)Cv;
                float2* p0 = (float2*)(C + (long)r * ldc + cn);
                float2* p1 = (float2*)(C + (long)(r + 8) * ldc + cn);
                if (ACC) {
                    float2 o0 = *p0, o1 = *p1;
                    v0.x += o0.x; v0.y += o0.y; v1.x += o1.x; v1.y += o1.y;
                }
                *p0 = v0; *p1 = v1;
            }
        }
    }
}

// ================= fused flash attention (fp16 operands) =================
// byte offsets in dynamic smem:
#define BQ   0         // Q 128x64 half              (16384)
#define BKT  16384     // K 2 bufs x 128x64 half     (32768)
#define BV   49152     // V 128x64 half              (16384)
#define BP   65536     // P 128x128 half             (32768)
#define BRED 98304     // red [2][128][2] float      (2048)
#define BVK  100352    // validK 512 int             (2048)
#define BVQ  102400    // validQ 512 int             (2048)
#define FASMEM 104448

__global__ __launch_bounds__(256) void flash_attn(
    const __half* __restrict__ Q, int ldq,
    const __half* __restrict__ K, int ldk,
    const __half* __restrict__ V, int ldv,
    const float* __restrict__ bias,
    const int* __restrict__ validQ, const int* __restrict__ validK,
    int causal, __half* __restrict__ O)
{
    extern __shared__ char smc[];
    float* smf = (float*)smc;
    int* smi = (int*)smc;
    const unsigned sb = su32(smc);
    const int tid = threadIdx.x, lane = tid & 31, warp = tid >> 5;
    const int mw = (warp & 3) * 32;
    const int nwid = warp >> 2;
    const int nw = nwid * 64;
    const int nhd = nwid * 32;
    const int q0 = blockIdx.x * 128;
    const int z = blockIdx.y, b = z / HH, h = z % HH;
    const __half* Qp = Q + (long)b * TT * ldq + h * HDIM;
    const __half* Kp = K + (long)b * TT * ldk + h * HDIM;
    const __half* Vp = V + (long)b * TT * ldv + h * HDIM;
    const float* biasH = bias ? bias + (long)h * TT * TT : nullptr;
    const int nt = TT / 128;

    auto loadQ = [&]() {
#pragma unroll
        for (int j = 0; j < 4; j++) {
            int c = tid + 256 * j, m = c >> 3, kc = c & 7;
            cp16(sb + BQ + ((m * 8 + (kc ^ (m & 7))) << 4),
                 Qp + (long)(q0 + m) * ldq + kc * 8);
        }
    };
    auto loadK = [&](int buf, int st) {
        int s0 = st * 128;
#pragma unroll
        for (int j = 0; j < 4; j++) {
            int c = tid + 256 * j, m = c >> 3, kc = c & 7;
            cp16(sb + BKT + buf * 16384 + ((m * 8 + (kc ^ (m & 7))) << 4),
                 Kp + (long)(s0 + m) * ldk + kc * 8);
        }
    };
    auto loadV = [&](int st) {
        int s0 = st * 128;
#pragma unroll
        for (int j = 0; j < 4; j++) {
            int c = tid + 256 * j, k = c >> 3, nc = c & 7;
            cp16(sb + BV + ((k * 8 + (nc ^ (k & 7))) << 4),
                 Vp + (long)(s0 + k) * ldv + nc * 8);
        }
    };

    loadQ(); loadK(0, 0); cp_commit();
    loadV(0); cp_commit();
    loadK(1, 1); cp_commit();

    smi[(BVK >> 2) + tid] = validK[b * TT + tid];
    smi[(BVK >> 2) + 256 + tid] = validK[b * TT + 256 + tid];
    smi[(BVQ >> 2) + tid] = validQ[b * TT + tid];
    smi[(BVQ >> 2) + 256 + tid] = validQ[b * TT + 256 + tid];

    cp_wait1();
    __syncthreads();

    float m_run[2][2], s_run[2][2], oacc[2][4][4];
#pragma unroll
    for (int i = 0; i < 2; i++)
#pragma unroll
        for (int rr = 0; rr < 2; rr++) { m_run[i][rr] = -3.0e38f; s_run[i][rr] = 0.f; }
#pragma unroll
    for (int i = 0; i < 2; i++)
#pragma unroll
        for (int j = 0; j < 4; j++)
#pragma unroll
            for (int q = 0; q < 4; q++) oacc[i][j][q] = 0.f;

    for (int t = 0; t < nt; t++) {
        if (t >= 1) {
            loadV(t); cp_commit();
            if (t + 1 < nt) { loadK((t + 1) & 1, t + 1); cp_commit(); }
        }
        const int s0 = t * 128;

        // ---- S = Q K^T ----
        float acc[2][8][4];
#pragma unroll
        for (int i = 0; i < 2; i++)
#pragma unroll
            for (int j = 0; j < 8; j++)
#pragma unroll
                for (int q = 0; q < 4; q++) acc[i][j][q] = 0.f;

        const unsigned kb = sb + BKT + (t & 1) * 16384;
#pragma unroll
        for (int kk = 0; kk < 64; kk += 16) {
            unsigned a[2][4];
#pragma unroll
            for (int i = 0; i < 2; i++) {
                int r = mw + 16 * i + (lane & 15);
                int ch = (kk >> 3) + (lane >> 4);
                ldsm4(sb + BQ + ((r * 8 + (ch ^ (r & 7))) << 4), a[i]);
            }
            unsigned bf[8][2];
#pragma unroll
            for (int j = 0; j < 8; j++) {
                int r = nw + 8 * j + (lane & 7);
                int ch = (kk >> 3) + ((lane >> 3) & 1);
                ldsm2(kb + ((r * 8 + (ch ^ (r & 7))) << 4), bf[j]);
            }
#pragma unroll
            for (int i = 0; i < 2; i++)
#pragma unroll
                for (int j = 0; j < 8; j++) mma16(acc[i][j], a[i], bf[j]);
        }

        // ---- bias + mask ----
#pragma unroll
        for (int i = 0; i < 2; i++)
#pragma unroll
            for (int rr = 0; rr < 2; rr++) {
                int Rl = mw + 16 * i + 8 * rr + (lane >> 2);
                int q = q0 + Rl;
                int vq = smi[(BVQ >> 2) + q];
#pragma unroll
                for (int j = 0; j < 8; j++) {
                    int Cl = nw + 8 * j + 2 * (lane & 3);
                    int s = s0 + Cl;
                    float b0 = 0.f, b1 = 0.f;
                    if (biasH) {
                        float2 bb = *(const float2*)(biasH + (long)q * TT + s);
                        b0 = bb.x; b1 = bb.y;
                    }
                    int2 vk = *(const int2*)(smi + (BVK >> 2) + s);
                    float v0 = acc[i][j][2 * rr + 0] + b0;
                    float v1 = acc[i][j][2 * rr + 1] + b1;
                    bool m0 = vq && vk.x && (!causal || s <= q);
                    bool m1 = vq && vk.y && (!causal || s + 1 <= q);
                    acc[i][j][2 * rr + 0] = m0 ? v0 : NEGINF;
                    acc[i][j][2 * rr + 1] = m1 ? v1 : NEGINF;
                }
            }

        // ---- row max ----
        float mp[2][2];
#pragma unroll
        for (int i = 0; i < 2; i++)
#pragma unroll
            for (int rr = 0; rr < 2; rr++) {
                float m = -3.4e38f;
#pragma unroll
                for (int j = 0; j < 8; j++)
                    m = fmaxf(m, fmaxf(acc[i][j][2 * rr], acc[i][j][2 * rr + 1]));
                mp[i][rr] = m;
            }
#pragma unroll
        for (int o = 1; o <= 2; o <<= 1)
#pragma unroll
            for (int i = 0; i < 2; i++)
#pragma unroll
                for (int rr = 0; rr < 2; rr++)
                    mp[i][rr] = fmaxf(mp[i][rr], __shfl_xor_sync(0xffffffffu, mp[i][rr], o));
        if ((lane & 3) == 0) {
#pragma unroll
            for (int i = 0; i < 2; i++)
#pragma unroll
                for (int rr = 0; rr < 2; rr++) {
                    int Rl = mw + 16 * i + 8 * rr + (lane >> 2);
                    smf[(BRED >> 2) + Rl * 2 + nwid] = mp[i][rr];
                }
        }
        __syncthreads();

        float mnew[2][2], scl[2][2];
#pragma unroll
        for (int i = 0; i < 2; i++)
#pragma unroll
            for (int rr = 0; rr < 2; rr++) {
                int Rl = mw + 16 * i + 8 * rr + (lane >> 2);
                float mt = fmaxf(smf[(BRED >> 2) + Rl * 2], smf[(BRED >> 2) + Rl * 2 + 1]);
                float mn = fmaxf(m_run[i][rr], mt);
                scl[i][rr] = __expf(m_run[i][rr] - mn);
                m_run[i][rr] = mn;
                mnew[i][rr] = mn;
            }

        // ---- p = exp(s-m), stage P (fp16), partial sums ----
        float sp[2][2] = {{0.f, 0.f}, {0.f, 0.f}};
#pragma unroll
        for (int i = 0; i < 2; i++)
#pragma unroll
            for (int rr = 0; rr < 2; rr++) {
                int Rl = mw + 16 * i + 8 * rr + (lane >> 2);
#pragma unroll
                for (int j = 0; j < 8; j++) {
                    float p0 = __expf(acc[i][j][2 * rr + 0] - mnew[i][rr]);
                    float p1 = __expf(acc[i][j][2 * rr + 1] - mnew[i][rr]);
                    sp[i][rr] += p0 + p1;
                    int Cl = nw + 8 * j + 2 * (lane & 3);
                    int nc = Cl >> 3;
                    *(__half2*)(smc + BP + Rl * 256 + ((nc ^ (Rl & 7)) << 4) + (Cl & 7) * 2) =
                        __floats2half2_rn(p0, p1);
                }
            }
#pragma unroll
        for (int o = 1; o <= 2; o <<= 1)
#pragma unroll
            for (int i = 0; i < 2; i++)
#pragma unroll
                for (int rr = 0; rr < 2; rr++)
                    sp[i][rr] += __shfl_xor_sync(0xffffffffu, sp[i][rr], o);
        if ((lane & 3) == 0) {
#pragma unroll
            for (int i = 0; i < 2; i++)
#pragma unroll
                for (int rr = 0; rr < 2; rr++) {
                    int Rl = mw + 16 * i + 8 * rr + (lane >> 2);
                    smf[(BRED >> 2) + 256 + Rl * 2 + nwid] = sp[i][rr];
                }
        }
        if (t + 1 < nt) cp_wait1(); else cp_wait0();
        __syncthreads();

#pragma unroll
        for (int i = 0; i < 2; i++)
#pragma unroll
            for (int rr = 0; rr < 2; rr++) {
                int Rl = mw + 16 * i + 8 * rr + (lane >> 2);
                float st = smf[(BRED >> 2) + 256 + Rl * 2] + smf[(BRED >> 2) + 256 + Rl * 2 + 1];
                s_run[i][rr] = s_run[i][rr] * scl[i][rr] + st;
            }
#pragma unroll
        for (int i = 0; i < 2; i++)
#pragma unroll
            for (int j = 0; j < 4; j++) {
                oacc[i][j][0] *= scl[i][0]; oacc[i][j][1] *= scl[i][0];
                oacc[i][j][2] *= scl[i][1]; oacc[i][j][3] *= scl[i][1];
            }

        // ---- PV: O += P * V ----
#pragma unroll
        for (int kk = 0; kk < 128; kk += 16) {
            unsigned a[2][4];
#pragma unroll
            for (int i = 0; i < 2; i++) {
                int r = mw + 16 * i + (lane & 15);
                int ch = (kk >> 3) + (lane >> 4);
                ldsm4(sb + BP + ((r * 16 + (ch ^ (r & 7))) << 4), a[i]);
            }
            unsigned bf[4][2];
#pragma unroll
            for (int j = 0; j < 4; j++) {
                int n0c = (nhd + 8 * j) >> 3;
                int r = kk + (lane & 7) + ((lane >> 3) & 1) * 8;
                ldsm2t(sb + BV + ((r * 8 + (n0c ^ (r & 7))) << 4), bf[j]);
            }
#pragma unroll
            for (int i = 0; i < 2; i++)
#pragma unroll
                for (int j = 0; j < 4; j++) mma16(oacc[i][j], a[i], bf[j]);
        }

        if (t + 1 < nt) { cp_wait0(); __syncthreads(); }
    }

    // ---- epilogue ----
    __half* Op = O + (long)b * TT * DD + h * HDIM;
#pragma unroll
    for (int i = 0; i < 2; i++)
#pragma unroll
        for (int rr = 0; rr < 2; rr++) {
            int Rl = mw + 16 * i + 8 * rr + (lane >> 2);
            float inv = 1.0f / s_run[i][rr];
#pragma unroll
            for (int j = 0; j < 4; j++) {
                int cn = nhd + 8 * j + 2 * (lane & 3);
                *(__half2*)(Op + (long)(q0 + Rl) * DD + cn) =
                    __floats2half2_rn(oacc[i][j][2 * rr + 0] * inv,
                                      oacc[i][j][2 * rr + 1] * inv);
            }
        }
}

// ---------------- elementwise ----------------
__global__ void rmsnorm_k(const float* __restrict__ X, const float* __restrict__ scale,
                          __half* __restrict__ O)
{
    int row = blockIdx.x, tid = threadIdx.x;
    const float* x = X + (size_t)row * DD;
    float s = 0.f;
    for (int d = tid; d < DD; d += 256) { float v = x[d]; s += v * v; }
    __shared__ float red[256];
    red[tid] = s;
    __syncthreads();
    for (int o = 128; o > 0; o >>= 1) { if (tid < o) red[tid] += red[tid + o]; __syncthreads(); }
    float r = 1.0f / sqrtf(red[0] / (float)DD + 1e-6f);
    for (int d = tid; d < DD; d += 256)
        O[(size_t)row * DD + d] = __float2half_rn(x[d] * r * scale[d]);
}

__global__ void embed_k(const int* __restrict__ tok, const float* __restrict__ emb,
                        float* __restrict__ O)
{
    int t = blockIdx.x, token = tok[t];
    const float* e = emb + (size_t)token * DD;
    for (int d = threadIdx.x; d < DD; d += 256) O[(size_t)t * DD + d] = e[d];
}

__global__ void valid_k(const int* __restrict__ tok, int* __restrict__ v, int n)
{
    int i = blockIdx.x * blockDim.x + threadIdx.x;
    if (i < n) v[i] = tok[i] > 0 ? 1 : 0;
}

__global__ void build_bias(const float* __restrict__ rel, float* __restrict__ bias, int bidir)
{
    int idx = blockIdx.x * blockDim.x + threadIdx.x;
    if (idx >= TT * TT) return;
    int q = idx / TT, s = idx % TT;
    int n = q - s, bucket;
    if (bidir) {
        int ret = (n < 0) ? 16 : 0;
        int na = n < 0 ? -n : n;
        if (na < 8) bucket = ret + na;
        else { int v = 8 + (int)(log((double)na / 8.0) / log(16.0) * 8.0); bucket = ret + (v < 15 ? v : 15); }
    } else {
        int na = n > 0 ? n : 0;
        if (na < 16) bucket = na;
        else { int v = 16 + (int)(log((double)na / 16.0) / log(8.0) * 16.0); bucket = (v < 31 ? v : 31); }
    }
#pragma unroll
    for (int h = 0; h < HH; h++)
        bias[(size_t)h * TT * TT + idx] = rel[h * 32 + bucket];
}

// ---------------- host ----------------
#define SMEM_G 65536

static void set_attrs()
{
    cudaFuncSetAttribute(gemm_h<false, false, true >, cudaFuncAttributeMaxDynamicSharedMemorySize, SMEM_G);
    cudaFuncSetAttribute(gemm_h<false, true,  true >, cudaFuncAttributeMaxDynamicSharedMemorySize, SMEM_G);
    cudaFuncSetAttribute(gemm_h<true,  false, false>, cudaFuncAttributeMaxDynamicSharedMemorySize, SMEM_G);
    cudaFuncSetAttribute(gemm_h<false, false, false>, cudaFuncAttributeMaxDynamicSharedMemorySize, SMEM_G);
    cudaFuncSetAttribute(flash_attn, cudaFuncAttributeMaxDynamicSharedMemorySize, FASMEM);
}

extern "C" void kernel_launch(void* const* d_in, const int* in_sizes, int n_in,
                              void* d_out, int out_size)
{
    const float* emb      = (const float*)d_in[0];
    const float* rel_enc  = (const float*)d_in[1];
    const float* rel_dec  = (const float*)d_in[2];
    const float* enc_ln1  = (const float*)d_in[3];
    const float* enc_wq   = (const float*)d_in[4];
    const float* enc_wk   = (const float*)d_in[5];
    const float* enc_wv   = (const float*)d_in[6];
    const float* enc_wo   = (const float*)d_in[7];
    const float* enc_ln2  = (const float*)d_in[8];
    const float* enc_wi   = (const float*)d_in[9];
    const float* enc_wmo  = (const float*)d_in[10];
    const float* enc_norm = (const float*)d_in[11];
    const float* dec_ln1  = (const float*)d_in[12];
    const float* dec_sq   = (const float*)d_in[13];
    const float* dec_sk   = (const float*)d_in[14];
    const float* dec_sv   = (const float*)d_in[15];
    const float* dec_so   = (const float*)d_in[16];
    const float* dec_ln2  = (const float*)d_in[17];
    const float* dec_cq   = (const float*)d_in[18];
    const float* dec_ck   = (const float*)d_in[19];
    const float* dec_cv   = (const float*)d_in[20];
    const float* dec_co   = (const float*)d_in[21];
    const float* dec_ln3  = (const float*)d_in[22];
    const float* dec_wi   = (const float*)d_in[23];
    const float* dec_wmo  = (const float*)d_in[24];
    const float* dec_norm = (const float*)d_in[25];
    const float* logits_w = (const float*)d_in[26];
    const int* enc_tok    = (const int*)d_in[27];
    const int* dec_in_tok = (const int*)d_in[28];
    const int* dec_tgt    = (const int*)d_in[29];

    float *xe, *xd, *be, *bd;
    __half *enc, *h, *qkv, *q, *kv, *ao, *hid;
    __half *wAe, *woe, *wAs, *wos, *cqT, *ckvT, *coT, *wie, *wmoe, *wid_, *wmod, *logT;
    int *ve, *vt;
    cudaGetSymbolAddress((void**)&xe, g_xe);     cudaGetSymbolAddress((void**)&xd, g_xd);
    cudaGetSymbolAddress((void**)&enc, g_enc);   cudaGetSymbolAddress((void**)&h, g_h);
    cudaGetSymbolAddress((void**)&qkv, g_qkv);   cudaGetSymbolAddress((void**)&q, g_q);
    cudaGetSymbolAddress((void**)&kv, g_kv);     cudaGetSymbolAddress((void**)&ao, g_ao);
    cudaGetSymbolAddress((void**)&hid, g_hid);
    cudaGetSymbolAddress((void**)&be, g_bias_e); cudaGetSymbolAddress((void**)&bd, g_bias_d);
    cudaGetSymbolAddress((void**)&ve, g_val_e);  cudaGetSymbolAddress((void**)&vt, g_val_t);
    cudaGetSymbolAddress((void**)&wAe, g_wA_e);  cudaGetSymbolAddress((void**)&woe, g_wo_e);
    cudaGetSymbolAddress((void**)&wAs, g_wA_s);  cudaGetSymbolAddress((void**)&wos, g_wo_s);
    cudaGetSymbolAddress((void**)&cqT, g_cqT);   cudaGetSymbolAddress((void**)&ckvT, g_ckvT);
    cudaGetSymbolAddress((void**)&coT, g_coT);   cudaGetSymbolAddress((void**)&wie, g_wiT_e);
    cudaGetSymbolAddress((void**)&wmoe, g_wmoT_e); cudaGetSymbolAddress((void**)&wid_, g_wiT_d);
    cudaGetSymbolAddress((void**)&wmod, g_wmoT_d); cudaGetSymbolAddress((void**)&logT, g_logT);

    set_attrs();

    valid_k<<<(NT + 255) / 256, 256>>>(enc_tok, ve, NT);
    valid_k<<<(NT + 255) / 256, 256>>>(dec_tgt, vt, NT);
    build_bias<<<(TT * TT) / 256, 256>>>(rel_enc, be, 1);
    build_bias<<<(TT * TT) / 256, 256>>>(rel_dec, bd, 0);

    auto T = [](const float* s, __half* d, int K, int N, long ss, long ds, int cnt) {
        transpose_b<<<dim3(N / 32, K / 32, cnt), dim3(32, 8)>>>(s, d, K, N, ss, ds);
    };
    const long QS = 3 * WSZ, KS = 2 * WSZ;
    T(enc_wq, wAe + 0,       768, 768, WSZ, QS, 6);
    T(enc_wk, wAe + WSZ,     768, 768, WSZ, QS, 6);
    T(enc_wv, wAe + 2 * WSZ, 768, 768, WSZ, QS, 6);
    T(enc_wo, woe, 768, 768, WSZ, WSZ, 6);
    T(dec_sq, wAs + 0,       768, 768, WSZ, QS, 6);
    T(dec_sk, wAs + WSZ,     768, 768, WSZ, QS, 6);
    T(dec_sv, wAs + 2 * WSZ, 768, 768, WSZ, QS, 6);
    T(dec_so, wos, 768, 768, WSZ, WSZ, 6);
    T(dec_cq, cqT, 768, 768, WSZ, WSZ, 6);
    T(dec_ck, ckvT + 0,   768, 768, WSZ, KS, 6);
    T(dec_cv, ckvT + WSZ, 768, 768, WSZ, KS, 6);
    T(dec_co, coT, 768, 768, WSZ, WSZ, 6);
    T(enc_wi,  wie,  768, 3072, DMM, DMM, 6);
    T(enc_wmo, wmoe, 3072, 768, DMM, DMM, 6);
    T(dec_wi,  wid_, 768, 3072, DMM, DMM, 6);
    T(dec_wmo, wmod, 3072, 768, DMM, DMM, 6);
    T(logits_w, logT, 768, VV, 0, 0, 1);

    auto self_attn = [&](const __half* hin, const __half* wqkvT, const __half* woT, float* x,
                         const float* bias, const int* vQ, const int* vK, int causal) {
        gemm_h<false, false, true><<<dim3(18, 16), 256, SMEM_G>>>(hin, wqkvT, qkv, DD, DD, DD, 2304);
        flash_attn<<<dim3(4, 48), 256, FASMEM>>>(qkv, 2304, qkv + 768, 2304, qkv + 1536, 2304,
                                                 bias, vQ, vK, causal, ao);
        gemm_h<true, false, false><<<dim3(6, 16), 256, SMEM_G>>>(ao, woT, x, DD, DD, DD, DD);
    };
    auto mlp = [&](const __half* hin, const __half* wiT, const __half* wmoT, float* x) {
        gemm_h<false, true, true><<<dim3(24, 16), 256, SMEM_G>>>(hin, wiT, hid, DD, DD, DD, MM);
        gemm_h<true, false, false><<<dim3(6, 16), 256, SMEM_G>>>(hid, wmoT, x, MM, MM, MM, DD);
    };

    // -------- encoder --------
    embed_k<<<NT, 256>>>(enc_tok, emb, xe);
    for (int l = 0; l < LL; l++) {
        rmsnorm_k<<<NT, 256>>>(xe, enc_ln1 + (size_t)l * DD, h);
        self_attn(h, wAe + l * QS, woe + l * WSZ, xe, be, ve, ve, 0);
        rmsnorm_k<<<NT, 256>>>(xe, enc_ln2 + (size_t)l * DD, h);
        mlp(h, wie + l * DMM, wmoe + l * DMM, xe);
    }
    rmsnorm_k<<<NT, 256>>>(xe, enc_norm, enc);

    // -------- decoder --------
    embed_k<<<NT, 256>>>(dec_in_tok, emb, xd);
    for (int l = 0; l < LL; l++) {
        rmsnorm_k<<<NT, 256>>>(xd, dec_ln1 + (size_t)l * DD, h);
        self_attn(h, wAs + l * QS, wos + l * WSZ, xd, bd, vt, vt, 1);
        rmsnorm_k<<<NT, 256>>>(xd, dec_ln2 + (size_t)l * DD, h);
        // cross attention
        gemm_h<false, false, true><<<dim3(6, 16), 256, SMEM_G>>>(h, cqT + l * WSZ, q, DD, DD, DD, DD);
        gemm_h<false, false, true><<<dim3(12, 16), 256, SMEM_G>>>(enc, ckvT + l * KS, kv, DD, DD, DD, 1536);
        flash_attn<<<dim3(4, 48), 256, FASMEM>>>(q, DD, kv, 1536, kv + 768, 1536,
                                                 nullptr, vt, ve, 0, ao);
        gemm_h<true, false, false><<<dim3(6, 16), 256, SMEM_G>>>(ao, coT + l * WSZ, xd, DD, DD, DD, DD);
        rmsnorm_k<<<NT, 256>>>(xd, dec_ln3 + (size_t)l * DD, h);
        mlp(h, wid_ + l * DMM, wmod + l * DMM, xd);
    }
    rmsnorm_k<<<NT, 256>>>(xd, dec_norm, h);

    // -------- logits --------
    gemm_h<false, false, false><<<dim3(251, 16), 256, SMEM_G>>>(h, logT, (float*)d_out, DD, DD, DD, VV);
}

// round 10
// speedup vs baseline: 2.5113x; 1.0226x over previous
#include <cuda_runtime.h>
#include <cuda_fp16.h>
#include <math.h>
#include <stdint.h>

#define TT 512
#define BBATCH 4
#define NT 2048
#define DD 768
#define HH 12
#define HDIM 64
#define MM 3072
#define VV 32128
#define LL 6
#define NEGINF -1e10f
#define WSZ ((long)DD * DD)
#define DMM ((long)DD * MM)

// ---------------- scratch ----------------
__device__ float  g_xe[NT * DD];
__device__ float  g_xd[NT * DD];
__device__ __half g_enc[NT * DD];
__device__ __half g_h[NT * DD];
__device__ __half g_qkv[NT * 3 * DD];
__device__ __half g_q[NT * DD];
__device__ __half g_kv[NT * 2 * DD];
__device__ __half g_ao[NT * DD];
__device__ __half g_hid[NT * MM];
__device__ __half g_bias_e[HH * TT * TT];
__device__ __half g_bias_d[HH * TT * TT];
__device__ int    g_lut_e[1023];
__device__ int    g_lut_d[1023];
__device__ int    g_val_e[NT];
__device__ int    g_val_t[NT];
// transposed fp16 weights [N,K]
__device__ __half g_wA_e[LL * 3 * DD * DD];
__device__ __half g_wo_e[LL * DD * DD];
__device__ __half g_wA_s[LL * 3 * DD * DD];
__device__ __half g_wo_s[LL * DD * DD];
__device__ __half g_cqT [LL * DD * DD];
__device__ __half g_ckvT[LL * 2 * DD * DD];
__device__ __half g_coT [LL * DD * DD];
__device__ __half g_wiT_e [LL * DD * MM];
__device__ __half g_wmoT_e[LL * DD * MM];
__device__ __half g_wiT_d [LL * DD * MM];
__device__ __half g_wmoT_d[LL * DD * MM];
__device__ __half g_logT[(long)VV * DD];

// ---------------- helpers ----------------
__device__ __forceinline__ void cp16(unsigned dst, const void* src)
{ asm volatile("cp.async.cg.shared.global [%0], [%1], 16;\n" :: "r"(dst), "l"(src)); }
__device__ __forceinline__ void cp_commit() { asm volatile("cp.async.commit_group;\n"); }
__device__ __forceinline__ void cp_wait1()  { asm volatile("cp.async.wait_group 1;\n"); }
__device__ __forceinline__ void cp_wait0()  { asm volatile("cp.async.wait_group 0;\n"); }

__device__ __forceinline__ unsigned su32(const void* p)
{ return (unsigned)__cvta_generic_to_shared(p); }

__device__ __forceinline__ void ldsm4(unsigned a_, unsigned* a)
{
    asm volatile("ldmatrix.sync.aligned.m8n8.x4.shared.b16 {%0,%1,%2,%3}, [%4];"
                 : "=r"(a[0]), "=r"(a[1]), "=r"(a[2]), "=r"(a[3]) : "r"(a_));
}
__device__ __forceinline__ void ldsm2(unsigned a_, unsigned* b)
{
    asm volatile("ldmatrix.sync.aligned.m8n8.x2.shared.b16 {%0,%1}, [%2];"
                 : "=r"(b[0]), "=r"(b[1]) : "r"(a_));
}
__device__ __forceinline__ void ldsm2t(unsigned a_, unsigned* b)
{
    asm volatile("ldmatrix.sync.aligned.m8n8.x2.trans.shared.b16 {%0,%1}, [%2];"
                 : "=r"(b[0]), "=r"(b[1]) : "r"(a_));
}
__device__ __forceinline__ void mma16(float* c, const unsigned* a, const unsigned* b)
{
    asm volatile("mma.sync.aligned.m16n8k16.row.col.f32.f16.f16.f32 "
                 "{%0,%1,%2,%3}, {%4,%5,%6,%7}, {%8,%9}, {%0,%1,%2,%3};"
                 : "+f"(c[0]), "+f"(c[1]), "+f"(c[2]), "+f"(c[3])
                 : "r"(a[0]), "r"(a[1]), "r"(a[2]), "r"(a[3]), "r"(b[0]), "r"(b[1]));
}

// ---------------- transposes ----------------
__global__ void transpose_b(const float* __restrict__ src, __half* __restrict__ dst,
                            int K, int N, long ss, long ds)
{
    __shared__ float t[32][33];
    const float* S = src + (long)blockIdx.z * ss;
    __half* D = dst + (long)blockIdx.z * ds;
    int k0 = blockIdx.y * 32, n0 = blockIdx.x * 32;
    int tx = threadIdx.x, ty = threadIdx.y;
#pragma unroll
    for (int i = 0; i < 32; i += 8)
        t[ty + i][tx] = S[(long)(k0 + ty + i) * N + n0 + tx];
    __syncthreads();
#pragma unroll
    for (int i = 0; i < 32; i += 8)
        D[(long)(n0 + ty + i) * K + k0 + tx] = __float2half_rn(t[tx][ty + i]);
}

struct P12 { const float* p[12]; };
struct D8  { __half* wAe; __half* woe; __half* wAs; __half* wos;
             __half* cqT; __half* ckvT; __half* coT; };

__global__ void transpose12(P12 srcs, D8 d)
{
    __shared__ float t[32][33];
    const int mat = blockIdx.z, layer = mat / 12, which = mat % 12;
    const float* S = srcs.p[which] + (long)layer * WSZ;
    __half* D;
    if (which < 3)       D = d.wAe + (long)layer * 3 * WSZ + (long)which * WSZ;
    else if (which == 3) D = d.woe + (long)layer * WSZ;
    else if (which < 7)  D = d.wAs + (long)layer * 3 * WSZ + (long)(which - 4) * WSZ;
    else if (which == 7) D = d.wos + (long)layer * WSZ;
    else if (which == 8) D = d.cqT + (long)layer * WSZ;
    else if (which < 11) D = d.ckvT + (long)layer * 2 * WSZ + (long)(which - 9) * WSZ;
    else                 D = d.coT + (long)layer * WSZ;
    int k0 = blockIdx.y * 32, n0 = blockIdx.x * 32;
    int tx = threadIdx.x, ty = threadIdx.y;
#pragma unroll
    for (int i = 0; i < 32; i += 8)
        t[ty + i][tx] = S[(long)(k0 + ty + i) * DD + n0 + tx];
    __syncthreads();
#pragma unroll
    for (int i = 0; i < 32; i += 8)
        D[(long)(n0 + ty + i) * DD + k0 + tx] = __float2half_rn(t[tx][ty + i]);
}

// ---------------- relpos bucket LUT + bias tables ----------------
__global__ void build_lut(int* __restrict__ lE, int* __restrict__ lD)
{
    int i = blockIdx.x * 256 + threadIdx.x;
    if (i >= 1023) return;
    int n = i - 511;
    {
        int ret = (n < 0) ? 16 : 0;
        int na = n < 0 ? -n : n;
        int bk;
        if (na < 8) bk = ret + na;
        else { int v = 8 + (int)(log((double)na / 8.0) / log(16.0) * 8.0); bk = ret + (v < 15 ? v : 15); }
        lE[i] = bk;
    }
    {
        int na = n > 0 ? n : 0;
        int bk;
        if (na < 16) bk = na;
        else { int v = 16 + (int)(log((double)na / 16.0) / log(8.0) * 16.0); bk = (v < 31 ? v : 31); }
        lD[i] = bk;
    }
}

__global__ void build_bias_h(const float* __restrict__ rel, const int* __restrict__ lut,
                             __half* __restrict__ bias)
{
    int idx = blockIdx.x * 256 + threadIdx.x;
    int q = idx / TT, s = idx % TT;
    int bk = lut[q - s + 511];
#pragma unroll
    for (int h = 0; h < HH; h++)
        bias[(long)h * TT * TT + idx] = __float2half_rn(rel[h * 32 + bk]);
}

// ---------------- fp16 NT GEMM v2: 4 warps, 64x64 warp tiles ----------------
// C[M,N](+)= A[M,K]*Bt[N,K]^T. 128x128 CTA tile, K-chunk 64, double buffered.
__device__ __forceinline__ void load_tileH128(unsigned sbase, const __half* P,
                                              int row0, int k0, int ld, int tid)
{
#pragma unroll
    for (int j = 0; j < 8; j++) {
        int c = tid + 128 * j, m = c >> 3, kc = c & 7;
        cp16(sbase + ((m * 8 + (kc ^ (m & 7))) << 4),
             P + (long)(row0 + m) * ld + k0 + kc * 8);
    }
}

template<bool ACC, bool RELU, bool OUTH>
__global__ __launch_bounds__(128) void gemm_h(
    const __half* __restrict__ A, const __half* __restrict__ Bt, void* __restrict__ Cv,
    int K, int lda, int ldb, int ldc)
{
    extern __shared__ char smc[];
    const unsigned asb = su32(smc);
    const unsigned bsb = asb + 32768;
    constexpr int STG = 16384;

    const int tid = threadIdx.x, lane = tid & 31, warp = tid >> 5;
    const int mw = (warp & 1) * 64, nw = (warp >> 1) * 64;
    const int m0 = blockIdx.y * 128, n0 = blockIdx.x * 128;

    float acc[4][8][4];
#pragma unroll
    for (int i = 0; i < 4; i++)
#pragma unroll
        for (int j = 0; j < 8; j++)
#pragma unroll
            for (int q = 0; q < 4; q++) acc[i][j][q] = 0.f;

    const int nk = K >> 6;
    load_tileH128(asb, A, m0, 0, lda, tid);
    load_tileH128(bsb, Bt, n0, 0, ldb, tid);
    cp_commit();

    for (int kt = 0; kt < nk; kt++) {
        const int st = kt & 1;
        if (kt + 1 < nk) {
            load_tileH128(asb + (st ^ 1) * STG, A, m0, (kt + 1) << 6, lda, tid);
            load_tileH128(bsb + (st ^ 1) * STG, Bt, n0, (kt + 1) << 6, ldb, tid);
        }
        cp_commit();
        cp_wait1();
        __syncthreads();

        const unsigned ab = asb + st * STG;
        const unsigned bb = bsb + st * STG;
#pragma unroll
        for (int kk = 0; kk < 64; kk += 16) {
            unsigned a[4][4];
#pragma unroll
            for (int i = 0; i < 4; i++) {
                int r = mw + 16 * i + (lane & 15);
                int ch = (kk >> 3) + (lane >> 4);
                ldsm4(ab + ((r * 8 + (ch ^ (r & 7))) << 4), a[i]);
            }
            unsigned bf[8][2];
#pragma unroll
            for (int jj = 0; jj < 4; jj++) {
                unsigned t4[4];
                int r = nw + 16 * jj + ((lane >> 4) << 3) + (lane & 7);
                int ch = (kk >> 3) + ((lane >> 3) & 1);
                ldsm4(bb + ((r * 8 + (ch ^ (r & 7))) << 4), t4);
                bf[2 * jj][0] = t4[0]; bf[2 * jj][1] = t4[1];
                bf[2 * jj + 1][0] = t4[2]; bf[2 * jj + 1][1] = t4[3];
            }
#pragma unroll
            for (int i = 0; i < 4; i++)
#pragma unroll
                for (int j = 0; j < 8; j++) mma16(acc[i][j], a[i], bf[j]);
        }
        __syncthreads();
    }

#pragma unroll
    for (int i = 0; i < 4; i++) {
        int r = m0 + mw + 16 * i + (lane >> 2);
#pragma unroll
        for (int j = 0; j < 8; j++) {
            int cn = n0 + nw + 8 * j + ((lane & 3) << 1);
            float2 v0 = make_float2(acc[i][j][0], acc[i][j][1]);
            float2 v1 = make_float2(acc[i][j][2], acc[i][j][3]);
            if (RELU) {
                v0.x = fmaxf(v0.x, 0.f); v0.y = fmaxf(v0.y, 0.f);
                v1.x = fmaxf(v1.x, 0.f); v1.y = fmaxf(v1.y, 0.f);
            }
            if (OUTH) {
                __half* C = (__half*)Cv;
                *(__half2*)(C + (long)r * ldc + cn)       = __floats2half2_rn(v0.x, v0.y);
                *(__half2*)(C + (long)(r + 8) * ldc + cn) = __floats2half2_rn(v1.x, v1.y);
            } else {
                float* C = (float*)Cv;
                float2* p0 = (float2*)(C + (long)r * ldc + cn);
                float2* p1 = (float2*)(C + (long)(r + 8) * ldc + cn);
                if (ACC) {
                    float2 o0 = *p0, o1 = *p1;
                    v0.x += o0.x; v0.y += o0.y; v1.x += o1.x; v1.y += o1.y;
                }
                *p0 = v0; *p1 = v1;
            }
        }
    }
}

// ================= fused flash attention (fp16 operands, half bias) =================
#define BQ   0
#define BKT  16384
#define BV   49152
#define BP   65536
#define BRED 98304
#define BVK  100352
#define BVQ  102400
#define FASMEM 104448

__global__ __launch_bounds__(256) void flash_attn(
    const __half* __restrict__ Q, int ldq,
    const __half* __restrict__ K, int ldk,
    const __half* __restrict__ V, int ldv,
    const __half* __restrict__ bias,
    const int* __restrict__ validQ, const int* __restrict__ validK,
    int causal, __half* __restrict__ O)
{
    extern __shared__ char smc[];
    float* smf = (float*)smc;
    int* smi = (int*)smc;
    const unsigned sb = su32(smc);
    const int tid = threadIdx.x, lane = tid & 31, warp = tid >> 5;
    const int mw = (warp & 3) * 32;
    const int nwid = warp >> 2;
    const int nw = nwid * 64;
    const int nhd = nwid * 32;
    const int q0 = blockIdx.x * 128;
    const int z = blockIdx.y, b = z / HH, h = z % HH;
    const __half* Qp = Q + (long)b * TT * ldq + h * HDIM;
    const __half* Kp = K + (long)b * TT * ldk + h * HDIM;
    const __half* Vp = V + (long)b * TT * ldv + h * HDIM;
    const __half* biasH = bias ? bias + (long)h * TT * TT : nullptr;
    const int nt = TT / 128;

    auto loadQ = [&]() {
#pragma unroll
        for (int j = 0; j < 4; j++) {
            int c = tid + 256 * j, m = c >> 3, kc = c & 7;
            cp16(sb + BQ + ((m * 8 + (kc ^ (m & 7))) << 4),
                 Qp + (long)(q0 + m) * ldq + kc * 8);
        }
    };
    auto loadK = [&](int buf, int st) {
        int s0 = st * 128;
#pragma unroll
        for (int j = 0; j < 4; j++) {
            int c = tid + 256 * j, m = c >> 3, kc = c & 7;
            cp16(sb + BKT + buf * 16384 + ((m * 8 + (kc ^ (m & 7))) << 4),
                 Kp + (long)(s0 + m) * ldk + kc * 8);
        }
    };
    auto loadV = [&](int st) {
        int s0 = st * 128;
#pragma unroll
        for (int j = 0; j < 4; j++) {
            int c = tid + 256 * j, k = c >> 3, nc = c & 7;
            cp16(sb + BV + ((k * 8 + (nc ^ (k & 7))) << 4),
                 Vp + (long)(s0 + k) * ldv + nc * 8);
        }
    };

    loadQ(); loadK(0, 0); cp_commit();
    loadV(0); cp_commit();
    loadK(1, 1); cp_commit();

    smi[(BVK >> 2) + tid] = validK[b * TT + tid];
    smi[(BVK >> 2) + 256 + tid] = validK[b * TT + 256 + tid];
    smi[(BVQ >> 2) + tid] = validQ[b * TT + tid];
    smi[(BVQ >> 2) + 256 + tid] = validQ[b * TT + 256 + tid];

    cp_wait1();
    __syncthreads();

    float m_run[2][2], s_run[2][2], oacc[2][4][4];
#pragma unroll
    for (int i = 0; i < 2; i++)
#pragma unroll
        for (int rr = 0; rr < 2; rr++) { m_run[i][rr] = -3.0e38f; s_run[i][rr] = 0.f; }
#pragma unroll
    for (int i = 0; i < 2; i++)
#pragma unroll
        for (int j = 0; j < 4; j++)
#pragma unroll
            for (int q = 0; q < 4; q++) oacc[i][j][q] = 0.f;

    for (int t = 0; t < nt; t++) {
        if (t >= 1) {
            loadV(t); cp_commit();
            if (t + 1 < nt) { loadK((t + 1) & 1, t + 1); cp_commit(); }
        }
        const int s0 = t * 128;

        float acc[2][8][4];
#pragma unroll
        for (int i = 0; i < 2; i++)
#pragma unroll
            for (int j = 0; j < 8; j++)
#pragma unroll
                for (int q = 0; q < 4; q++) acc[i][j][q] = 0.f;

        const unsigned kb = sb + BKT + (t & 1) * 16384;
#pragma unroll
        for (int kk = 0; kk < 64; kk += 16) {
            unsigned a[2][4];
#pragma unroll
            for (int i = 0; i < 2; i++) {
                int r = mw + 16 * i + (lane & 15);
                int ch = (kk >> 3) + (lane >> 4);
                ldsm4(sb + BQ + ((r * 8 + (ch ^ (r & 7))) << 4), a[i]);
            }
            unsigned bf[8][2];
#pragma unroll
            for (int j = 0; j < 8; j++) {
                int r = nw + 8 * j + (lane & 7);
                int ch = (kk >> 3) + ((lane >> 3) & 1);
                ldsm2(kb + ((r * 8 + (ch ^ (r & 7))) << 4), bf[j]);
            }
#pragma unroll
            for (int i = 0; i < 2; i++)
#pragma unroll
                for (int j = 0; j < 8; j++) mma16(acc[i][j], a[i], bf[j]);
        }

        // bias + mask
#pragma unroll
        for (int i = 0; i < 2; i++)
#pragma unroll
            for (int rr = 0; rr < 2; rr++) {
                int Rl = mw + 16 * i + 8 * rr + (lane >> 2);
                int q = q0 + Rl;
                int vq = smi[(BVQ >> 2) + q];
#pragma unroll
                for (int j = 0; j < 8; j++) {
                    int Cl = nw + 8 * j + 2 * (lane & 3);
                    int s = s0 + Cl;
                    float b0 = 0.f, b1 = 0.f;
                    if (biasH) {
                        __half2 bb = *(const __half2*)(biasH + (long)q * TT + s);
                        b0 = __half2float(__low2half(bb));
                        b1 = __half2float(__high2half(bb));
                    }
                    int2 vk = *(const int2*)(smi + (BVK >> 2) + s);
                    float v0 = acc[i][j][2 * rr + 0] + b0;
                    float v1 = acc[i][j][2 * rr + 1] + b1;
                    bool m0 = vq && vk.x && (!causal || s <= q);
                    bool m1 = vq && vk.y && (!causal || s + 1 <= q);
                    acc[i][j][2 * rr + 0] = m0 ? v0 : NEGINF;
                    acc[i][j][2 * rr + 1] = m1 ? v1 : NEGINF;
                }
            }

        // row max
        float mp[2][2];
#pragma unroll
        for (int i = 0; i < 2; i++)
#pragma unroll
            for (int rr = 0; rr < 2; rr++) {
                float m = -3.4e38f;
#pragma unroll
                for (int j = 0; j < 8; j++)
                    m = fmaxf(m, fmaxf(acc[i][j][2 * rr], acc[i][j][2 * rr + 1]));
                mp[i][rr] = m;
            }
#pragma unroll
        for (int o = 1; o <= 2; o <<= 1)
#pragma unroll
            for (int i = 0; i < 2; i++)
#pragma unroll
                for (int rr = 0; rr < 2; rr++)
                    mp[i][rr] = fmaxf(mp[i][rr], __shfl_xor_sync(0xffffffffu, mp[i][rr], o));
        if ((lane & 3) == 0) {
#pragma unroll
            for (int i = 0; i < 2; i++)
#pragma unroll
                for (int rr = 0; rr < 2; rr++) {
                    int Rl = mw + 16 * i + 8 * rr + (lane >> 2);
                    smf[(BRED >> 2) + Rl * 2 + nwid] = mp[i][rr];
                }
        }
        __syncthreads();

        float mnew[2][2], scl[2][2];
#pragma unroll
        for (int i = 0; i < 2; i++)
#pragma unroll
            for (int rr = 0; rr < 2; rr++) {
                int Rl = mw + 16 * i + 8 * rr + (lane >> 2);
                float mt = fmaxf(smf[(BRED >> 2) + Rl * 2], smf[(BRED >> 2) + Rl * 2 + 1]);
                float mn = fmaxf(m_run[i][rr], mt);
                scl[i][rr] = __expf(m_run[i][rr] - mn);
                m_run[i][rr] = mn;
                mnew[i][rr] = mn;
            }

        // p = exp(s-m), stage P (fp16), partial sums
        float sp[2][2] = {{0.f, 0.f}, {0.f, 0.f}};
#pragma unroll
        for (int i = 0; i < 2; i++)
#pragma unroll
            for (int rr = 0; rr < 2; rr++) {
                int Rl = mw + 16 * i + 8 * rr + (lane >> 2);
#pragma unroll
                for (int j = 0; j < 8; j++) {
                    float p0 = __expf(acc[i][j][2 * rr + 0] - mnew[i][rr]);
                    float p1 = __expf(acc[i][j][2 * rr + 1] - mnew[i][rr]);
                    sp[i][rr] += p0 + p1;
                    int Cl = nw + 8 * j + 2 * (lane & 3);
                    int nc = Cl >> 3;
                    *(__half2*)(smc + BP + Rl * 256 + ((nc ^ (Rl & 7)) << 4) + (Cl & 7) * 2) =
                        __floats2half2_rn(p0, p1);
                }
            }
#pragma unroll
        for (int o = 1; o <= 2; o <<= 1)
#pragma unroll
            for (int i = 0; i < 2; i++)
#pragma unroll
                for (int rr = 0; rr < 2; rr++)
                    sp[i][rr] += __shfl_xor_sync(0xffffffffu, sp[i][rr], o);
        if ((lane & 3) == 0) {
#pragma unroll
            for (int i = 0; i < 2; i++)
#pragma unroll
                for (int rr = 0; rr < 2; rr++) {
                    int Rl = mw + 16 * i + 8 * rr + (lane >> 2);
                    smf[(BRED >> 2) + 256 + Rl * 2 + nwid] = sp[i][rr];
                }
        }
        if (t + 1 < nt) cp_wait1(); else cp_wait0();
        __syncthreads();

#pragma unroll
        for (int i = 0; i < 2; i++)
#pragma unroll
            for (int rr = 0; rr < 2; rr++) {
                int Rl = mw + 16 * i + 8 * rr + (lane >> 2);
                float st = smf[(BRED >> 2) + 256 + Rl * 2] + smf[(BRED >> 2) + 256 + Rl * 2 + 1];
                s_run[i][rr] = s_run[i][rr] * scl[i][rr] + st;
            }
#pragma unroll
        for (int i = 0; i < 2; i++)
#pragma unroll
            for (int j = 0; j < 4; j++) {
                oacc[i][j][0] *= scl[i][0]; oacc[i][j][1] *= scl[i][0];
                oacc[i][j][2] *= scl[i][1]; oacc[i][j][3] *= scl[i][1];
            }

        // PV
#pragma unroll
        for (int kk = 0; kk < 128; kk += 16) {
            unsigned a[2][4];
#pragma unroll
            for (int i = 0; i < 2; i++) {
                int r = mw + 16 * i + (lane & 15);
                int ch = (kk >> 3) + (lane >> 4);
                ldsm4(sb + BP + ((r * 16 + (ch ^ (r & 7))) << 4), a[i]);
            }
            unsigned bf[4][2];
#pragma unroll
            for (int j = 0; j < 4; j++) {
                int n0c = (nhd + 8 * j) >> 3;
                int r = kk + (lane & 7) + ((lane >> 3) & 1) * 8;
                ldsm2t(sb + BV + ((r * 8 + (n0c ^ (r & 7))) << 4), bf[j]);
            }
#pragma unroll
            for (int i = 0; i < 2; i++)
#pragma unroll
                for (int j = 0; j < 4; j++) mma16(oacc[i][j], a[i], bf[j]);
        }

        if (t + 1 < nt) { cp_wait0(); __syncthreads(); }
    }

    __half* Op = O + (long)b * TT * DD + h * HDIM;
#pragma unroll
    for (int i = 0; i < 2; i++)
#pragma unroll
        for (int rr = 0; rr < 2; rr++) {
            int Rl = mw + 16 * i + 8 * rr + (lane >> 2);
            float inv = 1.0f / s_run[i][rr];
#pragma unroll
            for (int j = 0; j < 4; j++) {
                int cn = nhd + 8 * j + 2 * (lane & 3);
                *(__half2*)(Op + (long)(q0 + Rl) * DD + cn) =
                    __floats2half2_rn(oacc[i][j][2 * rr + 0] * inv,
                                      oacc[i][j][2 * rr + 1] * inv);
            }
        }
}

// ---------------- elementwise ----------------
__global__ __launch_bounds__(192) void rmsnorm_k(const float* __restrict__ X,
                                                 const float* __restrict__ scale,
                                                 __half* __restrict__ O)
{
    const int row = blockIdx.x, tid = threadIdx.x;
    float4 v = ((const float4*)(X + (long)row * DD))[tid];
    float s = v.x * v.x + v.y * v.y + v.z * v.z + v.w * v.w;
#pragma unroll
    for (int o = 16; o > 0; o >>= 1) s += __shfl_xor_sync(0xffffffffu, s, o);
    __shared__ float red[6];
    if ((tid & 31) == 0) red[tid >> 5] = s;
    __syncthreads();
    float tot = red[0] + red[1] + red[2] + red[3] + red[4] + red[5];
    float r = 1.0f / sqrtf(tot / (float)DD + 1e-6f);
    float4 sc = ((const float4*)scale)[tid];
    __half2* op = (__half2*)(O + (long)row * DD);
    op[2 * tid]     = __floats2half2_rn(v.x * r * sc.x, v.y * r * sc.y);
    op[2 * tid + 1] = __floats2half2_rn(v.z * r * sc.z, v.w * r * sc.w);
}

__global__ void embed_k(const int* __restrict__ tok, const float* __restrict__ emb,
                        float* __restrict__ O)
{
    int t = blockIdx.x, token = tok[t];
    const float* e = emb + (size_t)token * DD;
    for (int d = threadIdx.x; d < DD; d += 256) O[(size_t)t * DD + d] = e[d];
}

__global__ void valid2_k(const int* __restrict__ tokA, const int* __restrict__ tokB,
                         int* __restrict__ vA, int* __restrict__ vB)
{
    int i = blockIdx.x * blockDim.x + threadIdx.x;
    if (i < NT) vA[i] = tokA[i] > 0 ? 1 : 0;
    else { int j = i - NT; vB[j] = tokB[j] > 0 ? 1 : 0; }
}

// ---------------- host ----------------
#define SMEM_G 65536

static void set_attrs()
{
    cudaFuncSetAttribute(gemm_h<false, false, true >, cudaFuncAttributeMaxDynamicSharedMemorySize, SMEM_G);
    cudaFuncSetAttribute(gemm_h<false, true,  true >, cudaFuncAttributeMaxDynamicSharedMemorySize, SMEM_G);
    cudaFuncSetAttribute(gemm_h<true,  false, false>, cudaFuncAttributeMaxDynamicSharedMemorySize, SMEM_G);
    cudaFuncSetAttribute(gemm_h<false, false, false>, cudaFuncAttributeMaxDynamicSharedMemorySize, SMEM_G);
    cudaFuncSetAttribute(flash_attn, cudaFuncAttributeMaxDynamicSharedMemorySize, FASMEM);
}

extern "C" void kernel_launch(void* const* d_in, const int* in_sizes, int n_in,
                              void* d_out, int out_size)
{
    const float* emb      = (const float*)d_in[0];
    const float* rel_enc  = (const float*)d_in[1];
    const float* rel_dec  = (const float*)d_in[2];
    const float* enc_ln1  = (const float*)d_in[3];
    const float* enc_wq   = (const float*)d_in[4];
    const float* enc_wk   = (const float*)d_in[5];
    const float* enc_wv   = (const float*)d_in[6];
    const float* enc_wo   = (const float*)d_in[7];
    const float* enc_ln2  = (const float*)d_in[8];
    const float* enc_wi   = (const float*)d_in[9];
    const float* enc_wmo  = (const float*)d_in[10];
    const float* enc_norm = (const float*)d_in[11];
    const float* dec_ln1  = (const float*)d_in[12];
    const float* dec_sq   = (const float*)d_in[13];
    const float* dec_sk   = (const float*)d_in[14];
    const float* dec_sv   = (const float*)d_in[15];
    const float* dec_so   = (const float*)d_in[16];
    const float* dec_ln2  = (const float*)d_in[17];
    const float* dec_cq   = (const float*)d_in[18];
    const float* dec_ck   = (const float*)d_in[19];
    const float* dec_cv   = (const float*)d_in[20];
    const float* dec_co   = (const float*)d_in[21];
    const float* dec_ln3  = (const float*)d_in[22];
    const float* dec_wi   = (const float*)d_in[23];
    const float* dec_wmo  = (const float*)d_in[24];
    const float* dec_norm = (const float*)d_in[25];
    const float* logits_w = (const float*)d_in[26];
    const int* enc_tok    = (const int*)d_in[27];
    const int* dec_in_tok = (const int*)d_in[28];
    const int* dec_tgt    = (const int*)d_in[29];

    float *xe, *xd;
    __half *enc, *h, *qkv, *q, *kv, *ao, *hid, *be, *bd;
    __half *wAe, *woe, *wAs, *wos, *cqT, *ckvT, *coT, *wie, *wmoe, *wid_, *wmod, *logT;
    int *ve, *vt, *lutE, *lutD;
    cudaGetSymbolAddress((void**)&xe, g_xe);     cudaGetSymbolAddress((void**)&xd, g_xd);
    cudaGetSymbolAddress((void**)&enc, g_enc);   cudaGetSymbolAddress((void**)&h, g_h);
    cudaGetSymbolAddress((void**)&qkv, g_qkv);   cudaGetSymbolAddress((void**)&q, g_q);
    cudaGetSymbolAddress((void**)&kv, g_kv);     cudaGetSymbolAddress((void**)&ao, g_ao);
    cudaGetSymbolAddress((void**)&hid, g_hid);
    cudaGetSymbolAddress((void**)&be, g_bias_e); cudaGetSymbolAddress((void**)&bd, g_bias_d);
    cudaGetSymbolAddress((void**)&ve, g_val_e);  cudaGetSymbolAddress((void**)&vt, g_val_t);
    cudaGetSymbolAddress((void**)&lutE, g_lut_e); cudaGetSymbolAddress((void**)&lutD, g_lut_d);
    cudaGetSymbolAddress((void**)&wAe, g_wA_e);  cudaGetSymbolAddress((void**)&woe, g_wo_e);
    cudaGetSymbolAddress((void**)&wAs, g_wA_s);  cudaGetSymbolAddress((void**)&wos, g_wo_s);
    cudaGetSymbolAddress((void**)&cqT, g_cqT);   cudaGetSymbolAddress((void**)&ckvT, g_ckvT);
    cudaGetSymbolAddress((void**)&coT, g_coT);   cudaGetSymbolAddress((void**)&wie, g_wiT_e);
    cudaGetSymbolAddress((void**)&wmoe, g_wmoT_e); cudaGetSymbolAddress((void**)&wid_, g_wiT_d);
    cudaGetSymbolAddress((void**)&wmod, g_wmoT_d); cudaGetSymbolAddress((void**)&logT, g_logT);

    set_attrs();

    valid2_k<<<(2 * NT) / 256, 256>>>(enc_tok, dec_tgt, ve, vt);
    build_lut<<<4, 256>>>(lutE, lutD);
    build_bias_h<<<(TT * TT) / 256, 256>>>(rel_enc, lutE, be);
    build_bias_h<<<(TT * TT) / 256, 256>>>(rel_dec, lutD, bd);

    // weight transposes
    {
        P12 s;
        s.p[0] = enc_wq; s.p[1] = enc_wk; s.p[2] = enc_wv; s.p[3] = enc_wo;
        s.p[4] = dec_sq; s.p[5] = dec_sk; s.p[6] = dec_sv; s.p[7] = dec_so;
        s.p[8] = dec_cq; s.p[9] = dec_ck; s.p[10] = dec_cv; s.p[11] = dec_co;
        D8 d; d.wAe = wAe; d.woe = woe; d.wAs = wAs; d.wos = wos;
        d.cqT = cqT; d.ckvT = ckvT; d.coT = coT;
        transpose12<<<dim3(24, 24, 72), dim3(32, 8)>>>(s, d);
    }
    transpose_b<<<dim3(MM / 32, DD / 32, 6), dim3(32, 8)>>>(enc_wi,  wie,  DD, MM, DMM, DMM);
    transpose_b<<<dim3(DD / 32, MM / 32, 6), dim3(32, 8)>>>(enc_wmo, wmoe, MM, DD, DMM, DMM);
    transpose_b<<<dim3(MM / 32, DD / 32, 6), dim3(32, 8)>>>(dec_wi,  wid_, DD, MM, DMM, DMM);
    transpose_b<<<dim3(DD / 32, MM / 32, 6), dim3(32, 8)>>>(dec_wmo, wmod, MM, DD, DMM, DMM);
    transpose_b<<<dim3(VV / 32, DD / 32, 1), dim3(32, 8)>>>(logits_w, logT, DD, VV, 0, 0);

    const long QS = 3 * WSZ, KS = 2 * WSZ;

    auto self_attn = [&](const __half* hin, const __half* wqkvT, const __half* woT, float* x,
                         const __half* bias, const int* vQ, const int* vK, int causal) {
        gemm_h<false, false, true><<<dim3(18, 16), 128, SMEM_G>>>(hin, wqkvT, qkv, DD, DD, DD, 2304);
        flash_attn<<<dim3(4, 48), 256, FASMEM>>>(qkv, 2304, qkv + 768, 2304, qkv + 1536, 2304,
                                                 bias, vQ, vK, causal, ao);
        gemm_h<true, false, false><<<dim3(6, 16), 128, SMEM_G>>>(ao, woT, x, DD, DD, DD, DD);
    };
    auto mlp = [&](const __half* hin, const __half* wiT, const __half* wmoT, float* x) {
        gemm_h<false, true, true><<<dim3(24, 16), 128, SMEM_G>>>(hin, wiT, hid, DD, DD, DD, MM);
        gemm_h<true, false, false><<<dim3(6, 16), 128, SMEM_G>>>(hid, wmoT, x, MM, MM, MM, DD);
    };

    // -------- encoder --------
    embed_k<<<NT, 256>>>(enc_tok, emb, xe);
    for (int l = 0; l < LL; l++) {
        rmsnorm_k<<<NT, 192>>>(xe, enc_ln1 + (size_t)l * DD, h);
        self_attn(h, wAe + l * QS, woe + l * WSZ, xe, be, ve, ve, 0);
        rmsnorm_k<<<NT, 192>>>(xe, enc_ln2 + (size_t)l * DD, h);
        mlp(h, wie + l * DMM, wmoe + l * DMM, xe);
    }
    rmsnorm_k<<<NT, 192>>>(xe, enc_norm, enc);

    // -------- decoder --------
    embed_k<<<NT, 256>>>(dec_in_tok, emb, xd);
    for (int l = 0; l < LL; l++) {
        rmsnorm_k<<<NT, 192>>>(xd, dec_ln1 + (size_t)l * DD, h);
        self_attn(h, wAs + l * QS, wos + l * WSZ, xd, bd, vt, vt, 1);
        rmsnorm_k<<<NT, 192>>>(xd, dec_ln2 + (size_t)l * DD, h);
        // cross attention
        gemm_h<false, false, true><<<dim3(6, 16), 128, SMEM_G>>>(h, cqT + l * WSZ, q, DD, DD, DD, DD);
        gemm_h<false, false, true><<<dim3(12, 16), 128, SMEM_G>>>(enc, ckvT + l * KS, kv, DD, DD, DD, 1536);
        flash_attn<<<dim3(4, 48), 256, FASMEM>>>(q, DD, kv, 1536, kv + 768, 1536,
                                                 nullptr, vt, ve, 0, ao);
        gemm_h<true, false, false><<<dim3(6, 16), 128, SMEM_G>>>(ao, coT + l * WSZ, xd, DD, DD, DD, DD);
        rmsnorm_k<<<NT, 192>>>(xd, dec_ln3 + (size_t)l * DD, h);
        mlp(h, wid_ + l * DMM, wmod + l * DMM, xd);
    }
    rmsnorm_k<<<NT, 192>>>(xd, dec_norm, h);

    // -------- logits --------
    gemm_h<false, false, false><<<dim3(251, 16), 128, SMEM_G>>>(h, logT, (float*)d_out, DD, DD, DD, VV);
}

// round 12
// speedup vs baseline: 2.6587x; 1.0587x over previous
#include <cuda_runtime.h>
#include <cuda_fp16.h>
#include <math.h>
#include <stdint.h>

#define TT 512
#define BBATCH 4
#define NT 2048
#define DD 768
#define HH 12
#define HDIM 64
#define MM 3072
#define VV 32128
#define LL 6
#define NEGINF -1e10f
#define WSZ ((long)DD * DD)
#define DMM ((long)DD * MM)
#define KV6LD (LL * 1536)   // 9216

// ---------------- scratch ----------------
__device__ float  g_xe[NT * DD];
__device__ float  g_xd[NT * DD];
__device__ __half g_enc[NT * DD];
__device__ __half g_h[NT * DD];
__device__ __half g_qkv[NT * 3 * DD];
__device__ __half g_q[NT * DD];
__device__ __half g_kv6[(long)NT * KV6LD];
__device__ __half g_ao[NT * DD];
__device__ __half g_hid[NT * MM];
__device__ __half g_bias_e[HH * TT * TT];
__device__ __half g_bias_d[HH * TT * TT];
__device__ int    g_lut_e[1023];
__device__ int    g_lut_d[1023];
__device__ int    g_val_e[NT];
__device__ int    g_val_t[NT];
// transposed fp16 weights [N,K]
__device__ __half g_wA_e[LL * 3 * DD * DD];
__device__ __half g_wo_e[LL * DD * DD];
__device__ __half g_wA_s[LL * 3 * DD * DD];
__device__ __half g_wo_s[LL * DD * DD];
__device__ __half g_cqT [LL * DD * DD];
__device__ __half g_ckvT[LL * 2 * DD * DD];
__device__ __half g_coT [LL * DD * DD];
__device__ __half g_wiT_e [LL * DD * MM];
__device__ __half g_wmoT_e[LL * DD * MM];
__device__ __half g_wiT_d [LL * DD * MM];
__device__ __half g_wmoT_d[LL * DD * MM];
__device__ __half g_logT[(long)VV * DD];

// ---------------- helpers ----------------
__device__ __forceinline__ void cp16(unsigned dst, const void* src)
{ asm volatile("cp.async.cg.shared.global [%0], [%1], 16;\n" :: "r"(dst), "l"(src)); }
__device__ __forceinline__ void cp_commit() { asm volatile("cp.async.commit_group;\n"); }
__device__ __forceinline__ void cp_wait1()  { asm volatile("cp.async.wait_group 1;\n"); }
__device__ __forceinline__ void cp_wait0()  { asm volatile("cp.async.wait_group 0;\n"); }

__device__ __forceinline__ unsigned su32(const void* p)
{ return (unsigned)__cvta_generic_to_shared(p); }

__device__ __forceinline__ void ldsm4(unsigned a_, unsigned* a)
{
    asm volatile("ldmatrix.sync.aligned.m8n8.x4.shared.b16 {%0,%1,%2,%3}, [%4];"
                 : "=r"(a[0]), "=r"(a[1]), "=r"(a[2]), "=r"(a[3]) : "r"(a_));
}
__device__ __forceinline__ void ldsm2(unsigned a_, unsigned* b)
{
    asm volatile("ldmatrix.sync.aligned.m8n8.x2.shared.b16 {%0,%1}, [%2];"
                 : "=r"(b[0]), "=r"(b[1]) : "r"(a_));
}
__device__ __forceinline__ void ldsm2t(unsigned a_, unsigned* b)
{
    asm volatile("ldmatrix.sync.aligned.m8n8.x2.trans.shared.b16 {%0,%1}, [%2];"
                 : "=r"(b[0]), "=r"(b[1]) : "r"(a_));
}
__device__ __forceinline__ void mma16(float* c, const unsigned* a, const unsigned* b)
{
    asm volatile("mma.sync.aligned.m16n8k16.row.col.f32.f16.f16.f32 "
                 "{%0,%1,%2,%3}, {%4,%5,%6,%7}, {%8,%9}, {%0,%1,%2,%3};"
                 : "+f"(c[0]), "+f"(c[1]), "+f"(c[2]), "+f"(c[3])
                 : "r"(a[0]), "r"(a[1]), "r"(a[2]), "r"(a[3]), "r"(b[0]), "r"(b[1]));
}

// ---------------- transposes ----------------
__global__ void transpose_b(const float* __restrict__ src, __half* __restrict__ dst,
                            int K, int N, long ss, long ds)
{
    __shared__ float t[32][33];
    const float* S = src + (long)blockIdx.z * ss;
    __half* D = dst + (long)blockIdx.z * ds;
    int k0 = blockIdx.y * 32, n0 = blockIdx.x * 32;
    int tx = threadIdx.x, ty = threadIdx.y;
#pragma unroll
    for (int i = 0; i < 32; i += 8)
        t[ty + i][tx] = S[(long)(k0 + ty + i) * N + n0 + tx];
    __syncthreads();
#pragma unroll
    for (int i = 0; i < 32; i += 8)
        D[(long)(n0 + ty + i) * K + k0 + tx] = __float2half_rn(t[tx][ty + i]);
}

struct P12 { const float* p[12]; };
struct D8  { __half* wAe; __half* woe; __half* wAs; __half* wos;
             __half* cqT; __half* ckvT; __half* coT; };

__global__ void transpose12(P12 srcs, D8 d)
{
    __shared__ float t[32][33];
    const int mat = blockIdx.z, layer = mat / 12, which = mat % 12;
    const float* S = srcs.p[which] + (long)layer * WSZ;
    __half* D;
    if (which < 3)       D = d.wAe + (long)layer * 3 * WSZ + (long)which * WSZ;
    else if (which == 3) D = d.woe + (long)layer * WSZ;
    else if (which < 7)  D = d.wAs + (long)layer * 3 * WSZ + (long)(which - 4) * WSZ;
    else if (which == 7) D = d.wos + (long)layer * WSZ;
    else if (which == 8) D = d.cqT + (long)layer * WSZ;
    else if (which < 11) D = d.ckvT + (long)layer * 2 * WSZ + (long)(which - 9) * WSZ;
    else                 D = d.coT + (long)layer * WSZ;
    int k0 = blockIdx.y * 32, n0 = blockIdx.x * 32;
    int tx = threadIdx.x, ty = threadIdx.y;
#pragma unroll
    for (int i = 0; i < 32; i += 8)
        t[ty + i][tx] = S[(long)(k0 + ty + i) * DD + n0 + tx];
    __syncthreads();
#pragma unroll
    for (int i = 0; i < 32; i += 8)
        D[(long)(n0 + ty + i) * DD + k0 + tx] = __float2half_rn(t[tx][ty + i]);
}

// ---------------- relpos bucket LUT + bias tables ----------------
__global__ void build_lut(int* __restrict__ lE, int* __restrict__ lD)
{
    int i = blockIdx.x * 256 + threadIdx.x;
    if (i >= 1023) return;
    int n = i - 511;
    {
        int ret = (n < 0) ? 16 : 0;
        int na = n < 0 ? -n : n;
        int bk;
        if (na < 8) bk = ret + na;
        else { int v = 8 + (int)(log((double)na / 8.0) / log(16.0) * 8.0); bk = ret + (v < 15 ? v : 15); }
        lE[i] = bk;
    }
    {
        int na = n > 0 ? n : 0;
        int bk;
        if (na < 16) bk = na;
        else { int v = 16 + (int)(log((double)na / 16.0) / log(8.0) * 16.0); bk = (v < 31 ? v : 31); }
        lD[i] = bk;
    }
}

__global__ void build_bias_h(const float* __restrict__ rel, const int* __restrict__ lut,
                             __half* __restrict__ bias)
{
    int idx = blockIdx.x * 256 + threadIdx.x;
    int q = idx / TT, s = idx % TT;
    int bk = lut[q - s + 511];
#pragma unroll
    for (int h = 0; h < HH; h++)
        bias[(long)h * TT * TT + idx] = __float2half_rn(rel[h * 32 + bk]);
}

// ---------------- tile loaders ----------------
// 128 threads: 128 rows x 64 halves
__device__ __forceinline__ void load_tileH128(unsigned sbase, const __half* P,
                                              int row0, int k0, int ld, int tid)
{
#pragma unroll
    for (int j = 0; j < 8; j++) {
        int c = tid + 128 * j, m = c >> 3, kc = c & 7;
        cp16(sbase + ((m * 8 + (kc ^ (m & 7))) << 4),
             P + (long)(row0 + m) * ld + k0 + kc * 8);
    }
}
// 256 threads: 128 rows x 64 halves
__device__ __forceinline__ void load_tileH256(unsigned sbase, const __half* P,
                                              int row0, int k0, int ld, int tid)
{
#pragma unroll
    for (int j = 0; j < 4; j++) {
        int c = tid + 256 * j, m = c >> 3, kc = c & 7;
        cp16(sbase + ((m * 8 + (kc ^ (m & 7))) << 4),
             P + (long)(row0 + m) * ld + k0 + kc * 8);
    }
}

// ---------------- fp16 NT GEMM, 4 warps / 64x64 warp tiles (big grids) ----------------
template<bool ACC, bool RELU, bool OUTH>
__global__ __launch_bounds__(128) void gemm_h(
    const __half* __restrict__ A, const __half* __restrict__ Bt, void* __restrict__ Cv,
    int K, int lda, int ldb, int ldc)
{
    extern __shared__ char smc[];
    const unsigned asb = su32(smc);
    const unsigned bsb = asb + 32768;
    constexpr int STG = 16384;

    const int tid = threadIdx.x, lane = tid & 31, warp = tid >> 5;
    const int mw = (warp & 1) * 64, nw = (warp >> 1) * 64;
    const int m0 = blockIdx.y * 128, n0 = blockIdx.x * 128;

    float acc[4][8][4];
#pragma unroll
    for (int i = 0; i < 4; i++)
#pragma unroll
        for (int j = 0; j < 8; j++)
#pragma unroll
            for (int q = 0; q < 4; q++) acc[i][j][q] = 0.f;

    const int nk = K >> 6;
    load_tileH128(asb, A, m0, 0, lda, tid);
    load_tileH128(bsb, Bt, n0, 0, ldb, tid);
    cp_commit();

    for (int kt = 0; kt < nk; kt++) {
        const int st = kt & 1;
        if (kt + 1 < nk) {
            load_tileH128(asb + (st ^ 1) * STG, A, m0, (kt + 1) << 6, lda, tid);
            load_tileH128(bsb + (st ^ 1) * STG, Bt, n0, (kt + 1) << 6, ldb, tid);
        }
        cp_commit();
        cp_wait1();
        __syncthreads();

        const unsigned ab = asb + st * STG;
        const unsigned bb = bsb + st * STG;
#pragma unroll
        for (int kk = 0; kk < 64; kk += 16) {
            unsigned a[4][4];
#pragma unroll
            for (int i = 0; i < 4; i++) {
                int r = mw + 16 * i + (lane & 15);
                int ch = (kk >> 3) + (lane >> 4);
                ldsm4(ab + ((r * 8 + (ch ^ (r & 7))) << 4), a[i]);
            }
            unsigned bf[8][2];
#pragma unroll
            for (int jj = 0; jj < 4; jj++) {
                unsigned t4[4];
                int r = nw + 16 * jj + ((lane >> 4) << 3) + (lane & 7);
                int ch = (kk >> 3) + ((lane >> 3) & 1);
                ldsm4(bb + ((r * 8 + (ch ^ (r & 7))) << 4), t4);
                bf[2 * jj][0] = t4[0]; bf[2 * jj][1] = t4[1];
                bf[2 * jj + 1][0] = t4[2]; bf[2 * jj + 1][1] = t4[3];
            }
#pragma unroll
            for (int i = 0; i < 4; i++)
#pragma unroll
                for (int j = 0; j < 8; j++) mma16(acc[i][j], a[i], bf[j]);
        }
        __syncthreads();
    }

#pragma unroll
    for (int i = 0; i < 4; i++) {
        int r = m0 + mw + 16 * i + (lane >> 2);
#pragma unroll
        for (int j = 0; j < 8; j++) {
            int cn = n0 + nw + 8 * j + ((lane & 3) << 1);
            float2 v0 = make_float2(acc[i][j][0], acc[i][j][1]);
            float2 v1 = make_float2(acc[i][j][2], acc[i][j][3]);
            if (RELU) {
                v0.x = fmaxf(v0.x, 0.f); v0.y = fmaxf(v0.y, 0.f);
                v1.x = fmaxf(v1.x, 0.f); v1.y = fmaxf(v1.y, 0.f);
            }
            if (OUTH) {
                __half* C = (__half*)Cv;
                *(__half2*)(C + (long)r * ldc + cn)       = __floats2half2_rn(v0.x, v0.y);
                *(__half2*)(C + (long)(r + 8) * ldc + cn) = __floats2half2_rn(v1.x, v1.y);
            } else {
                float* C = (float*)Cv;
                float2* p0 = (float2*)(C + (long)r * ldc + cn);
                float2* p1 = (float2*)(C + (long)(r + 8) * ldc + cn);
                if (ACC) {
                    float2 o0 = *p0, o1 = *p1;
                    v0.x += o0.x; v0.y += o0.y; v1.x += o1.x; v1.y += o1.y;
                }
                *p0 = v0; *p1 = v1;
            }
        }
    }
}

// ---------------- fp16 NT GEMM, 8 warps / 64x32 warp tiles (small grids) ----------------
template<bool ACC, bool RELU, bool OUTH>
__global__ __launch_bounds__(256) void gemm_h8(
    const __half* __restrict__ A, const __half* __restrict__ Bt, void* __restrict__ Cv,
    int K, int lda, int ldb, int ldc)
{
    extern __shared__ char smc[];
    const unsigned asb = su32(smc);
    const unsigned bsb = asb + 32768;
    constexpr int STG = 16384;

    const int tid = threadIdx.x, lane = tid & 31, warp = tid >> 5;
    const int mw = (warp & 1) * 64, nw = (warp >> 1) * 32;
    const int m0 = blockIdx.y * 128, n0 = blockIdx.x * 128;

    float acc[4][4][4];
#pragma unroll
    for (int i = 0; i < 4; i++)
#pragma unroll
        for (int j = 0; j < 4; j++)
#pragma unroll
            for (int q = 0; q < 4; q++) acc[i][j][q] = 0.f;

    const int nk = K >> 6;
    load_tileH256(asb, A, m0, 0, lda, tid);
    load_tileH256(bsb, Bt, n0, 0, ldb, tid);
    cp_commit();

    for (int kt = 0; kt < nk; kt++) {
        const int st = kt & 1;
        if (kt + 1 < nk) {
            load_tileH256(asb + (st ^ 1) * STG, A, m0, (kt + 1) << 6, lda, tid);
            load_tileH256(bsb + (st ^ 1) * STG, Bt, n0, (kt + 1) << 6, ldb, tid);
        }
        cp_commit();
        cp_wait1();
        __syncthreads();

        const unsigned ab = asb + st * STG;
        const unsigned bb = bsb + st * STG;
#pragma unroll
        for (int kk = 0; kk < 64; kk += 16) {
            unsigned a[4][4];
#pragma unroll
            for (int i = 0; i < 4; i++) {
                int r = mw + 16 * i + (lane & 15);
                int ch = (kk >> 3) + (lane >> 4);
                ldsm4(ab + ((r * 8 + (ch ^ (r & 7))) << 4), a[i]);
            }
            unsigned bf[4][2];
#pragma unroll
            for (int j = 0; j < 4; j++) {
                int r = nw + 8 * j + (lane & 7);
                int ch = (kk >> 3) + ((lane >> 3) & 1);
                ldsm2(bb + ((r * 8 + (ch ^ (r & 7))) << 4), bf[j]);
            }
#pragma unroll
            for (int i = 0; i < 4; i++)
#pragma unroll
                for (int j = 0; j < 4; j++) mma16(acc[i][j], a[i], bf[j]);
        }
        __syncthreads();
    }

#pragma unroll
    for (int i = 0; i < 4; i++) {
        int r = m0 + mw + 16 * i + (lane >> 2);
#pragma unroll
        for (int j = 0; j < 4; j++) {
            int cn = n0 + nw + 8 * j + ((lane & 3) << 1);
            float2 v0 = make_float2(acc[i][j][0], acc[i][j][1]);
            float2 v1 = make_float2(acc[i][j][2], acc[i][j][3]);
            if (RELU) {
                v0.x = fmaxf(v0.x, 0.f); v0.y = fmaxf(v0.y, 0.f);
                v1.x = fmaxf(v1.x, 0.f); v1.y = fmaxf(v1.y, 0.f);
            }
            if (OUTH) {
                __half* C = (__half*)Cv;
                *(__half2*)(C + (long)r * ldc + cn)       = __floats2half2_rn(v0.x, v0.y);
                *(__half2*)(C + (long)(r + 8) * ldc + cn) = __floats2half2_rn(v1.x, v1.y);
            } else {
                float* C = (float*)Cv;
                float2* p0 = (float2*)(C + (long)r * ldc + cn);
                float2* p1 = (float2*)(C + (long)(r + 8) * ldc + cn);
                if (ACC) {
                    float2 o0 = *p0, o1 = *p1;
                    v0.x += o0.x; v0.y += o0.y; v1.x += o1.x; v1.y += o1.y;
                }
                *p0 = v0; *p1 = v1;
            }
        }
    }
}

// ================= fused flash attention (fp16 operands, half bias) =================
#define BQ   0
#define BKT  16384
#define BV   49152
#define BP   65536
#define BRED 98304
#define BVK  100352
#define BVQ  102400
#define FASMEM 104448

__global__ __launch_bounds__(256) void flash_attn(
    const __half* __restrict__ Q, int ldq,
    const __half* __restrict__ K, int ldk,
    const __half* __restrict__ V, int ldv,
    const __half* __restrict__ bias,
    const int* __restrict__ validQ, const int* __restrict__ validK,
    int causal, __half* __restrict__ O)
{
    extern __shared__ char smc[];
    float* smf = (float*)smc;
    int* smi = (int*)smc;
    __shared__ int s_anyinvalid;
    const unsigned sb = su32(smc);
    const int tid = threadIdx.x, lane = tid & 31, warp = tid >> 5;
    const int mw = (warp & 3) * 32;
    const int nwid = warp >> 2;
    const int nw = nwid * 64;
    const int nhd = nwid * 32;
    const int q0 = blockIdx.x * 128;
    const int z = blockIdx.y, b = z / HH, h = z % HH;
    const __half* Qp = Q + (long)b * TT * ldq + h * HDIM;
    const __half* Kp = K + (long)b * TT * ldk + h * HDIM;
    const __half* Vp = V + (long)b * TT * ldv + h * HDIM;
    const __half* biasH = bias ? bias + (long)h * TT * TT : nullptr;
    const int nt = TT / 128;

    auto loadQ = [&]() {
#pragma unroll
        for (int j = 0; j < 4; j++) {
            int c = tid + 256 * j, m = c >> 3, kc = c & 7;
            cp16(sb + BQ + ((m * 8 + (kc ^ (m & 7))) << 4),
                 Qp + (long)(q0 + m) * ldq + kc * 8);
        }
    };
    auto loadK = [&](int buf, int st) {
        int s0 = st * 128;
#pragma unroll
        for (int j = 0; j < 4; j++) {
            int c = tid + 256 * j, m = c >> 3, kc = c & 7;
            cp16(sb + BKT + buf * 16384 + ((m * 8 + (kc ^ (m & 7))) << 4),
                 Kp + (long)(s0 + m) * ldk + kc * 8);
        }
    };
    auto loadV = [&](int st) {
        int s0 = st * 128;
#pragma unroll
        for (int j = 0; j < 4; j++) {
            int c = tid + 256 * j, k = c >> 3, nc = c & 7;
            cp16(sb + BV + ((k * 8 + (nc ^ (k & 7))) << 4),
                 Vp + (long)(s0 + k) * ldv + nc * 8);
        }
    };

    loadQ(); loadK(0, 0); cp_commit();
    loadV(0); cp_commit();
    loadK(1, 1); cp_commit();

    smi[(BVK >> 2) + tid] = validK[b * TT + tid];
    smi[(BVK >> 2) + 256 + tid] = validK[b * TT + 256 + tid];
    smi[(BVQ >> 2) + tid] = validQ[b * TT + tid];
    smi[(BVQ >> 2) + 256 + tid] = validQ[b * TT + 256 + tid];
    if (tid == 0) s_anyinvalid = 0;

    cp_wait1();
    __syncthreads();

    // causal tile-skip: exact only when every query row in this tile is valid
    int nt_eff = nt;
    if (causal) {
        if (tid < 128 && smi[(BVQ >> 2) + q0 + tid] == 0) s_anyinvalid = 1;
        __syncthreads();
        if (!s_anyinvalid) nt_eff = blockIdx.x + 1;
        __syncthreads();
    }

    float m_run[2][2], s_run[2][2], oacc[2][4][4];
#pragma unroll
    for (int i = 0; i < 2; i++)
#pragma unroll
        for (int rr = 0; rr < 2; rr++) { m_run[i][rr] = -3.0e38f; s_run[i][rr] = 0.f; }
#pragma unroll
    for (int i = 0; i < 2; i++)
#pragma unroll
        for (int j = 0; j < 4; j++)
#pragma unroll
            for (int q = 0; q < 4; q++) oacc[i][j][q] = 0.f;

    for (int t = 0; t < nt_eff; t++) {
        if (t >= 1) {
            loadV(t); cp_commit();
            if (t + 1 < nt_eff) { loadK((t + 1) & 1, t + 1); cp_commit(); }
        }
        const int s0 = t * 128;

        float acc[2][8][4];
#pragma unroll
        for (int i = 0; i < 2; i++)
#pragma unroll
            for (int j = 0; j < 8; j++)
#pragma unroll
                for (int q = 0; q < 4; q++) acc[i][j][q] = 0.f;

        const unsigned kb = sb + BKT + (t & 1) * 16384;
#pragma unroll
        for (int kk = 0; kk < 64; kk += 16) {
            unsigned a[2][4];
#pragma unroll
            for (int i = 0; i < 2; i++) {
                int r = mw + 16 * i + (lane & 15);
                int ch = (kk >> 3) + (lane >> 4);
                ldsm4(sb + BQ + ((r * 8 + (ch ^ (r & 7))) << 4), a[i]);
            }
            unsigned bf[8][2];
#pragma unroll
            for (int j = 0; j < 8; j++) {
                int r = nw + 8 * j + (lane & 7);
                int ch = (kk >> 3) + ((lane >> 3) & 1);
                ldsm2(kb + ((r * 8 + (ch ^ (r & 7))) << 4), bf[j]);
            }
#pragma unroll
            for (int i = 0; i < 2; i++)
#pragma unroll
                for (int j = 0; j < 8; j++) mma16(acc[i][j], a[i], bf[j]);
        }

        // bias + mask
#pragma unroll
        for (int i = 0; i < 2; i++)
#pragma unroll
            for (int rr = 0; rr < 2; rr++) {
                int Rl = mw + 16 * i + 8 * rr + (lane >> 2);
                int q = q0 + Rl;
                int vq = smi[(BVQ >> 2) + q];
#pragma unroll
                for (int j = 0; j < 8; j++) {
                    int Cl = nw + 8 * j + 2 * (lane & 3);
                    int s = s0 + Cl;
                    float b0 = 0.f, b1 = 0.f;
                    if (biasH) {
                        __half2 bb = *(const __half2*)(biasH + (long)q * TT + s);
                        b0 = __half2float(__low2half(bb));
                        b1 = __half2float(__high2half(bb));
                    }
                    int2 vk = *(const int2*)(smi + (BVK >> 2) + s);
                    float v0 = acc[i][j][2 * rr + 0] + b0;
                    float v1 = acc[i][j][2 * rr + 1] + b1;
                    bool m0 = vq && vk.x && (!causal || s <= q);
                    bool m1 = vq && vk.y && (!causal || s + 1 <= q);
                    acc[i][j][2 * rr + 0] = m0 ? v0 : NEGINF;
                    acc[i][j][2 * rr + 1] = m1 ? v1 : NEGINF;
                }
            }

        // row max
        float mp[2][2];
#pragma unroll
        for (int i = 0; i < 2; i++)
#pragma unroll
            for (int rr = 0; rr < 2; rr++) {
                float m = -3.4e38f;
#pragma unroll
                for (int j = 0; j < 8; j++)
                    m = fmaxf(m, fmaxf(acc[i][j][2 * rr], acc[i][j][2 * rr + 1]));
                mp[i][rr] = m;
            }
#pragma unroll
        for (int o = 1; o <= 2; o <<= 1)
#pragma unroll
            for (int i = 0; i < 2; i++)
#pragma unroll
                for (int rr = 0; rr < 2; rr++)
                    mp[i][rr] = fmaxf(mp[i][rr], __shfl_xor_sync(0xffffffffu, mp[i][rr], o));
        if ((lane & 3) == 0) {
#pragma unroll
            for (int i = 0; i < 2; i++)
#pragma unroll
                for (int rr = 0; rr < 2; rr++) {
                    int Rl = mw + 16 * i + 8 * rr + (lane >> 2);
                    smf[(BRED >> 2) + Rl * 2 + nwid] = mp[i][rr];
                }
        }
        __syncthreads();

        float mnew[2][2], scl[2][2];
#pragma unroll
        for (int i = 0; i < 2; i++)
#pragma unroll
            for (int rr = 0; rr < 2; rr++) {
                int Rl = mw + 16 * i + 8 * rr + (lane >> 2);
                float mt = fmaxf(smf[(BRED >> 2) + Rl * 2], smf[(BRED >> 2) + Rl * 2 + 1]);
                float mn = fmaxf(m_run[i][rr], mt);
                scl[i][rr] = __expf(m_run[i][rr] - mn);
                m_run[i][rr] = mn;
                mnew[i][rr] = mn;
            }

        // p = exp(s-m), stage P (fp16), partial sums
        float sp[2][2] = {{0.f, 0.f}, {0.f, 0.f}};
#pragma unroll
        for (int i = 0; i < 2; i++)
#pragma unroll
            for (int rr = 0; rr < 2; rr++) {
                int Rl = mw + 16 * i + 8 * rr + (lane >> 2);
#pragma unroll
                for (int j = 0; j < 8; j++) {
                    float p0 = __expf(acc[i][j][2 * rr + 0] - mnew[i][rr]);
                    float p1 = __expf(acc[i][j][2 * rr + 1] - mnew[i][rr]);
                    sp[i][rr] += p0 + p1;
                    int Cl = nw + 8 * j + 2 * (lane & 3);
                    int nc = Cl >> 3;
                    *(__half2*)(smc + BP + Rl * 256 + ((nc ^ (Rl & 7)) << 4) + (Cl & 7) * 2) =
                        __floats2half2_rn(p0, p1);
                }
            }
#pragma unroll
        for (int o = 1; o <= 2; o <<= 1)
#pragma unroll
            for (int i = 0; i < 2; i++)
#pragma unroll
                for (int rr = 0; rr < 2; rr++)
                    sp[i][rr] += __shfl_xor_sync(0xffffffffu, sp[i][rr], o);
        if ((lane & 3) == 0) {
#pragma unroll
            for (int i = 0; i < 2; i++)
#pragma unroll
                for (int rr = 0; rr < 2; rr++) {
                    int Rl = mw + 16 * i + 8 * rr + (lane >> 2);
                    smf[(BRED >> 2) + 256 + Rl * 2 + nwid] = sp[i][rr];
                }
        }
        if (t + 1 < nt_eff) cp_wait1(); else cp_wait0();
        __syncthreads();

#pragma unroll
        for (int i = 0; i < 2; i++)
#pragma unroll
            for (int rr = 0; rr < 2; rr++) {
                int Rl = mw + 16 * i + 8 * rr + (lane >> 2);
                float st = smf[(BRED >> 2) + 256 + Rl * 2] + smf[(BRED >> 2) + 256 + Rl * 2 + 1];
                s_run[i][rr] = s_run[i][rr] * scl[i][rr] + st;
            }
#pragma unroll
        for (int i = 0; i < 2; i++)
#pragma unroll
            for (int j = 0; j < 4; j++) {
                oacc[i][j][0] *= scl[i][0]; oacc[i][j][1] *= scl[i][0];
                oacc[i][j][2] *= scl[i][1]; oacc[i][j][3] *= scl[i][1];
            }

        // PV
#pragma unroll
        for (int kk = 0; kk < 128; kk += 16) {
            unsigned a[2][4];
#pragma unroll
            for (int i = 0; i < 2; i++) {
                int r = mw + 16 * i + (lane & 15);
                int ch = (kk >> 3) + (lane >> 4);
                ldsm4(sb + BP + ((r * 16 + (ch ^ (r & 7))) << 4), a[i]);
            }
            unsigned bf[4][2];
#pragma unroll
            for (int j = 0; j < 4; j++) {
                int n0c = (nhd + 8 * j) >> 3;
                int r = kk + (lane & 7) + ((lane >> 3) & 1) * 8;
                ldsm2t(sb + BV + ((r * 8 + (n0c ^ (r & 7))) << 4), bf[j]);
            }
#pragma unroll
            for (int i = 0; i < 2; i++)
#pragma unroll
                for (int j = 0; j < 4; j++) mma16(oacc[i][j], a[i], bf[j]);
        }

        if (t + 1 < nt_eff) { cp_wait0(); __syncthreads(); }
    }

    __half* Op = O + (long)b * TT * DD + h * HDIM;
#pragma unroll
    for (int i = 0; i < 2; i++)
#pragma unroll
        for (int rr = 0; rr < 2; rr++) {
            int Rl = mw + 16 * i + 8 * rr + (lane >> 2);
            float inv = 1.0f / s_run[i][rr];
#pragma unroll
            for (int j = 0; j < 4; j++) {
                int cn = nhd + 8 * j + 2 * (lane & 3);
                *(__half2*)(Op + (long)(q0 + Rl) * DD + cn) =
                    __floats2half2_rn(oacc[i][j][2 * rr + 0] * inv,
                                      oacc[i][j][2 * rr + 1] * inv);
            }
        }
}

// ---------------- elementwise ----------------
__global__ __launch_bounds__(192) void rmsnorm_k(const float* __restrict__ X,
                                                 const float* __restrict__ scale,
                                                 __half* __restrict__ O)
{
    const int row = blockIdx.x, tid = threadIdx.x;
    float4 v = ((const float4*)(X + (long)row * DD))[tid];
    float s = v.x * v.x + v.y * v.y + v.z * v.z + v.w * v.w;
#pragma unroll
    for (int o = 16; o > 0; o >>= 1) s += __shfl_xor_sync(0xffffffffu, s, o);
    __shared__ float red[6];
    if ((tid & 31) == 0) red[tid >> 5] = s;
    __syncthreads();
    float tot = red[0] + red[1] + red[2] + red[3] + red[4] + red[5];
    float r = 1.0f / sqrtf(tot / (float)DD + 1e-6f);
    float4 sc = ((const float4*)scale)[tid];
    __half2* op = (__half2*)(O + (long)row * DD);
    op[2 * tid]     = __floats2half2_rn(v.x * r * sc.x, v.y * r * sc.y);
    op[2 * tid + 1] = __floats2half2_rn(v.z * r * sc.z, v.w * r * sc.w);
}

__global__ void embed_k(const int* __restrict__ tok, const float* __restrict__ emb,
                        float* __restrict__ O)
{
    int t = blockIdx.x, token = tok[t];
    const float* e = emb + (size_t)token * DD;
    for (int d = threadIdx.x; d < DD; d += 256) O[(size_t)t * DD + d] = e[d];
}

__global__ void valid2_k(const int* __restrict__ tokA, const int* __restrict__ tokB,
                         int* __restrict__ vA, int* __restrict__ vB)
{
    int i = blockIdx.x * blockDim.x + threadIdx.x;
    if (i < NT) vA[i] = tokA[i] > 0 ? 1 : 0;
    else { int j = i - NT; vB[j] = tokB[j] > 0 ? 1 : 0; }
}

// ---------------- host ----------------
#define SMEM_G 65536

static void set_attrs()
{
    cudaFuncSetAttribute(gemm_h<false, false, true >, cudaFuncAttributeMaxDynamicSharedMemorySize, SMEM_G);
    cudaFuncSetAttribute(gemm_h<false, true,  true >, cudaFuncAttributeMaxDynamicSharedMemorySize, SMEM_G);
    cudaFuncSetAttribute(gemm_h<false, false, false>, cudaFuncAttributeMaxDynamicSharedMemorySize, SMEM_G);
    cudaFuncSetAttribute(gemm_h8<true,  false, false>, cudaFuncAttributeMaxDynamicSharedMemorySize, SMEM_G);
    cudaFuncSetAttribute(gemm_h8<false, false, true >, cudaFuncAttributeMaxDynamicSharedMemorySize, SMEM_G);
    cudaFuncSetAttribute(flash_attn, cudaFuncAttributeMaxDynamicSharedMemorySize, FASMEM);
}

extern "C" void kernel_launch(void* const* d_in, const int* in_sizes, int n_in,
                              void* d_out, int out_size)
{
    const float* emb      = (const float*)d_in[0];
    const float* rel_enc  = (const float*)d_in[1];
    const float* rel_dec  = (const float*)d_in[2];
    const float* enc_ln1  = (const float*)d_in[3];
    const float* enc_wq   = (const float*)d_in[4];
    const float* enc_wk   = (const float*)d_in[5];
    const float* enc_wv   = (const float*)d_in[6];
    const float* enc_wo   = (const float*)d_in[7];
    const float* enc_ln2  = (const float*)d_in[8];
    const float* enc_wi   = (const float*)d_in[9];
    const float* enc_wmo  = (const float*)d_in[10];
    const float* enc_norm = (const float*)d_in[11];
    const float* dec_ln1  = (const float*)d_in[12];
    const float* dec_sq   = (const float*)d_in[13];
    const float* dec_sk   = (const float*)d_in[14];
    const float* dec_sv   = (const float*)d_in[15];
    const float* dec_so   = (const float*)d_in[16];
    const float* dec_ln2  = (const float*)d_in[17];
    const float* dec_cq   = (const float*)d_in[18];
    const float* dec_ck   = (const float*)d_in[19];
    const float* dec_cv   = (const float*)d_in[20];
    const float* dec_co   = (const float*)d_in[21];
    const float* dec_ln3  = (const float*)d_in[22];
    const float* dec_wi   = (const float*)d_in[23];
    const float* dec_wmo  = (const float*)d_in[24];
    const float* dec_norm = (const float*)d_in[25];
    const float* logits_w = (const float*)d_in[26];
    const int* enc_tok    = (const int*)d_in[27];
    const int* dec_in_tok = (const int*)d_in[28];
    const int* dec_tgt    = (const int*)d_in[29];

    float *xe, *xd;
    __half *enc, *h, *qkv, *q, *kv6, *ao, *hid, *be, *bd;
    __half *wAe, *woe, *wAs, *wos, *cqT, *ckvT, *coT, *wie, *wmoe, *wid_, *wmod, *logT;
    int *ve, *vt, *lutE, *lutD;
    cudaGetSymbolAddress((void**)&xe, g_xe);     cudaGetSymbolAddress((void**)&xd, g_xd);
    cudaGetSymbolAddress((void**)&enc, g_enc);   cudaGetSymbolAddress((void**)&h, g_h);
    cudaGetSymbolAddress((void**)&qkv, g_qkv);   cudaGetSymbolAddress((void**)&q, g_q);
    cudaGetSymbolAddress((void**)&kv6, g_kv6);   cudaGetSymbolAddress((void**)&ao, g_ao);
    cudaGetSymbolAddress((void**)&hid, g_hid);
    cudaGetSymbolAddress((void**)&be, g_bias_e); cudaGetSymbolAddress((void**)&bd, g_bias_d);
    cudaGetSymbolAddress((void**)&ve, g_val_e);  cudaGetSymbolAddress((void**)&vt, g_val_t);
    cudaGetSymbolAddress((void**)&lutE, g_lut_e); cudaGetSymbolAddress((void**)&lutD, g_lut_d);
    cudaGetSymbolAddress((void**)&wAe, g_wA_e);  cudaGetSymbolAddress((void**)&woe, g_wo_e);
    cudaGetSymbolAddress((void**)&wAs, g_wA_s);  cudaGetSymbolAddress((void**)&wos, g_wo_s);
    cudaGetSymbolAddress((void**)&cqT, g_cqT);   cudaGetSymbolAddress((void**)&ckvT, g_ckvT);
    cudaGetSymbolAddress((void**)&coT, g_coT);   cudaGetSymbolAddress((void**)&wie, g_wiT_e);
    cudaGetSymbolAddress((void**)&wmoe, g_wmoT_e); cudaGetSymbolAddress((void**)&wid_, g_wiT_d);
    cudaGetSymbolAddress((void**)&wmod, g_wmoT_d); cudaGetSymbolAddress((void**)&logT, g_logT);

    set_attrs();

    valid2_k<<<(2 * NT) / 256, 256>>>(enc_tok, dec_tgt, ve, vt);
    build_lut<<<4, 256>>>(lutE, lutD);
    build_bias_h<<<(TT * TT) / 256, 256>>>(rel_enc, lutE, be);
    build_bias_h<<<(TT * TT) / 256, 256>>>(rel_dec, lutD, bd);

    // weight transposes
    {
        P12 s;
        s.p[0] = enc_wq; s.p[1] = enc_wk; s.p[2] = enc_wv; s.p[3] = enc_wo;
        s.p[4] = dec_sq; s.p[5] = dec_sk; s.p[6] = dec_sv; s.p[7] = dec_so;
        s.p[8] = dec_cq; s.p[9] = dec_ck; s.p[10] = dec_cv; s.p[11] = dec_co;
        D8 d; d.wAe = wAe; d.woe = woe; d.wAs = wAs; d.wos = wos;
        d.cqT = cqT; d.ckvT = ckvT; d.coT = coT;
        transpose12<<<dim3(24, 24, 72), dim3(32, 8)>>>(s, d);
    }
    transpose_b<<<dim3(MM / 32, DD / 32, 6), dim3(32, 8)>>>(enc_wi,  wie,  DD, MM, DMM, DMM);
    transpose_b<<<dim3(DD / 32, MM / 32, 6), dim3(32, 8)>>>(enc_wmo, wmoe, MM, DD, DMM, DMM);
    transpose_b<<<dim3(MM / 32, DD / 32, 6), dim3(32, 8)>>>(dec_wi,  wid_, DD, MM, DMM, DMM);
    transpose_b<<<dim3(DD / 32, MM / 32, 6), dim3(32, 8)>>>(dec_wmo, wmod, MM, DD, DMM, DMM);
    transpose_b<<<dim3(VV / 32, DD / 32, 1), dim3(32, 8)>>>(logits_w, logT, DD, VV, 0, 0);

    const long QS = 3 * WSZ;

    auto self_attn = [&](const __half* hin, const __half* wqkvT, const __half* woT, float* x,
                         const __half* bias, const int* vQ, const int* vK, int causal) {
        gemm_h<false, false, true><<<dim3(18, 16), 128, SMEM_G>>>(hin, wqkvT, qkv, DD, DD, DD, 2304);
        flash_attn<<<dim3(4, 48), 256, FASMEM>>>(qkv, 2304, qkv + 768, 2304, qkv + 1536, 2304,
                                                 bias, vQ, vK, causal, ao);
        gemm_h8<true, false, false><<<dim3(6, 16), 256, SMEM_G>>>(ao, woT, x, DD, DD, DD, DD);
    };
    auto mlp = [&](const __half* hin, const __half* wiT, const __half* wmoT, float* x) {
        gemm_h<false, true, true><<<dim3(24, 16), 128, SMEM_G>>>(hin, wiT, hid, DD, DD, DD, MM);
        gemm_h8<true, false, false><<<dim3(6, 16), 256, SMEM_G>>>(hid, wmoT, x, MM, MM, MM, DD);
    };

    // -------- encoder --------
    embed_k<<<NT, 256>>>(enc_tok, emb, xe);
    for (int l = 0; l < LL; l++) {
        rmsnorm_k<<<NT, 192>>>(xe, enc_ln1 + (size_t)l * DD, h);
        self_attn(h, wAe + l * QS, woe + l * WSZ, xe, be, ve, ve, 0);
        rmsnorm_k<<<NT, 192>>>(xe, enc_ln2 + (size_t)l * DD, h);
        mlp(h, wie + l * DMM, wmoe + l * DMM, xe);
    }
    rmsnorm_k<<<NT, 192>>>(xe, enc_norm, enc);

    // -------- decoder --------
    embed_k<<<NT, 256>>>(dec_in_tok, emb, xd);
    // all 6 layers' cross K/V in one GEMM: enc[2048,768] x ckvT[9216,768]^T
    gemm_h<false, false, true><<<dim3(KV6LD / 128, 16), 128, SMEM_G>>>(
        enc, ckvT, kv6, DD, DD, DD, KV6LD);

    for (int l = 0; l < LL; l++) {
        rmsnorm_k<<<NT, 192>>>(xd, dec_ln1 + (size_t)l * DD, h);
        self_attn(h, wAs + l * QS, wos + l * WSZ, xd, bd, vt, vt, 1);
        rmsnorm_k<<<NT, 192>>>(xd, dec_ln2 + (size_t)l * DD, h);
        // cross attention
        gemm_h8<false, false, true><<<dim3(6, 16), 256, SMEM_G>>>(h, cqT + l * WSZ, q, DD, DD, DD, DD);
        flash_attn<<<dim3(4, 48), 256, FASMEM>>>(q, DD,
                                                 kv6 + (long)l * 1536, KV6LD,
                                                 kv6 + (long)l * 1536 + 768, KV6LD,
                                                 nullptr, vt, ve, 0, ao);
        gemm_h8<true, false, false><<<dim3(6, 16), 256, SMEM_G>>>(ao, coT + l * WSZ, xd, DD, DD, DD, DD);
        rmsnorm_k<<<NT, 192>>>(xd, dec_ln3 + (size_t)l * DD, h);
        mlp(h, wid_ + l * DMM, wmod + l * DMM, xd);
    }
    rmsnorm_k<<<NT, 192>>>(xd, dec_norm, h);

    // -------- logits --------
    gemm_h<false, false, false><<<dim3(251, 16), 128, SMEM_G>>>(h, logT, (float*)d_out, DD, DD, DD, VV);
}